// round 1
// baseline (speedup 1.0000x reference)
#include <cuda_runtime.h>
#include <math.h>
#include <stdint.h>

#define BB 8
#define LL 1024
#define DIN 256
#define HH 512
#define NHEAD 8
#define HD 64
#define MROWS (BB*LL)   // 8192

// ---------------- scratch (device globals; no allocations) ----------------
__device__ float g_x   [MROWS*HH];       // input projection output (kept for mean + residual)
__device__ float g_loc [MROWS*HH];
__device__ float g_qkv [MROWS*3*HH];
__device__ float g_att [MROWS*HH];       // attention out; later ffn out scratch
__device__ float g_tmp [MROWS*2*HH];     // out-proj scratch / ffn hidden
__device__ float g_comb[MROWS*HH];
__device__ float g_si  [MROWS*544];      // [enc(512) | temb(32)]
__device__ float g_h256[MROWS*256];
__device__ float g_mean [BB*HH];
__device__ float g_gsum [BB*HH];
__device__ float g_gpart[BB*HH];

// ---------------- generic fp32 GEMM: C[M,N] = act(A[M,K]@W[K,N] + bias) ----
// Tile 128x64x16, 256 threads, 8x4 per thread. Requires M%128==0, N%64==0, K%16==0.
template<int ACT>  // 0=none 1=relu 2=gelu(exact)
__global__ __launch_bounds__(256) void gemm_kernel(
    const float* __restrict__ A, int lda,
    const float* __restrict__ W,
    const float* __restrict__ bias,
    float* __restrict__ C, int N, int K)
{
    __shared__ float As[16][132];   // As[k][m], row 528B (16B aligned), stride%32=4
    __shared__ float Bs[16][68];    // Bs[k][n], row 272B (16B aligned)

    const int tid = threadIdx.x;
    const int tx = tid & 15;        // 16 cols of 4
    const int ty = tid >> 4;        // 16 rows of 8
    const int m0 = blockIdx.y * 128;
    const int n0 = blockIdx.x * 64;

    const int ar = tid >> 4;        // 0..15
    const int ac = tid & 15;        // 0..15
    const int br = tid >> 6;        // 0..3
    const int bc = tid & 63;        // 0..63

    float acc[8][4];
#pragma unroll
    for (int i = 0; i < 8; i++)
#pragma unroll
        for (int j = 0; j < 4; j++) acc[i][j] = 0.f;

    for (int k0 = 0; k0 < K; k0 += 16) {
#pragma unroll
        for (int i = 0; i < 8; i++)
            As[ac][ar + 16*i] = A[(size_t)(m0 + ar + 16*i)*lda + (k0 + ac)];
#pragma unroll
        for (int i = 0; i < 4; i++)
            Bs[br + 4*i][bc] = W[(size_t)(k0 + br + 4*i)*N + (n0 + bc)];
        __syncthreads();
#pragma unroll
        for (int kk = 0; kk < 16; kk++) {
            float4 a0 = *(const float4*)&As[kk][ty*8];
            float4 a1 = *(const float4*)&As[kk][ty*8 + 4];
            float4 b4 = *(const float4*)&Bs[kk][tx*4];
            float av[8] = {a0.x,a0.y,a0.z,a0.w,a1.x,a1.y,a1.z,a1.w};
            float bv[4] = {b4.x,b4.y,b4.z,b4.w};
#pragma unroll
            for (int i = 0; i < 8; i++)
#pragma unroll
                for (int j = 0; j < 4; j++)
                    acc[i][j] = fmaf(av[i], bv[j], acc[i][j]);
        }
        __syncthreads();
    }

#pragma unroll
    for (int i = 0; i < 8; i++) {
        const int m = m0 + ty*8 + i;
        float4 out;
        float* po = (float*)&out;
#pragma unroll
        for (int j = 0; j < 4; j++) {
            const int n = n0 + tx*4 + j;
            float v = acc[i][j];
            if (bias) v += bias[n];
            if (ACT == 1) v = fmaxf(v, 0.f);
            else if (ACT == 2) v = 0.5f * v * (1.f + erff(v * 0.70710678118654752f));
            po[j] = v;
        }
        *(float4*)&C[(size_t)m*N + (n0 + tx*4)] = out;
    }
}

// ---------------- windowed attention (NATTEN, window 31) -------------------
// grid (L/64, NHEAD, B), block 64 threads; one thread per query.
__global__ __launch_bounds__(64) void natten_kernel(
    const float* __restrict__ qkv, float* __restrict__ out)
{
    const int qt = blockIdx.x;
    const int h  = blockIdx.y;
    const int b  = blockIdx.z;
    const int q0 = qt * 64;
    const int base = q0 - 15;               // first key pos (may be <0)

    __shared__ float ks[64][95];            // ks[d][r], stride 95 -> conflict-free
    __shared__ float vs[64][95];

    const int tid = threadIdx.x;
    for (int idx = tid; idx < 94*64; idx += 64) {
        const int r = idx >> 6;             // 0..93
        const int d = idx & 63;
        const int pos = base + r;
        float kk = 0.f, vv = 0.f;
        if (pos >= 0 && pos < LL) {
            const size_t off = ((size_t)(b*LL + pos))*1536 + h*64 + d;
            kk = qkv[off + 512];
            vv = qkv[off + 1024];
        }
        ks[d][r] = kk;
        vs[d][r] = vv;
    }
    __syncthreads();

    const int l = q0 + tid;
    const float* qp = &qkv[((size_t)(b*LL + l))*1536 + h*64];

    float s[31];
#pragma unroll
    for (int j = 0; j < 31; j++) s[j] = 0.f;

#pragma unroll
    for (int c = 0; c < 4; c++) {
        float q[16];
#pragma unroll
        for (int d = 0; d < 16; d++) q[d] = qp[c*16 + d];
#pragma unroll
        for (int j = 0; j < 31; j++) {
            float dot = 0.f;
#pragma unroll
            for (int d = 0; d < 16; d++)
                dot = fmaf(q[d], ks[c*16 + d][tid + j], dot);
            s[j] += dot;
        }
    }

    float mx = -1e30f;
#pragma unroll
    for (int j = 0; j < 31; j++) {
        const int pos = l - 15 + j;
        if (pos < 0 || pos >= LL) s[j] = -1e30f;
        else                      s[j] *= 0.125f;   // 64^-0.5
        mx = fmaxf(mx, s[j]);
    }
    float sum = 0.f;
#pragma unroll
    for (int j = 0; j < 31; j++) { s[j] = expf(s[j] - mx); sum += s[j]; }
    const float inv = 1.f / sum;

    float* op = &out[((size_t)(b*LL + l))*512 + h*64];
#pragma unroll
    for (int c = 0; c < 4; c++) {
        float o[16];
#pragma unroll
        for (int d = 0; d < 16; d++) o[d] = 0.f;
#pragma unroll
        for (int j = 0; j < 31; j++) {
            const float p = s[j];
#pragma unroll
            for (int d = 0; d < 16; d++)
                o[d] = fmaf(p, vs[c*16 + d][tid + j], o[d]);
        }
#pragma unroll
        for (int d = 0; d < 16; d++) op[c*16 + d] = o[d] * inv;
    }
}

// ---------------- fused residual add + LayerNorm (+clip) -------------------
// block = 128 threads per row of 512
template<bool CLIP>
__global__ __launch_bounds__(128) void add_ln_kernel(
    const float* __restrict__ a, const float* __restrict__ res,
    const float* __restrict__ gam, const float* __restrict__ bet,
    float* __restrict__ outp, int ldo)
{
    const int row = blockIdx.x;
    const int tid = threadIdx.x;
    const float* ap = a   + (size_t)row*512;
    const float* rp = res + (size_t)row*512;

    float v[4];
    float s = 0.f, s2 = 0.f;
#pragma unroll
    for (int i = 0; i < 4; i++) {
        const float x = ap[tid + 128*i] + rp[tid + 128*i];
        v[i] = x; s += x; s2 += x*x;
    }
    __shared__ float red[2][4];
#pragma unroll
    for (int o = 16; o > 0; o >>= 1) {
        s  += __shfl_down_sync(~0u, s,  o);
        s2 += __shfl_down_sync(~0u, s2, o);
    }
    const int wid = tid >> 5, lane = tid & 31;
    if (lane == 0) { red[0][wid] = s; red[1][wid] = s2; }
    __syncthreads();
    __shared__ float stats[2];
    if (tid == 0) {
        float ts = 0.f, ts2 = 0.f;
#pragma unroll
        for (int w = 0; w < 4; w++) { ts += red[0][w]; ts2 += red[1][w]; }
        const float mean = ts * (1.f/512.f);
        stats[0] = mean;
        stats[1] = rsqrtf(ts2 * (1.f/512.f) - mean*mean + 1e-5f);
    }
    __syncthreads();
    const float mean = stats[0], rstd = stats[1];
    float* op = outp + (size_t)row*ldo;
#pragma unroll
    for (int i = 0; i < 4; i++) {
        const int c = tid + 128*i;
        float y = (v[i] - mean) * rstd * gam[c] + bet[c];
        if (CLIP) y = fminf(fmaxf(y, -100.f), 100.f);
        op[c] = y;
    }
}

// ---------------- mean over sequence axis ----------------------------------
__global__ void mean_kernel(const float* __restrict__ x, float* __restrict__ outp)
{
    const int c = blockIdx.x*128 + threadIdx.x;  // grid.x = 4
    const int b = blockIdx.y;
    const float* p = x + (size_t)b*LL*512 + c;
    float s = 0.f;
    for (int l = 0; l < LL; l++) s += p[(size_t)l*512];
    outp[b*512 + c] = s * (1.f/LL);
}

// ---------------- tiny per-batch GEMM: C[8,512] = A[8,512]@W[512,512]+b ----
__global__ __launch_bounds__(512) void vec_gemm_kernel(
    const float* __restrict__ A, const float* __restrict__ W,
    const float* __restrict__ bias, float* __restrict__ C)
{
    const int b = blockIdx.x, n = threadIdx.x;
    const float* a = A + b*512;
    float s = bias[n];
    for (int k = 0; k < 512; k++) s = fmaf(a[k], W[(size_t)k*512 + n], s);
    C[b*512 + n] = s;
}

// ---------------- broadcast add of per-batch vector ------------------------
__global__ void add_batch_kernel(float* __restrict__ C, const float* __restrict__ g)
{
    for (size_t idx = (size_t)blockIdx.x*blockDim.x + threadIdx.x;
         idx < (size_t)MROWS*512; idx += (size_t)gridDim.x*blockDim.x) {
        const int b = (int)(idx / ((size_t)LL*512));
        const int c = (int)(idx & 511);
        C[idx] += g[b*512 + c];
    }
}

// ---------------- small-N GEMM (N=18 or 5), K=256 --------------------------
__global__ void small_gemm_kernel(
    const float* __restrict__ A, const float* __restrict__ W,
    const float* __restrict__ bias, float* __restrict__ C, int N)
{
    const int idx = blockIdx.x*blockDim.x + threadIdx.x;
    if (idx >= MROWS*N) return;
    const int m = idx / N, n = idx - m*N;
    const float* a = A + (size_t)m*256;
    float s = bias[n];
    for (int k = 0; k < 256; k++) s = fmaf(a[k], W[k*N + n], s);
    C[idx] = s;
}

// ---------------- softmax(type_logits) @ type_emb -> si[:,512:544] ---------
__global__ __launch_bounds__(256) void type_emb_kernel(
    const float* __restrict__ logits, const float* __restrict__ emb,
    float* __restrict__ si)
{
    const int row  = blockIdx.x*8 + (threadIdx.x >> 5);
    const int lane = threadIdx.x & 31;
    if (row >= MROWS) return;
    const float* lp = logits + (size_t)row*18;
    float v[18];
    float mx = -1e30f;
#pragma unroll
    for (int j = 0; j < 18; j++) { v[j] = lp[j]; mx = fmaxf(mx, v[j]); }
    float sum = 0.f;
#pragma unroll
    for (int j = 0; j < 18; j++) { v[j] = expf(v[j] - mx); sum += v[j]; }
    const float inv = 1.f / sum;
    float o = 0.f;
#pragma unroll
    for (int j = 0; j < 18; j++) o = fmaf(v[j], emb[j*32 + lane], o);
    si[(size_t)row*544 + 512 + lane] = o * inv;
}

// ---------------- launch ----------------------------------------------------
extern "C" void kernel_launch(void* const* d_in, const int* in_sizes, int n_in,
                              void* d_out, int out_size)
{
    (void)in_sizes; (void)n_in; (void)out_size;
    const float* state = (const float*)d_in[0];
    const float* Wp    = (const float*)d_in[1];
    const float* bp    = (const float*)d_in[2];
    const float* Wqkv  = (const float*)d_in[3];
    const float* bqkv  = (const float*)d_in[4];
    const float* Wo    = (const float*)d_in[5];
    const float* bo    = (const float*)d_in[6];
    const float* ln_g  = (const float*)d_in[7];
    const float* ln_b  = (const float*)d_in[8];
    const float* Wg    = (const float*)d_in[9];
    const float* bg    = (const float*)d_in[10];
    const float* Wc    = (const float*)d_in[11];
    const float* bc    = (const float*)d_in[12];
    const float* W1    = (const float*)d_in[13];
    const float* b1    = (const float*)d_in[14];
    const float* W2    = (const float*)d_in[15];
    const float* b2    = (const float*)d_in[16];
    const float* fn_g  = (const float*)d_in[17];
    const float* fn_b  = (const float*)d_in[18];
    const float* Wt1   = (const float*)d_in[19];
    const float* bt1   = (const float*)d_in[20];
    const float* Wt2   = (const float*)d_in[21];
    const float* bt2   = (const float*)d_in[22];
    const float* temb  = (const float*)d_in[23];
    const float* Ws1   = (const float*)d_in[24];
    const float* bs1   = (const float*)d_in[25];
    const float* Ws2   = (const float*)d_in[26];
    const float* bs2   = (const float*)d_in[27];
    const float* Wa1   = (const float*)d_in[28];
    const float* ba1   = (const float*)d_in[29];
    const float* Wa2   = (const float*)d_in[30];
    const float* ba2   = (const float*)d_in[31];

    float* out = (float*)d_out;

    // resolve scratch addresses once (pure address queries; first call is pre-capture)
    static float *px=nullptr,*ploc,*pqkv,*patt,*ptmp,*pcomb,*psi,*ph256,*pmean,*pgsum,*pgpart;
    if (!px) {
        cudaGetSymbolAddress((void**)&px,    g_x);
        cudaGetSymbolAddress((void**)&ploc,  g_loc);
        cudaGetSymbolAddress((void**)&pqkv,  g_qkv);
        cudaGetSymbolAddress((void**)&patt,  g_att);
        cudaGetSymbolAddress((void**)&ptmp,  g_tmp);
        cudaGetSymbolAddress((void**)&pcomb, g_comb);
        cudaGetSymbolAddress((void**)&psi,   g_si);
        cudaGetSymbolAddress((void**)&ph256, g_h256);
        cudaGetSymbolAddress((void**)&pmean, g_mean);
        cudaGetSymbolAddress((void**)&pgsum, g_gsum);
        cudaGetSymbolAddress((void**)&pgpart,g_gpart);
    }

    const dim3 thr(256);

    // 1. x = state @ Wp + bp
    gemm_kernel<0><<<dim3(512/64, MROWS/128), thr>>>(state, DIN, Wp, bp, px, 512, DIN);

    // 2. two NATTEN layers
    const float* locIn = px;
    for (int i = 0; i < 2; i++) {
        gemm_kernel<0><<<dim3(1536/64, MROWS/128), thr>>>(locIn, 512, Wqkv + (size_t)i*512*1536,
                                                          bqkv + i*1536, pqkv, 1536, 512);
        natten_kernel<<<dim3(LL/64, NHEAD, BB), 64>>>(pqkv, patt);
        gemm_kernel<0><<<dim3(512/64, MROWS/128), thr>>>(patt, 512, Wo + (size_t)i*512*512,
                                                         bo + i*512, ptmp, 512, 512);
        add_ln_kernel<false><<<MROWS, 128>>>(ptmp, locIn, ln_g + i*512, ln_b + i*512, ploc, 512);
        locIn = ploc;
    }

    // 3. global summary path (per-batch, tiny)
    mean_kernel<<<dim3(4, BB), 128>>>(px, pmean);
    vec_gemm_kernel<<<BB, 512>>>(pmean, Wg, bg, pgsum);
    vec_gemm_kernel<<<BB, 512>>>(pgsum, Wc + (size_t)512*512, bc, pgpart);

    // 4. comb = loc @ Wc[:512] + gpart[b]
    gemm_kernel<0><<<dim3(512/64, MROWS/128), thr>>>(ploc, 512, Wc, nullptr, pcomb, 512, 512);
    add_batch_kernel<<<8192, 256>>>(pcomb, pgpart);

    // 5. FFN + LN(clip) -> enc (into si[:, :512], stride 544)
    gemm_kernel<2><<<dim3(1024/64, MROWS/128), thr>>>(pcomb, 512, W1, b1, ptmp, 1024, 512);
    gemm_kernel<0><<<dim3(512/64, MROWS/128), thr>>>(ptmp, 1024, W2, b2, patt, 512, 1024);
    add_ln_kernel<true><<<MROWS, 128>>>(patt, pcomb, fn_g, fn_b, psi, 544);

    // 6. type head: logits straight to d_out, then softmax@emb -> si[:,512:]
    gemm_kernel<1><<<dim3(256/64, MROWS/128), thr>>>(psi, 544, Wt1, bt1, ph256, 256, 512);
    small_gemm_kernel<<<(MROWS*18 + 255)/256, 256>>>(ph256, Wt2, bt2, out, 18);
    type_emb_kernel<<<MROWS/8, 256>>>(out, temb, psi);

    // 7. size head
    gemm_kernel<1><<<dim3(256/64, MROWS/128), thr>>>(psi, 544, Ws1, bs1, ph256, 256, 544);
    small_gemm_kernel<<<(MROWS*5 + 255)/256, 256>>>(ph256, Ws2, bs2, out + (size_t)MROWS*18, 5);

    // 8. amount head
    gemm_kernel<1><<<dim3(256/64, MROWS/128), thr>>>(psi, 544, Wa1, ba1, ph256, 256, 544);
    small_gemm_kernel<<<(MROWS*5 + 255)/256, 256>>>(ph256, Wa2, ba2, out + (size_t)MROWS*23, 5);
}

// round 2
// speedup vs baseline: 1.8155x; 1.8155x over previous
#include <cuda_runtime.h>
#include <math.h>
#include <stdint.h>

#define BB 8
#define LL 1024
#define DIN 256
#define HH 512
#define NHEAD 8
#define HD 64
#define MROWS (BB*LL)   // 8192

// ---------------- scratch (device globals; no allocations) ----------------
__device__ float g_x   [MROWS*HH];
__device__ float g_loc [MROWS*HH];
__device__ float g_qkv [MROWS*3*HH];
__device__ float g_att [MROWS*HH];
__device__ float g_tmp [MROWS*2*HH];
__device__ float g_comb[MROWS*HH];
__device__ float g_si  [MROWS*544];      // [enc(512) | temb(32)]
__device__ float g_h256[MROWS*256];
__device__ float g_mean [BB*HH];
__device__ float g_gsum [BB*HH];
__device__ float g_gpart[BB*HH];

// ---------------- tf32 helpers ---------------------------------------------
__device__ __forceinline__ uint32_t f2tf32(float f) {
    uint32_t r;
    asm("cvt.rna.tf32.f32 %0, %1;" : "=r"(r) : "f"(f));
    return r;
}

__device__ __forceinline__ void mma_tf32(
    float& d0, float& d1, float& d2, float& d3,
    uint32_t a0, uint32_t a1, uint32_t a2, uint32_t a3,
    uint32_t b0, uint32_t b1)
{
    asm volatile(
        "mma.sync.aligned.m16n8k8.row.col.f32.tf32.tf32.f32 "
        "{%0,%1,%2,%3}, {%4,%5,%6,%7}, {%8,%9}, {%0,%1,%2,%3};"
        : "+f"(d0), "+f"(d1), "+f"(d2), "+f"(d3)
        : "r"(a0), "r"(a1), "r"(a2), "r"(a3), "r"(b0), "r"(b1));
}

// ---------------- tf32 tensor-core GEMM ------------------------------------
// C[M,N] = act(A[M,K] @ W[K,N] + bias).  Tile 128x64x32, 256 thr (8 warps 4x2).
// Requires M%128==0, N%64==0, K%32==0, lda%4==0, N%4==0.
template<int ACT>  // 0=none 1=relu 2=gelu(exact)
__global__ __launch_bounds__(256) void gemm_tc(
    const float* __restrict__ A, int lda,
    const float* __restrict__ W,
    const float* __restrict__ bias,
    float* __restrict__ C, int N, int K)
{
    __shared__ uint32_t As[128][36];   // [m][k], pad 36 -> conflict-free frags
    __shared__ uint32_t Bs[32][68];    // [k][n], pad 68

    const int tid  = threadIdx.x;
    const int warp = tid >> 5;
    const int lane = tid & 31;
    const int wm = warp >> 1;          // 0..3 -> m offset 32*wm
    const int wn = warp & 1;           // 0..1 -> n offset 32*wn
    const int qr = lane >> 2;          // 0..7
    const int qc = lane & 3;           // 0..3

    const int m0 = blockIdx.y * 128;
    const int n0 = blockIdx.x * 64;

    // loader indices
    const int a_m  = tid >> 3;         // 0..31
    const int a_k4 = (tid & 7) * 4;    // 0,4,...,28
    const int b_k  = tid >> 4;         // 0..15
    const int b_n4 = (tid & 15) * 4;   // 0,4,...,60

    float acc[2][4][4];
#pragma unroll
    for (int i = 0; i < 2; i++)
#pragma unroll
        for (int j = 0; j < 4; j++)
#pragma unroll
            for (int c = 0; c < 4; c++) acc[i][j][c] = 0.f;

    for (int k0 = 0; k0 < K; k0 += 32) {
        // load A tile 128x32 (4 float4 per thread), convert to tf32
#pragma unroll
        for (int r = 0; r < 4; r++) {
            const int m = a_m + 32*r;
            float4 v = *(const float4*)&A[(size_t)(m0 + m)*lda + k0 + a_k4];
            As[m][a_k4+0] = f2tf32(v.x);
            As[m][a_k4+1] = f2tf32(v.y);
            As[m][a_k4+2] = f2tf32(v.z);
            As[m][a_k4+3] = f2tf32(v.w);
        }
        // load B tile 32x64 (2 float4 per thread)
#pragma unroll
        for (int r = 0; r < 2; r++) {
            const int k = b_k + 16*r;
            float4 v = *(const float4*)&W[(size_t)(k0 + k)*N + n0 + b_n4];
            Bs[k][b_n4+0] = f2tf32(v.x);
            Bs[k][b_n4+1] = f2tf32(v.y);
            Bs[k][b_n4+2] = f2tf32(v.z);
            Bs[k][b_n4+3] = f2tf32(v.w);
        }
        __syncthreads();

#pragma unroll
        for (int kk = 0; kk < 32; kk += 8) {
            uint32_t a[2][4], b[4][2];
#pragma unroll
            for (int mf = 0; mf < 2; mf++) {
                const int mb = wm*32 + mf*16;
                a[mf][0] = As[mb + qr    ][kk + qc];
                a[mf][1] = As[mb + qr + 8][kk + qc];
                a[mf][2] = As[mb + qr    ][kk + qc + 4];
                a[mf][3] = As[mb + qr + 8][kk + qc + 4];
            }
#pragma unroll
            for (int nf = 0; nf < 4; nf++) {
                const int nb = wn*32 + nf*8 + qr;
                b[nf][0] = Bs[kk + qc    ][nb];
                b[nf][1] = Bs[kk + qc + 4][nb];
            }
#pragma unroll
            for (int mf = 0; mf < 2; mf++)
#pragma unroll
                for (int nf = 0; nf < 4; nf++)
                    mma_tf32(acc[mf][nf][0], acc[mf][nf][1],
                             acc[mf][nf][2], acc[mf][nf][3],
                             a[mf][0], a[mf][1], a[mf][2], a[mf][3],
                             b[nf][0], b[nf][1]);
        }
        __syncthreads();
    }

    // epilogue: c0,c1 -> (row qr, cols 2qc,2qc+1); c2,c3 -> row qr+8
#pragma unroll
    for (int mf = 0; mf < 2; mf++) {
#pragma unroll
        for (int nf = 0; nf < 4; nf++) {
            const int n = n0 + wn*32 + nf*8 + qc*2;
            float bx = 0.f, by = 0.f;
            if (bias) { bx = bias[n]; by = bias[n+1]; }
#pragma unroll
            for (int half = 0; half < 2; half++) {
                const int m = m0 + wm*32 + mf*16 + qr + half*8;
                float v0 = acc[mf][nf][half*2+0] + bx;
                float v1 = acc[mf][nf][half*2+1] + by;
                if (ACT == 1) { v0 = fmaxf(v0, 0.f); v1 = fmaxf(v1, 0.f); }
                else if (ACT == 2) {
                    v0 = 0.5f*v0*(1.f + erff(v0*0.70710678118654752f));
                    v1 = 0.5f*v1*(1.f + erff(v1*0.70710678118654752f));
                }
                float2 o = make_float2(v0, v1);
                *(float2*)&C[(size_t)m*N + n] = o;
            }
        }
    }
}

// ---------------- windowed attention (NATTEN, window 31) -------------------
__global__ __launch_bounds__(64) void natten_kernel(
    const float* __restrict__ qkv, float* __restrict__ out)
{
    const int qt = blockIdx.x;
    const int h  = blockIdx.y;
    const int b  = blockIdx.z;
    const int q0 = qt * 64;
    const int base = q0 - 15;

    __shared__ float ks[64][95];
    __shared__ float vs[64][95];

    const int tid = threadIdx.x;
    for (int idx = tid; idx < 94*64; idx += 64) {
        const int r = idx >> 6;
        const int d = idx & 63;
        const int pos = base + r;
        float kk = 0.f, vv = 0.f;
        if (pos >= 0 && pos < LL) {
            const size_t off = ((size_t)(b*LL + pos))*1536 + h*64 + d;
            kk = qkv[off + 512];
            vv = qkv[off + 1024];
        }
        ks[d][r] = kk;
        vs[d][r] = vv;
    }
    __syncthreads();

    const int l = q0 + tid;
    const float* qp = &qkv[((size_t)(b*LL + l))*1536 + h*64];

    float s[31];
#pragma unroll
    for (int j = 0; j < 31; j++) s[j] = 0.f;

#pragma unroll
    for (int c = 0; c < 4; c++) {
        float q[16];
#pragma unroll
        for (int d = 0; d < 16; d++) q[d] = qp[c*16 + d];
#pragma unroll
        for (int j = 0; j < 31; j++) {
            float dot = 0.f;
#pragma unroll
            for (int d = 0; d < 16; d++)
                dot = fmaf(q[d], ks[c*16 + d][tid + j], dot);
            s[j] += dot;
        }
    }

    float mx = -1e30f;
#pragma unroll
    for (int j = 0; j < 31; j++) {
        const int pos = l - 15 + j;
        if (pos < 0 || pos >= LL) s[j] = -1e30f;
        else                      s[j] *= 0.125f;
        mx = fmaxf(mx, s[j]);
    }
    float sum = 0.f;
#pragma unroll
    for (int j = 0; j < 31; j++) { s[j] = expf(s[j] - mx); sum += s[j]; }
    const float inv = 1.f / sum;

    float* op = &out[((size_t)(b*LL + l))*512 + h*64];
#pragma unroll
    for (int c = 0; c < 4; c++) {
        float o[16];
#pragma unroll
        for (int d = 0; d < 16; d++) o[d] = 0.f;
#pragma unroll
        for (int j = 0; j < 31; j++) {
            const float p = s[j];
#pragma unroll
            for (int d = 0; d < 16; d++)
                o[d] = fmaf(p, vs[c*16 + d][tid + j], o[d]);
        }
#pragma unroll
        for (int d = 0; d < 16; d++) op[c*16 + d] = o[d] * inv;
    }
}

// ---------------- fused residual add + LayerNorm (+clip) -------------------
template<bool CLIP>
__global__ __launch_bounds__(128) void add_ln_kernel(
    const float* __restrict__ a, const float* __restrict__ res,
    const float* __restrict__ gam, const float* __restrict__ bet,
    float* __restrict__ outp, int ldo)
{
    const int row = blockIdx.x;
    const int tid = threadIdx.x;
    const float* ap = a   + (size_t)row*512;
    const float* rp = res + (size_t)row*512;

    float v[4];
    float s = 0.f, s2 = 0.f;
#pragma unroll
    for (int i = 0; i < 4; i++) {
        const float x = ap[tid + 128*i] + rp[tid + 128*i];
        v[i] = x; s += x; s2 += x*x;
    }
    __shared__ float red[2][4];
#pragma unroll
    for (int o = 16; o > 0; o >>= 1) {
        s  += __shfl_down_sync(~0u, s,  o);
        s2 += __shfl_down_sync(~0u, s2, o);
    }
    const int wid = tid >> 5, lane = tid & 31;
    if (lane == 0) { red[0][wid] = s; red[1][wid] = s2; }
    __syncthreads();
    __shared__ float stats[2];
    if (tid == 0) {
        float ts = 0.f, ts2 = 0.f;
#pragma unroll
        for (int w = 0; w < 4; w++) { ts += red[0][w]; ts2 += red[1][w]; }
        const float mean = ts * (1.f/512.f);
        stats[0] = mean;
        stats[1] = rsqrtf(ts2 * (1.f/512.f) - mean*mean + 1e-5f);
    }
    __syncthreads();
    const float mean = stats[0], rstd = stats[1];
    float* op = outp + (size_t)row*ldo;
#pragma unroll
    for (int i = 0; i < 4; i++) {
        const int c = tid + 128*i;
        float y = (v[i] - mean) * rstd * gam[c] + bet[c];
        if (CLIP) y = fminf(fmaxf(y, -100.f), 100.f);
        op[c] = y;
    }
}

// ---------------- mean over sequence axis ----------------------------------
__global__ void mean_kernel(const float* __restrict__ x, float* __restrict__ outp)
{
    const int c = blockIdx.x*128 + threadIdx.x;
    const int b = blockIdx.y;
    const float* p = x + (size_t)b*LL*512 + c;
    float s = 0.f;
    for (int l = 0; l < LL; l++) s += p[(size_t)l*512];
    outp[b*512 + c] = s * (1.f/LL);
}

// ---------------- tiny per-batch GEMM --------------------------------------
__global__ __launch_bounds__(512) void vec_gemm_kernel(
    const float* __restrict__ A, const float* __restrict__ W,
    const float* __restrict__ bias, float* __restrict__ C)
{
    const int b = blockIdx.x, n = threadIdx.x;
    const float* a = A + b*512;
    float s = bias[n];
    for (int k = 0; k < 512; k++) s = fmaf(a[k], W[(size_t)k*512 + n], s);
    C[b*512 + n] = s;
}

// ---------------- broadcast add of per-batch vector ------------------------
__global__ void add_batch_kernel(float* __restrict__ C, const float* __restrict__ g)
{
    for (size_t idx = (size_t)blockIdx.x*blockDim.x + threadIdx.x;
         idx < (size_t)MROWS*512; idx += (size_t)gridDim.x*blockDim.x) {
        const int b = (int)(idx / ((size_t)LL*512));
        const int c = (int)(idx & 511);
        C[idx] += g[b*512 + c];
    }
}

// ---------------- small-N GEMM (N=18 or 5), K=256 --------------------------
__global__ void small_gemm_kernel(
    const float* __restrict__ A, const float* __restrict__ W,
    const float* __restrict__ bias, float* __restrict__ C, int N)
{
    const int idx = blockIdx.x*blockDim.x + threadIdx.x;
    if (idx >= MROWS*N) return;
    const int m = idx / N, n = idx - m*N;
    const float* a = A + (size_t)m*256;
    float s = bias[n];
    for (int k = 0; k < 256; k++) s = fmaf(a[k], W[k*N + n], s);
    C[idx] = s;
}

// ---------------- softmax(type_logits) @ type_emb -> si[:,512:544] ---------
__global__ __launch_bounds__(256) void type_emb_kernel(
    const float* __restrict__ logits, const float* __restrict__ emb,
    float* __restrict__ si)
{
    const int row  = blockIdx.x*8 + (threadIdx.x >> 5);
    const int lane = threadIdx.x & 31;
    if (row >= MROWS) return;
    const float* lp = logits + (size_t)row*18;
    float v[18];
    float mx = -1e30f;
#pragma unroll
    for (int j = 0; j < 18; j++) { v[j] = lp[j]; mx = fmaxf(mx, v[j]); }
    float sum = 0.f;
#pragma unroll
    for (int j = 0; j < 18; j++) { v[j] = expf(v[j] - mx); sum += v[j]; }
    const float inv = 1.f / sum;
    float o = 0.f;
#pragma unroll
    for (int j = 0; j < 18; j++) o = fmaf(v[j], emb[j*32 + lane], o);
    si[(size_t)row*544 + 512 + lane] = o * inv;
}

// ---------------- launch ----------------------------------------------------
extern "C" void kernel_launch(void* const* d_in, const int* in_sizes, int n_in,
                              void* d_out, int out_size)
{
    (void)in_sizes; (void)n_in; (void)out_size;
    const float* state = (const float*)d_in[0];
    const float* Wp    = (const float*)d_in[1];
    const float* bp    = (const float*)d_in[2];
    const float* Wqkv  = (const float*)d_in[3];
    const float* bqkv  = (const float*)d_in[4];
    const float* Wo    = (const float*)d_in[5];
    const float* bo    = (const float*)d_in[6];
    const float* ln_g  = (const float*)d_in[7];
    const float* ln_b  = (const float*)d_in[8];
    const float* Wg    = (const float*)d_in[9];
    const float* bg    = (const float*)d_in[10];
    const float* Wc    = (const float*)d_in[11];
    const float* bc    = (const float*)d_in[12];
    const float* W1    = (const float*)d_in[13];
    const float* b1    = (const float*)d_in[14];
    const float* W2    = (const float*)d_in[15];
    const float* b2    = (const float*)d_in[16];
    const float* fn_g  = (const float*)d_in[17];
    const float* fn_b  = (const float*)d_in[18];
    const float* Wt1   = (const float*)d_in[19];
    const float* bt1   = (const float*)d_in[20];
    const float* Wt2   = (const float*)d_in[21];
    const float* bt2   = (const float*)d_in[22];
    const float* temb  = (const float*)d_in[23];
    const float* Ws1   = (const float*)d_in[24];
    const float* bs1   = (const float*)d_in[25];
    const float* Ws2   = (const float*)d_in[26];
    const float* bs2   = (const float*)d_in[27];
    const float* Wa1   = (const float*)d_in[28];
    const float* ba1   = (const float*)d_in[29];
    const float* Wa2   = (const float*)d_in[30];
    const float* ba2   = (const float*)d_in[31];

    float* out = (float*)d_out;

    static float *px=nullptr,*ploc,*pqkv,*patt,*ptmp,*pcomb,*psi,*ph256,*pmean,*pgsum,*pgpart;
    if (!px) {
        cudaGetSymbolAddress((void**)&px,    g_x);
        cudaGetSymbolAddress((void**)&ploc,  g_loc);
        cudaGetSymbolAddress((void**)&pqkv,  g_qkv);
        cudaGetSymbolAddress((void**)&patt,  g_att);
        cudaGetSymbolAddress((void**)&ptmp,  g_tmp);
        cudaGetSymbolAddress((void**)&pcomb, g_comb);
        cudaGetSymbolAddress((void**)&psi,   g_si);
        cudaGetSymbolAddress((void**)&ph256, g_h256);
        cudaGetSymbolAddress((void**)&pmean, g_mean);
        cudaGetSymbolAddress((void**)&pgsum, g_gsum);
        cudaGetSymbolAddress((void**)&pgpart,g_gpart);
    }

    const dim3 thr(256);

    // 1. x = state @ Wp + bp
    gemm_tc<0><<<dim3(512/64, MROWS/128), thr>>>(state, DIN, Wp, bp, px, 512, DIN);

    // 2. two NATTEN layers
    const float* locIn = px;
    for (int i = 0; i < 2; i++) {
        gemm_tc<0><<<dim3(1536/64, MROWS/128), thr>>>(locIn, 512, Wqkv + (size_t)i*512*1536,
                                                      bqkv + i*1536, pqkv, 1536, 512);
        natten_kernel<<<dim3(LL/64, NHEAD, BB), 64>>>(pqkv, patt);
        gemm_tc<0><<<dim3(512/64, MROWS/128), thr>>>(patt, 512, Wo + (size_t)i*512*512,
                                                     bo + i*512, ptmp, 512, 512);
        add_ln_kernel<false><<<MROWS, 128>>>(ptmp, locIn, ln_g + i*512, ln_b + i*512, ploc, 512);
        locIn = ploc;
    }

    // 3. global summary path (per-batch, tiny, fp32 exact)
    mean_kernel<<<dim3(4, BB), 128>>>(px, pmean);
    vec_gemm_kernel<<<BB, 512>>>(pmean, Wg, bg, pgsum);
    vec_gemm_kernel<<<BB, 512>>>(pgsum, Wc + (size_t)512*512, bc, pgpart);

    // 4. comb = loc @ Wc[:512] + gpart[b]
    gemm_tc<0><<<dim3(512/64, MROWS/128), thr>>>(ploc, 512, Wc, nullptr, pcomb, 512, 512);
    add_batch_kernel<<<8192, 256>>>(pcomb, pgpart);

    // 5. FFN + LN(clip) -> enc (into si[:, :512], stride 544)
    gemm_tc<2><<<dim3(1024/64, MROWS/128), thr>>>(pcomb, 512, W1, b1, ptmp, 1024, 512);
    gemm_tc<0><<<dim3(512/64, MROWS/128), thr>>>(ptmp, 1024, W2, b2, patt, 512, 1024);
    add_ln_kernel<true><<<MROWS, 128>>>(patt, pcomb, fn_g, fn_b, psi, 544);

    // 6. type head: logits straight to d_out, then softmax@emb -> si[:,512:]
    gemm_tc<1><<<dim3(256/64, MROWS/128), thr>>>(psi, 544, Wt1, bt1, ph256, 256, 512);
    small_gemm_kernel<<<(MROWS*18 + 255)/256, 256>>>(ph256, Wt2, bt2, out, 18);
    type_emb_kernel<<<MROWS/8, 256>>>(out, temb, psi);

    // 7. size head
    gemm_tc<1><<<dim3(256/64, MROWS/128), thr>>>(psi, 544, Ws1, bs1, ph256, 256, 544);
    small_gemm_kernel<<<(MROWS*5 + 255)/256, 256>>>(ph256, Ws2, bs2, out + (size_t)MROWS*18, 5);

    // 8. amount head
    gemm_tc<1><<<dim3(256/64, MROWS/128), thr>>>(psi, 544, Wa1, ba1, ph256, 256, 544);
    small_gemm_kernel<<<(MROWS*5 + 255)/256, 256>>>(ph256, Wa2, ba2, out + (size_t)MROWS*23, 5);
}

// round 3
// speedup vs baseline: 2.0073x; 1.1056x over previous
#include <cuda_runtime.h>
#include <math.h>
#include <stdint.h>

#define BB 8
#define LL 1024
#define DIN 256
#define HH 512
#define NHEAD 8
#define HD 64
#define MROWS (BB*LL)   // 8192

// ---------------- scratch (device globals; no allocations) ----------------
__device__ float g_x   [MROWS*HH];
__device__ float g_loc [MROWS*HH];
__device__ float g_qkv [MROWS*3*HH];
__device__ float g_att [MROWS*HH];
__device__ float g_tmp [MROWS*2*HH];
__device__ float g_comb[MROWS*HH];
__device__ float g_si  [MROWS*544];      // [enc(512) | temb(32)]
__device__ float g_h256[MROWS*256];
__device__ float g_pmean[16*BB*HH];
__device__ float g_mean [BB*HH];
__device__ float g_gsum [BB*HH];
__device__ float g_gpart[BB*HH];

// ---------------- tf32 helpers ---------------------------------------------
__device__ __forceinline__ uint32_t f2tf32(float f) {
    uint32_t r;
    asm("cvt.rna.tf32.f32 %0, %1;" : "=r"(r) : "f"(f));
    return r;
}

__device__ __forceinline__ void mma_tf32(
    float& d0, float& d1, float& d2, float& d3,
    uint32_t a0, uint32_t a1, uint32_t a2, uint32_t a3,
    uint32_t b0, uint32_t b1)
{
    asm volatile(
        "mma.sync.aligned.m16n8k8.row.col.f32.tf32.tf32.f32 "
        "{%0,%1,%2,%3}, {%4,%5,%6,%7}, {%8,%9}, {%0,%1,%2,%3};"
        : "+f"(d0), "+f"(d1), "+f"(d2), "+f"(d3)
        : "r"(a0), "r"(a1), "r"(a2), "r"(a3), "r"(b0), "r"(b1));
}

// ---------------- tf32 tensor-core GEMM, double-buffered -------------------
// C[M,N] = act(A[M,K] @ W[K,N] + bias [+ gb[batch]]).
// Tile 128x128x32, 512 threads (16 warps 4x4, warp tile 32x32).
// Requires M%128==0, N%128==0, K%32==0, lda%4==0.
#define A_STRIDE 36
#define B_STRIDE 136
#define A_BUF (128*A_STRIDE)
#define B_BUF (32*B_STRIDE)
#define SMEM_GEMM ((2*A_BUF + 2*B_BUF)*4)   // 71680 bytes

template<int ACT, bool BBIAS>  // ACT: 0=none 1=relu 2=gelu(exact)
__global__ __launch_bounds__(512) void gemm_tc2(
    const float* __restrict__ A, int lda,
    const float* __restrict__ W,
    const float* __restrict__ bias,
    const float* __restrict__ gb,   // per-batch bias [BB][N] if BBIAS
    float* __restrict__ C, int N, int K)
{
    extern __shared__ uint32_t sh[];
    uint32_t* As0 = sh;                // 2 x [128][A_STRIDE]
    uint32_t* Bs0 = sh + 2*A_BUF;      // 2 x [32][B_STRIDE]

    const int tid  = threadIdx.x;
    const int warp = tid >> 5;
    const int lane = tid & 31;
    const int wm = warp >> 2;          // 0..3 -> m offset 32*wm
    const int wn = warp & 3;           // 0..3 -> n offset 32*wn
    const int qr = lane >> 2;          // 0..7
    const int qc = lane & 3;           // 0..3

    const int m0 = blockIdx.y * 128;
    const int n0 = blockIdx.x * 128;

    // loader indices (512 threads)
    const int am = tid >> 3;           // 0..63 (two rows: am, am+64)
    const int ak = (tid & 7) * 4;      // 0..28
    const int bk = tid >> 5;           // 0..15 (two rows: bk, bk+16)
    const int bn = (tid & 31) * 4;     // 0..124

    const float* Aptr = A + (size_t)(m0 + am)*lda + ak;
    const float* Wptr = W + (size_t)bk*N + n0 + bn;

    float acc[2][4][4];
#pragma unroll
    for (int i = 0; i < 2; i++)
#pragma unroll
        for (int j = 0; j < 4; j++)
#pragma unroll
            for (int c = 0; c < 4; c++) acc[i][j][c] = 0.f;

    float4 ar0, ar1, br0, br1;
    // prologue: load k-tile 0
    ar0 = *(const float4*)(Aptr);
    ar1 = *(const float4*)(Aptr + (size_t)64*lda);
    br0 = *(const float4*)(Wptr);
    br1 = *(const float4*)(Wptr + (size_t)16*N);

    // store tile 0 into buf 0
    {
        uint32_t* As = As0;
        uint32_t* Bs = Bs0;
        uint4 u;
        u.x=f2tf32(ar0.x); u.y=f2tf32(ar0.y); u.z=f2tf32(ar0.z); u.w=f2tf32(ar0.w);
        *(uint4*)&As[am*A_STRIDE + ak] = u;
        u.x=f2tf32(ar1.x); u.y=f2tf32(ar1.y); u.z=f2tf32(ar1.z); u.w=f2tf32(ar1.w);
        *(uint4*)&As[(am+64)*A_STRIDE + ak] = u;
        u.x=f2tf32(br0.x); u.y=f2tf32(br0.y); u.z=f2tf32(br0.z); u.w=f2tf32(br0.w);
        *(uint4*)&Bs[bk*B_STRIDE + bn] = u;
        u.x=f2tf32(br1.x); u.y=f2tf32(br1.y); u.z=f2tf32(br1.z); u.w=f2tf32(br1.w);
        *(uint4*)&Bs[(bk+16)*B_STRIDE + bn] = u;
    }
    __syncthreads();

    const int nk = K >> 5;
    int buf = 0;

    for (int kt = 0; kt < nk; kt++) {
        // prefetch next tile into registers (overlaps with MMA below)
        if (kt + 1 < nk) {
            const float* Ap = Aptr + (kt+1)*32;
            ar0 = *(const float4*)(Ap);
            ar1 = *(const float4*)(Ap + (size_t)64*lda);
            const float* Wp = Wptr + (size_t)(kt+1)*32*N;
            br0 = *(const float4*)(Wp);
            br1 = *(const float4*)(Wp + (size_t)16*N);
        }

        // compute on current buffer
        const uint32_t* As = As0 + buf*A_BUF;
        const uint32_t* Bs = Bs0 + buf*B_BUF;
#pragma unroll
        for (int kk = 0; kk < 32; kk += 8) {
            uint32_t a[2][4], b[4][2];
#pragma unroll
            for (int mf = 0; mf < 2; mf++) {
                const int mb = wm*32 + mf*16;
                a[mf][0] = As[(mb + qr    )*A_STRIDE + kk + qc];
                a[mf][1] = As[(mb + qr + 8)*A_STRIDE + kk + qc];
                a[mf][2] = As[(mb + qr    )*A_STRIDE + kk + qc + 4];
                a[mf][3] = As[(mb + qr + 8)*A_STRIDE + kk + qc + 4];
            }
#pragma unroll
            for (int nf = 0; nf < 4; nf++) {
                const int nb = wn*32 + nf*8 + qr;
                b[nf][0] = Bs[(kk + qc    )*B_STRIDE + nb];
                b[nf][1] = Bs[(kk + qc + 4)*B_STRIDE + nb];
            }
#pragma unroll
            for (int mf = 0; mf < 2; mf++)
#pragma unroll
                for (int nf = 0; nf < 4; nf++)
                    mma_tf32(acc[mf][nf][0], acc[mf][nf][1],
                             acc[mf][nf][2], acc[mf][nf][3],
                             a[mf][0], a[mf][1], a[mf][2], a[mf][3],
                             b[nf][0], b[nf][1]);
        }

        // store prefetched tile into other buffer, single sync, swap
        if (kt + 1 < nk) {
            uint32_t* Asn = As0 + (buf^1)*A_BUF;
            uint32_t* Bsn = Bs0 + (buf^1)*B_BUF;
            uint4 u;
            u.x=f2tf32(ar0.x); u.y=f2tf32(ar0.y); u.z=f2tf32(ar0.z); u.w=f2tf32(ar0.w);
            *(uint4*)&Asn[am*A_STRIDE + ak] = u;
            u.x=f2tf32(ar1.x); u.y=f2tf32(ar1.y); u.z=f2tf32(ar1.z); u.w=f2tf32(ar1.w);
            *(uint4*)&Asn[(am+64)*A_STRIDE + ak] = u;
            u.x=f2tf32(br0.x); u.y=f2tf32(br0.y); u.z=f2tf32(br0.z); u.w=f2tf32(br0.w);
            *(uint4*)&Bsn[bk*B_STRIDE + bn] = u;
            u.x=f2tf32(br1.x); u.y=f2tf32(br1.y); u.z=f2tf32(br1.z); u.w=f2tf32(br1.w);
            *(uint4*)&Bsn[(bk+16)*B_STRIDE + bn] = u;
            __syncthreads();
            buf ^= 1;
        }
    }

    // epilogue
    const int batch = m0 >> 10;   // 1024 rows per batch, 128 | 1024
#pragma unroll
    for (int mf = 0; mf < 2; mf++) {
#pragma unroll
        for (int nf = 0; nf < 4; nf++) {
            const int n = n0 + wn*32 + nf*8 + qc*2;
            float bx = 0.f, by = 0.f;
            if (bias) { bx = bias[n]; by = bias[n+1]; }
            if (BBIAS) { bx += gb[batch*N + n]; by += gb[batch*N + n + 1]; }
#pragma unroll
            for (int half = 0; half < 2; half++) {
                const int m = m0 + wm*32 + mf*16 + qr + half*8;
                float v0 = acc[mf][nf][half*2+0] + bx;
                float v1 = acc[mf][nf][half*2+1] + by;
                if (ACT == 1) { v0 = fmaxf(v0, 0.f); v1 = fmaxf(v1, 0.f); }
                else if (ACT == 2) {
                    v0 = 0.5f*v0*(1.f + erff(v0*0.70710678118654752f));
                    v1 = 0.5f*v1*(1.f + erff(v1*0.70710678118654752f));
                }
                *(float2*)&C[(size_t)m*N + n] = make_float2(v0, v1);
            }
        }
    }
}

// ---------------- windowed attention (NATTEN, window 31) -------------------
__global__ __launch_bounds__(64) void natten_kernel(
    const float* __restrict__ qkv, float* __restrict__ out)
{
    const int qt = blockIdx.x;
    const int h  = blockIdx.y;
    const int b  = blockIdx.z;
    const int q0 = qt * 64;
    const int base = q0 - 15;

    __shared__ float ks[64][95];
    __shared__ float vs[64][95];

    const int tid = threadIdx.x;
    for (int idx = tid; idx < 94*64; idx += 64) {
        const int r = idx >> 6;
        const int d = idx & 63;
        const int pos = base + r;
        float kk = 0.f, vv = 0.f;
        if (pos >= 0 && pos < LL) {
            const size_t off = ((size_t)(b*LL + pos))*1536 + h*64 + d;
            kk = qkv[off + 512];
            vv = qkv[off + 1024];
        }
        ks[d][r] = kk;
        vs[d][r] = vv;
    }
    __syncthreads();

    const int l = q0 + tid;
    const float* qp = &qkv[((size_t)(b*LL + l))*1536 + h*64];

    float s[31];
#pragma unroll
    for (int j = 0; j < 31; j++) s[j] = 0.f;

#pragma unroll
    for (int c = 0; c < 4; c++) {
        float q[16];
#pragma unroll
        for (int d = 0; d < 16; d++) q[d] = qp[c*16 + d];
#pragma unroll
        for (int j = 0; j < 31; j++) {
            float dot = 0.f;
#pragma unroll
            for (int d = 0; d < 16; d++)
                dot = fmaf(q[d], ks[c*16 + d][tid + j], dot);
            s[j] += dot;
        }
    }

    float mx = -1e30f;
#pragma unroll
    for (int j = 0; j < 31; j++) {
        const int pos = l - 15 + j;
        if (pos < 0 || pos >= LL) s[j] = -1e30f;
        else                      s[j] *= 0.125f;
        mx = fmaxf(mx, s[j]);
    }
    float sum = 0.f;
#pragma unroll
    for (int j = 0; j < 31; j++) { s[j] = expf(s[j] - mx); sum += s[j]; }
    const float inv = 1.f / sum;

    float* op = &out[((size_t)(b*LL + l))*512 + h*64];
#pragma unroll
    for (int c = 0; c < 4; c++) {
        float o[16];
#pragma unroll
        for (int d = 0; d < 16; d++) o[d] = 0.f;
#pragma unroll
        for (int j = 0; j < 31; j++) {
            const float p = s[j];
#pragma unroll
            for (int d = 0; d < 16; d++)
                o[d] = fmaf(p, vs[c*16 + d][tid + j], o[d]);
        }
#pragma unroll
        for (int d = 0; d < 16; d++) op[c*16 + d] = o[d] * inv;
    }
}

// ---------------- fused residual add + LayerNorm (+clip) -------------------
template<bool CLIP>
__global__ __launch_bounds__(128) void add_ln_kernel(
    const float* __restrict__ a, const float* __restrict__ res,
    const float* __restrict__ gam, const float* __restrict__ bet,
    float* __restrict__ outp, int ldo)
{
    const int row = blockIdx.x;
    const int tid = threadIdx.x;
    const float* ap = a   + (size_t)row*512;
    const float* rp = res + (size_t)row*512;

    float v[4];
    float s = 0.f, s2 = 0.f;
#pragma unroll
    for (int i = 0; i < 4; i++) {
        const float x = ap[tid + 128*i] + rp[tid + 128*i];
        v[i] = x; s += x; s2 += x*x;
    }
    __shared__ float red[2][4];
#pragma unroll
    for (int o = 16; o > 0; o >>= 1) {
        s  += __shfl_down_sync(~0u, s,  o);
        s2 += __shfl_down_sync(~0u, s2, o);
    }
    const int wid = tid >> 5, lane = tid & 31;
    if (lane == 0) { red[0][wid] = s; red[1][wid] = s2; }
    __syncthreads();
    __shared__ float stats[2];
    if (tid == 0) {
        float ts = 0.f, ts2 = 0.f;
#pragma unroll
        for (int w = 0; w < 4; w++) { ts += red[0][w]; ts2 += red[1][w]; }
        const float mean = ts * (1.f/512.f);
        stats[0] = mean;
        stats[1] = rsqrtf(ts2 * (1.f/512.f) - mean*mean + 1e-5f);
    }
    __syncthreads();
    const float mean = stats[0], rstd = stats[1];
    float* op = outp + (size_t)row*ldo;
#pragma unroll
    for (int i = 0; i < 4; i++) {
        const int c = tid + 128*i;
        float y = (v[i] - mean) * rstd * gam[c] + bet[c];
        if (CLIP) y = fminf(fmaxf(y, -100.f), 100.f);
        op[c] = y;
    }
}

// ---------------- two-stage mean over sequence axis ------------------------
__global__ void mean1_kernel(const float* __restrict__ x, float* __restrict__ outp)
{
    const int c = blockIdx.x*128 + threadIdx.x;  // grid (4, BB, 16)
    const int b = blockIdx.y;
    const int z = blockIdx.z;
    const float* p = x + ((size_t)b*LL + z*64)*512 + c;
    float s = 0.f;
#pragma unroll 4
    for (int l = 0; l < 64; l++) s += p[(size_t)l*512];
    outp[(z*BB + b)*512 + c] = s;
}
__global__ void mean2_kernel(const float* __restrict__ part, float* __restrict__ outp)
{
    const int c = blockIdx.x*128 + threadIdx.x;  // grid (4, BB)
    const int b = blockIdx.y;
    float s = 0.f;
#pragma unroll
    for (int z = 0; z < 16; z++) s += part[(z*BB + b)*512 + c];
    outp[b*512 + c] = s * (1.f/LL);
}

// ---------------- tiny per-batch GEMM --------------------------------------
__global__ __launch_bounds__(512) void vec_gemm_kernel(
    const float* __restrict__ A, const float* __restrict__ W,
    const float* __restrict__ bias, float* __restrict__ C)
{
    const int b = blockIdx.x, n = threadIdx.x;
    const float* a = A + b*512;
    float s = bias[n];
    for (int k = 0; k < 512; k++) s = fmaf(a[k], W[(size_t)k*512 + n], s);
    C[b*512 + n] = s;
}

// ---------------- small-N GEMM (N=18 or 5), K=256 --------------------------
__global__ void small_gemm_kernel(
    const float* __restrict__ A, const float* __restrict__ W,
    const float* __restrict__ bias, float* __restrict__ C, int N)
{
    const int idx = blockIdx.x*blockDim.x + threadIdx.x;
    if (idx >= MROWS*N) return;
    const int m = idx / N, n = idx - m*N;
    const float* a = A + (size_t)m*256;
    float s0 = bias[n], s1 = 0.f, s2 = 0.f, s3 = 0.f;
    for (int k = 0; k < 256; k += 4) {
        const float4 av = *(const float4*)&a[k];
        s0 = fmaf(av.x, W[(k  )*N + n], s0);
        s1 = fmaf(av.y, W[(k+1)*N + n], s1);
        s2 = fmaf(av.z, W[(k+2)*N + n], s2);
        s3 = fmaf(av.w, W[(k+3)*N + n], s3);
    }
    C[idx] = (s0 + s1) + (s2 + s3);
}

// ---------------- softmax(type_logits) @ type_emb -> si[:,512:544] ---------
__global__ __launch_bounds__(256) void type_emb_kernel(
    const float* __restrict__ logits, const float* __restrict__ emb,
    float* __restrict__ si)
{
    const int row  = blockIdx.x*8 + (threadIdx.x >> 5);
    const int lane = threadIdx.x & 31;
    if (row >= MROWS) return;
    const float* lp = logits + (size_t)row*18;
    float v[18];
    float mx = -1e30f;
#pragma unroll
    for (int j = 0; j < 18; j++) { v[j] = lp[j]; mx = fmaxf(mx, v[j]); }
    float sum = 0.f;
#pragma unroll
    for (int j = 0; j < 18; j++) { v[j] = expf(v[j] - mx); sum += v[j]; }
    const float inv = 1.f / sum;
    float o = 0.f;
#pragma unroll
    for (int j = 0; j < 18; j++) o = fmaf(v[j], emb[j*32 + lane], o);
    si[(size_t)row*544 + 512 + lane] = o * inv;
}

// ---------------- launch ----------------------------------------------------
extern "C" void kernel_launch(void* const* d_in, const int* in_sizes, int n_in,
                              void* d_out, int out_size)
{
    (void)in_sizes; (void)n_in; (void)out_size;
    const float* state = (const float*)d_in[0];
    const float* Wp    = (const float*)d_in[1];
    const float* bp    = (const float*)d_in[2];
    const float* Wqkv  = (const float*)d_in[3];
    const float* bqkv  = (const float*)d_in[4];
    const float* Wo    = (const float*)d_in[5];
    const float* bo    = (const float*)d_in[6];
    const float* ln_g  = (const float*)d_in[7];
    const float* ln_b  = (const float*)d_in[8];
    const float* Wg    = (const float*)d_in[9];
    const float* bg    = (const float*)d_in[10];
    const float* Wc    = (const float*)d_in[11];
    const float* bc    = (const float*)d_in[12];
    const float* W1    = (const float*)d_in[13];
    const float* b1    = (const float*)d_in[14];
    const float* W2    = (const float*)d_in[15];
    const float* b2    = (const float*)d_in[16];
    const float* fn_g  = (const float*)d_in[17];
    const float* fn_b  = (const float*)d_in[18];
    const float* Wt1   = (const float*)d_in[19];
    const float* bt1   = (const float*)d_in[20];
    const float* Wt2   = (const float*)d_in[21];
    const float* bt2   = (const float*)d_in[22];
    const float* temb  = (const float*)d_in[23];
    const float* Ws1   = (const float*)d_in[24];
    const float* bs1   = (const float*)d_in[25];
    const float* Ws2   = (const float*)d_in[26];
    const float* bs2   = (const float*)d_in[27];
    const float* Wa1   = (const float*)d_in[28];
    const float* ba1   = (const float*)d_in[29];
    const float* Wa2   = (const float*)d_in[30];
    const float* ba2   = (const float*)d_in[31];

    float* out = (float*)d_out;

    static float *px=nullptr,*ploc,*pqkv,*patt,*ptmp,*pcomb,*psi,*ph256,*ppm,*pmean,*pgsum,*pgpart;
    if (!px) {
        cudaGetSymbolAddress((void**)&px,    g_x);
        cudaGetSymbolAddress((void**)&ploc,  g_loc);
        cudaGetSymbolAddress((void**)&pqkv,  g_qkv);
        cudaGetSymbolAddress((void**)&patt,  g_att);
        cudaGetSymbolAddress((void**)&ptmp,  g_tmp);
        cudaGetSymbolAddress((void**)&pcomb, g_comb);
        cudaGetSymbolAddress((void**)&psi,   g_si);
        cudaGetSymbolAddress((void**)&ph256, g_h256);
        cudaGetSymbolAddress((void**)&ppm,   g_pmean);
        cudaGetSymbolAddress((void**)&pmean, g_mean);
        cudaGetSymbolAddress((void**)&pgsum, g_gsum);
        cudaGetSymbolAddress((void**)&pgpart,g_gpart);
        // opt-in to >48KB dynamic shared memory (host-side config, pre-capture)
        cudaFuncSetAttribute(gemm_tc2<0,false>, cudaFuncAttributeMaxDynamicSharedMemorySize, SMEM_GEMM);
        cudaFuncSetAttribute(gemm_tc2<0,true >, cudaFuncAttributeMaxDynamicSharedMemorySize, SMEM_GEMM);
        cudaFuncSetAttribute(gemm_tc2<1,false>, cudaFuncAttributeMaxDynamicSharedMemorySize, SMEM_GEMM);
        cudaFuncSetAttribute(gemm_tc2<2,false>, cudaFuncAttributeMaxDynamicSharedMemorySize, SMEM_GEMM);
    }

    const dim3 thr(512);
    #define GRID(NN) dim3((NN)/128, MROWS/128)

    // 1. x = state @ Wp + bp
    gemm_tc2<0,false><<<GRID(512), thr, SMEM_GEMM>>>(state, DIN, Wp, bp, nullptr, px, 512, DIN);

    // 2. two NATTEN layers
    const float* locIn = px;
    for (int i = 0; i < 2; i++) {
        gemm_tc2<0,false><<<GRID(1536), thr, SMEM_GEMM>>>(locIn, 512, Wqkv + (size_t)i*512*1536,
                                                          bqkv + i*1536, nullptr, pqkv, 1536, 512);
        natten_kernel<<<dim3(LL/64, NHEAD, BB), 64>>>(pqkv, patt);
        gemm_tc2<0,false><<<GRID(512), thr, SMEM_GEMM>>>(patt, 512, Wo + (size_t)i*512*512,
                                                         bo + i*512, nullptr, ptmp, 512, 512);
        add_ln_kernel<false><<<MROWS, 128>>>(ptmp, locIn, ln_g + i*512, ln_b + i*512, ploc, 512);
        locIn = ploc;
    }

    // 3. global summary path (per-batch, tiny, fp32 exact)
    mean1_kernel<<<dim3(4, BB, 16), 128>>>(px, ppm);
    mean2_kernel<<<dim3(4, BB), 128>>>(ppm, pmean);
    vec_gemm_kernel<<<BB, 512>>>(pmean, Wg, bg, pgsum);
    vec_gemm_kernel<<<BB, 512>>>(pgsum, Wc + (size_t)512*512, bc, pgpart);

    // 4. comb = loc @ Wc[:512] + gpart[batch]  (batch bias fused in epilogue)
    gemm_tc2<0,true><<<GRID(512), thr, SMEM_GEMM>>>(ploc, 512, Wc, nullptr, pgpart, pcomb, 512, 512);

    // 5. FFN + LN(clip) -> enc (into si[:, :512], stride 544)
    gemm_tc2<2,false><<<GRID(1024), thr, SMEM_GEMM>>>(pcomb, 512, W1, b1, nullptr, ptmp, 1024, 512);
    gemm_tc2<0,false><<<GRID(512), thr, SMEM_GEMM>>>(ptmp, 1024, W2, b2, nullptr, patt, 512, 1024);
    add_ln_kernel<true><<<MROWS, 128>>>(patt, pcomb, fn_g, fn_b, psi, 544);

    // 6. type head: logits straight to d_out, then softmax@emb -> si[:,512:]
    gemm_tc2<1,false><<<GRID(256), thr, SMEM_GEMM>>>(psi, 544, Wt1, bt1, nullptr, ph256, 256, 512);
    small_gemm_kernel<<<(MROWS*18 + 255)/256, 256>>>(ph256, Wt2, bt2, out, 18);
    type_emb_kernel<<<MROWS/8, 256>>>(out, temb, psi);

    // 7. size head
    gemm_tc2<1,false><<<GRID(256), thr, SMEM_GEMM>>>(psi, 544, Ws1, bs1, nullptr, ph256, 256, 544);
    small_gemm_kernel<<<(MROWS*5 + 255)/256, 256>>>(ph256, Ws2, bs2, out + (size_t)MROWS*18, 5);

    // 8. amount head
    gemm_tc2<1,false><<<GRID(256), thr, SMEM_GEMM>>>(psi, 544, Wa1, ba1, nullptr, ph256, 256, 544);
    small_gemm_kernel<<<(MROWS*5 + 255)/256, 256>>>(ph256, Wa2, ba2, out + (size_t)MROWS*23, 5);
}

// round 5
// speedup vs baseline: 2.2094x; 1.1007x over previous
#include <cuda_runtime.h>
#include <math.h>
#include <stdint.h>

#define BB 8
#define LL 1024
#define DIN 256
#define HH 512
#define NHEAD 8
#define MROWS (BB*LL)   // 8192

// ---------------- scratch (device globals; no allocations) ----------------
__device__ float g_x   [MROWS*HH];
__device__ float g_loc [MROWS*HH];
__device__ float g_qkv [MROWS*3*HH];
__device__ float g_att [MROWS*HH];
__device__ float g_tmp [MROWS*2*HH];
__device__ float g_comb[MROWS*HH];
__device__ float g_si  [MROWS*544];
__device__ float g_h256[MROWS*256];
__device__ float g_pmean[16*BB*HH];
__device__ float g_mean [BB*HH];
__device__ float g_gsum [BB*HH];
__device__ float g_gpart[BB*HH];
__device__ float g_bsa  [512];
__device__ float g_wt  [3948544];       // transposed (tf32-rounded) weights

// transposed-weight offsets (floats)
#define WT_P    0
#define WT_QKV0 131072
#define WT_QKV1 917504
#define WT_O0   1703936
#define WT_O1   1966080
#define WT_C    2228224
#define WT_1    2490368
#define WT_2    3014656
#define WT_T1   3538944
#define WT_SA   3670016     // Ws1^T rows 0..255, Wa1^T rows 256..511 (K=544)

// ---------------- helpers ---------------------------------------------------
__device__ __forceinline__ uint32_t f2tf32(float f) {
    uint32_t r; asm("cvt.rna.tf32.f32 %0, %1;" : "=r"(r) : "f"(f)); return r;
}
__device__ __forceinline__ uint32_t s2u(const void* p) {
    uint32_t a;
    asm("{ .reg .u64 t; cvta.to.shared.u64 t, %1; cvt.u32.u64 %0, t; }" : "=r"(a) : "l"(p));
    return a;
}
__device__ __forceinline__ void cpa16(uint32_t sdst, const void* gsrc) {
    asm volatile("cp.async.cg.shared.global [%0], [%1], 16;" :: "r"(sdst), "l"(gsrc) : "memory");
}
#define CP_COMMIT() asm volatile("cp.async.commit_group;" ::: "memory")
#define CP_WAIT1()  asm volatile("cp.async.wait_group 1;" ::: "memory")

__device__ __forceinline__ void mma_tf32(
    float& d0, float& d1, float& d2, float& d3,
    uint32_t a0, uint32_t a1, uint32_t a2, uint32_t a3,
    uint32_t b0, uint32_t b1)
{
    asm volatile(
        "mma.sync.aligned.m16n8k8.row.col.f32.tf32.tf32.f32 "
        "{%0,%1,%2,%3}, {%4,%5,%6,%7}, {%8,%9}, {%0,%1,%2,%3};"
        : "+f"(d0), "+f"(d1), "+f"(d2), "+f"(d3)
        : "r"(a0), "r"(a1), "r"(a2), "r"(a3), "r"(b0), "r"(b1));
}

// ---------------- cp.async tf32 GEMM ----------------------------------------
// C[M,N] = act(A[M,K] @ W[K,N] + bias [+ gb[batch]]).  Wt = rounded W^T [N][K].
// Block tile 256x128 (512 thr, 16 warps 8x2, warp tile 32x64), 3-stage cp.async.
// M%256==0, N%128==0, K%32==0, lda%4==0.
#define STG 3
#define SA_ST 36
#define ST_A_FL (256*SA_ST)          // floats per A stage (9216)
#define ST_B_FL (128*SA_ST)          // floats per B stage (4608)
#define ST_FL   (ST_A_FL + ST_B_FL)  // 13824 floats
#define SMEM_CP (STG*ST_FL*4)        // 165888 bytes

template<int ACT, bool BBIAS>  // ACT: 0=none 1=relu 2=gelu(exact)
__global__ __launch_bounds__(512) void gemm_cp(
    const float* __restrict__ A, int lda,
    const float* __restrict__ Wt,
    const float* __restrict__ bias,
    const float* __restrict__ gb,
    float* __restrict__ C, int N, int K)
{
    extern __shared__ float sm[];
    const uint32_t sbase = s2u(sm);

    const int tid  = threadIdx.x;
    const int warp = tid >> 5;
    const int lane = tid & 31;
    const int wm = warp >> 1;          // 0..7 -> m offset 32*wm
    const int wn = warp & 1;           // 0..1 -> n offset 64*wn
    const int qr = lane >> 2;          // 0..7
    const int qc = lane & 3;           // 0..3

    const int m0 = blockIdx.y * 256;
    const int n0 = blockIdx.x * 128;
    const int nk = K >> 5;

    // cp.async loader indices
    const int lrow = tid >> 3;         // 0..63
    const int lc4  = (tid & 7) * 4;    // 0..28

    const float* Abase = A + (size_t)(m0 + lrow) * lda + lc4;
    const float* Bbase = Wt + (size_t)(n0 + lrow) * K + lc4;

#define STAGE_LOAD(kt) do {                                                   \
        const uint32_t sA = sbase + ((kt) % STG) * (ST_FL*4);                 \
        const uint32_t sB = sA + ST_A_FL*4;                                   \
        _Pragma("unroll")                                                     \
        for (int it = 0; it < 4; it++)                                        \
            cpa16(sA + ((lrow + 64*it)*SA_ST + lc4)*4,                        \
                  Abase + (size_t)(64*it)*lda + (kt)*32);                     \
        _Pragma("unroll")                                                     \
        for (int it = 0; it < 2; it++)                                        \
            cpa16(sB + ((lrow + 64*it)*SA_ST + lc4)*4,                        \
                  Bbase + (size_t)(64*it)*K + (kt)*32);                       \
        CP_COMMIT();                                                          \
    } while (0)

    float acc[2][8][4];
#pragma unroll
    for (int i = 0; i < 2; i++)
#pragma unroll
        for (int j = 0; j < 8; j++)
#pragma unroll
            for (int c = 0; c < 4; c++) acc[i][j][c] = 0.f;

    STAGE_LOAD(0);
    STAGE_LOAD(1);

    for (int kt = 0; kt < nk; kt++) {
        CP_WAIT1();                     // stage kt arrived
        __syncthreads();                // all threads done with buffer (kt)%STG's prior use
        if (kt + 2 < nk) STAGE_LOAD(kt + 2);

        const float* As = sm + (kt % STG) * ST_FL;
        const float* Bs = As + ST_A_FL;
#pragma unroll
        for (int kk = 0; kk < 32; kk += 8) {
            uint32_t a[2][4], b[8][2];
#pragma unroll
            for (int mf = 0; mf < 2; mf++) {
                const int mb = wm*32 + mf*16;
                a[mf][0] = f2tf32(As[(mb + qr    )*SA_ST + kk + qc]);
                a[mf][1] = f2tf32(As[(mb + qr + 8)*SA_ST + kk + qc]);
                a[mf][2] = f2tf32(As[(mb + qr    )*SA_ST + kk + qc + 4]);
                a[mf][3] = f2tf32(As[(mb + qr + 8)*SA_ST + kk + qc + 4]);
            }
#pragma unroll
            for (int nf = 0; nf < 8; nf++) {
                const int nb = wn*64 + nf*8 + qr;
                b[nf][0] = __float_as_uint(Bs[nb*SA_ST + kk + qc]);
                b[nf][1] = __float_as_uint(Bs[nb*SA_ST + kk + qc + 4]);
            }
#pragma unroll
            for (int mf = 0; mf < 2; mf++)
#pragma unroll
                for (int nf = 0; nf < 8; nf++)
                    mma_tf32(acc[mf][nf][0], acc[mf][nf][1],
                             acc[mf][nf][2], acc[mf][nf][3],
                             a[mf][0], a[mf][1], a[mf][2], a[mf][3],
                             b[nf][0], b[nf][1]);
        }
        __syncthreads();                // done reading buffer before producer refills
    }

    // epilogue
    const int batch = m0 >> 10;
#pragma unroll
    for (int mf = 0; mf < 2; mf++) {
#pragma unroll
        for (int nf = 0; nf < 8; nf++) {
            const int n = n0 + wn*64 + nf*8 + qc*2;
            float bx = 0.f, by = 0.f;
            if (bias) { bx = bias[n]; by = bias[n+1]; }
            if (BBIAS) { bx += gb[batch*N + n]; by += gb[batch*N + n + 1]; }
#pragma unroll
            for (int half = 0; half < 2; half++) {
                const int m = m0 + wm*32 + mf*16 + qr + half*8;
                float v0 = acc[mf][nf][half*2+0] + bx;
                float v1 = acc[mf][nf][half*2+1] + by;
                if (ACT == 1) { v0 = fmaxf(v0, 0.f); v1 = fmaxf(v1, 0.f); }
                else if (ACT == 2) {
                    v0 = 0.5f*v0*(1.f + erff(v0*0.70710678118654752f));
                    v1 = 0.5f*v1*(1.f + erff(v1*0.70710678118654752f));
                }
                *(float2*)&C[(size_t)m*N + n] = make_float2(v0, v1);
            }
        }
    }
#undef STAGE_LOAD
}

// ---------------- weight transpose + tf32 pre-round: out[N][K] = rna(in[K][N])
__global__ __launch_bounds__(256) void transpose_kernel(
    const float* __restrict__ in, float* __restrict__ outp, int K, int N)
{
    __shared__ float t[32][33];
    const int n0 = blockIdx.x * 32, k0 = blockIdx.y * 32;
    const int x = threadIdx.x, y = threadIdx.y;   // 32 x 8
#pragma unroll
    for (int i = 0; i < 4; i++)
        t[y + 8*i][x] = in[(size_t)(k0 + y + 8*i) * N + n0 + x];
    __syncthreads();
#pragma unroll
    for (int i = 0; i < 4; i++)
        outp[(size_t)(n0 + y + 8*i) * K + k0 + x] = __uint_as_float(f2tf32(t[x][y + 8*i]));
}

// ---------------- windowed attention (NATTEN, window 31) -------------------
__global__ __launch_bounds__(64) void natten_kernel(
    const float* __restrict__ qkv, float* __restrict__ out)
{
    const int qt = blockIdx.x;
    const int h  = blockIdx.y;
    const int b  = blockIdx.z;
    const int q0 = qt * 64;
    const int base = q0 - 15;

    __shared__ float ks[64][95];
    __shared__ float vs[64][95];

    const int tid = threadIdx.x;
    for (int idx = tid; idx < 94*64; idx += 64) {
        const int r = idx >> 6;
        const int d = idx & 63;
        const int pos = base + r;
        float kk = 0.f, vv = 0.f;
        if (pos >= 0 && pos < LL) {
            const size_t off = ((size_t)(b*LL + pos))*1536 + h*64 + d;
            kk = qkv[off + 512];
            vv = qkv[off + 1024];
        }
        ks[d][r] = kk;
        vs[d][r] = vv;
    }
    __syncthreads();

    const int l = q0 + tid;
    const float* qp = &qkv[((size_t)(b*LL + l))*1536 + h*64];

    float s[31];
#pragma unroll
    for (int j = 0; j < 31; j++) s[j] = 0.f;

#pragma unroll
    for (int c = 0; c < 4; c++) {
        float q[16];
#pragma unroll
        for (int d = 0; d < 16; d++) q[d] = qp[c*16 + d];
#pragma unroll
        for (int j = 0; j < 31; j++) {
            float dot = 0.f;
#pragma unroll
            for (int d = 0; d < 16; d++)
                dot = fmaf(q[d], ks[c*16 + d][tid + j], dot);
            s[j] += dot;
        }
    }

    float mx = -1e30f;
#pragma unroll
    for (int j = 0; j < 31; j++) {
        const int pos = l - 15 + j;
        if (pos < 0 || pos >= LL) s[j] = -1e30f;
        else                      s[j] *= 0.125f;
        mx = fmaxf(mx, s[j]);
    }
    float sum = 0.f;
#pragma unroll
    for (int j = 0; j < 31; j++) { s[j] = expf(s[j] - mx); sum += s[j]; }
    const float inv = 1.f / sum;

    float* op = &out[((size_t)(b*LL + l))*512 + h*64];
#pragma unroll
    for (int c = 0; c < 4; c++) {
        float o[16];
#pragma unroll
        for (int d = 0; d < 16; d++) o[d] = 0.f;
#pragma unroll
        for (int j = 0; j < 31; j++) {
            const float p = s[j];
#pragma unroll
            for (int d = 0; d < 16; d++)
                o[d] = fmaf(p, vs[c*16 + d][tid + j], o[d]);
        }
#pragma unroll
        for (int d = 0; d < 16; d++) op[c*16 + d] = o[d] * inv;
    }
}

// ---------------- fused residual add + LayerNorm (+clip) -------------------
template<bool CLIP>
__global__ __launch_bounds__(128) void add_ln_kernel(
    const float* __restrict__ a, const float* __restrict__ res,
    const float* __restrict__ gam, const float* __restrict__ bet,
    float* __restrict__ outp, int ldo)
{
    const int row = blockIdx.x;
    const int tid = threadIdx.x;
    const float* ap = a   + (size_t)row*512;
    const float* rp = res + (size_t)row*512;

    float v[4];
    float s = 0.f, s2 = 0.f;
#pragma unroll
    for (int i = 0; i < 4; i++) {
        const float x = ap[tid + 128*i] + rp[tid + 128*i];
        v[i] = x; s += x; s2 += x*x;
    }
    __shared__ float red[2][4];
#pragma unroll
    for (int o = 16; o > 0; o >>= 1) {
        s  += __shfl_down_sync(~0u, s,  o);
        s2 += __shfl_down_sync(~0u, s2, o);
    }
    const int wd = tid >> 5, lane = tid & 31;
    if (lane == 0) { red[0][wd] = s; red[1][wd] = s2; }
    __syncthreads();
    __shared__ float stats[2];
    if (tid == 0) {
        float ts = 0.f, ts2 = 0.f;
#pragma unroll
        for (int w = 0; w < 4; w++) { ts += red[0][w]; ts2 += red[1][w]; }
        const float mean = ts * (1.f/512.f);
        stats[0] = mean;
        stats[1] = rsqrtf(ts2 * (1.f/512.f) - mean*mean + 1e-5f);
    }
    __syncthreads();
    const float mean = stats[0], rstd = stats[1];
    float* op = outp + (size_t)row*ldo;
#pragma unroll
    for (int i = 0; i < 4; i++) {
        const int c = tid + 128*i;
        float y = (v[i] - mean) * rstd * gam[c] + bet[c];
        if (CLIP) y = fminf(fmaxf(y, -100.f), 100.f);
        op[c] = y;
    }
}

// ---------------- two-stage mean over sequence axis ------------------------
__global__ void mean1_kernel(const float* __restrict__ x, float* __restrict__ outp)
{
    const int c = blockIdx.x*128 + threadIdx.x;
    const int b = blockIdx.y;
    const int z = blockIdx.z;
    const float* p = x + ((size_t)b*LL + z*64)*512 + c;
    float s = 0.f;
#pragma unroll 4
    for (int l = 0; l < 64; l++) s += p[(size_t)l*512];
    outp[(z*BB + b)*512 + c] = s;
}
__global__ void mean2_kernel(const float* __restrict__ part, float* __restrict__ outp)
{
    const int c = blockIdx.x*128 + threadIdx.x;
    const int b = blockIdx.y;
    float s = 0.f;
#pragma unroll
    for (int z = 0; z < 16; z++) s += part[(z*BB + b)*512 + c];
    outp[b*512 + c] = s * (1.f/LL);
}

// ---------------- tiny per-batch GEMM --------------------------------------
__global__ __launch_bounds__(512) void vec_gemm_kernel(
    const float* __restrict__ A, const float* __restrict__ W,
    const float* __restrict__ bias, float* __restrict__ C)
{
    const int b = blockIdx.x, n = threadIdx.x;
    const float* a = A + b*512;
    float s = bias[n];
    for (int k = 0; k < 512; k++) s = fmaf(a[k], W[(size_t)k*512 + n], s);
    C[b*512 + n] = s;
}

// ---------------- bias concat -----------------------------------------------
__global__ void concat_bias_kernel(const float* __restrict__ b1,
                                   const float* __restrict__ b2,
                                   float* __restrict__ o)
{
    const int i = threadIdx.x;
    o[i] = (i < 256) ? b1[i] : b2[i - 256];
}

// ---------------- small-N GEMM (N=18 or 5), K=256 --------------------------
__global__ void small_gemm_kernel(
    const float* __restrict__ A, int lda, const float* __restrict__ W,
    const float* __restrict__ bias, float* __restrict__ C, int N)
{
    const int idx = blockIdx.x*blockDim.x + threadIdx.x;
    if (idx >= MROWS*N) return;
    const int m = idx / N, n = idx - m*N;
    const float* a = A + (size_t)m*lda;
    float s0 = bias[n], s1 = 0.f, s2 = 0.f, s3 = 0.f;
    for (int k = 0; k < 256; k += 4) {
        const float4 av = *(const float4*)&a[k];
        s0 = fmaf(av.x, W[(k  )*N + n], s0);
        s1 = fmaf(av.y, W[(k+1)*N + n], s1);
        s2 = fmaf(av.z, W[(k+2)*N + n], s2);
        s3 = fmaf(av.w, W[(k+3)*N + n], s3);
    }
    C[idx] = (s0 + s1) + (s2 + s3);
}

// ---------------- softmax(type_logits) @ type_emb -> si[:,512:544] ---------
__global__ __launch_bounds__(256) void type_emb_kernel(
    const float* __restrict__ logits, const float* __restrict__ emb,
    float* __restrict__ si)
{
    const int row  = blockIdx.x*8 + (threadIdx.x >> 5);
    const int lane = threadIdx.x & 31;
    if (row >= MROWS) return;
    const float* lp = logits + (size_t)row*18;
    float v[18];
    float mx = -1e30f;
#pragma unroll
    for (int j = 0; j < 18; j++) { v[j] = lp[j]; mx = fmaxf(mx, v[j]); }
    float sum = 0.f;
#pragma unroll
    for (int j = 0; j < 18; j++) { v[j] = expf(v[j] - mx); sum += v[j]; }
    const float inv = 1.f / sum;
    float o = 0.f;
#pragma unroll
    for (int j = 0; j < 18; j++) o = fmaf(v[j], emb[j*32 + lane], o);
    si[(size_t)row*544 + 512 + lane] = o * inv;
}

// ---------------- launch ----------------------------------------------------
extern "C" void kernel_launch(void* const* d_in, const int* in_sizes, int n_in,
                              void* d_out, int out_size)
{
    (void)in_sizes; (void)n_in; (void)out_size;
    const float* state = (const float*)d_in[0];
    const float* Wp    = (const float*)d_in[1];
    const float* bp    = (const float*)d_in[2];
    const float* Wqkv  = (const float*)d_in[3];
    const float* bqkv  = (const float*)d_in[4];
    const float* Wo    = (const float*)d_in[5];
    const float* bo    = (const float*)d_in[6];
    const float* ln_g  = (const float*)d_in[7];
    const float* ln_b  = (const float*)d_in[8];
    const float* Wg    = (const float*)d_in[9];
    const float* bg    = (const float*)d_in[10];
    const float* Wc    = (const float*)d_in[11];
    const float* bc    = (const float*)d_in[12];
    const float* W1    = (const float*)d_in[13];
    const float* b1    = (const float*)d_in[14];
    const float* W2    = (const float*)d_in[15];
    const float* b2    = (const float*)d_in[16];
    const float* fn_g  = (const float*)d_in[17];
    const float* fn_b  = (const float*)d_in[18];
    const float* Wt1   = (const float*)d_in[19];
    const float* bt1   = (const float*)d_in[20];
    const float* Wt2   = (const float*)d_in[21];
    const float* bt2   = (const float*)d_in[22];
    const float* temb  = (const float*)d_in[23];
    const float* Ws1   = (const float*)d_in[24];
    const float* bs1   = (const float*)d_in[25];
    const float* Ws2   = (const float*)d_in[26];
    const float* bs2   = (const float*)d_in[27];
    const float* Wa1   = (const float*)d_in[28];
    const float* ba1   = (const float*)d_in[29];
    const float* Wa2   = (const float*)d_in[30];
    const float* ba2   = (const float*)d_in[31];

    float* out = (float*)d_out;

    static float *px=nullptr,*ploc,*pqkv,*patt,*ptmp,*pcomb,*psi,*ph256,*ppm,*pmean,*pgsum,*pgpart,*pwt,*pbsa;
    if (!px) {
        cudaGetSymbolAddress((void**)&px,    g_x);
        cudaGetSymbolAddress((void**)&ploc,  g_loc);
        cudaGetSymbolAddress((void**)&pqkv,  g_qkv);
        cudaGetSymbolAddress((void**)&patt,  g_att);
        cudaGetSymbolAddress((void**)&ptmp,  g_tmp);
        cudaGetSymbolAddress((void**)&pcomb, g_comb);
        cudaGetSymbolAddress((void**)&psi,   g_si);
        cudaGetSymbolAddress((void**)&ph256, g_h256);
        cudaGetSymbolAddress((void**)&ppm,   g_pmean);
        cudaGetSymbolAddress((void**)&pmean, g_mean);
        cudaGetSymbolAddress((void**)&pgsum, g_gsum);
        cudaGetSymbolAddress((void**)&pgpart,g_gpart);
        cudaGetSymbolAddress((void**)&pwt,   g_wt);
        cudaGetSymbolAddress((void**)&pbsa,  g_bsa);
        cudaFuncSetAttribute(gemm_cp<0,false>, cudaFuncAttributeMaxDynamicSharedMemorySize, SMEM_CP);
        cudaFuncSetAttribute(gemm_cp<0,true >, cudaFuncAttributeMaxDynamicSharedMemorySize, SMEM_CP);
        cudaFuncSetAttribute(gemm_cp<1,false>, cudaFuncAttributeMaxDynamicSharedMemorySize, SMEM_CP);
        cudaFuncSetAttribute(gemm_cp<2,false>, cudaFuncAttributeMaxDynamicSharedMemorySize, SMEM_CP);
    }

    const dim3 tthr(32, 8);
    #define TR(inp, off, KK, NN) \
        transpose_kernel<<<dim3((NN)/32, (KK)/32), tthr>>>(inp, pwt + (off), KK, NN)

    // 0. transpose (+tf32 round) all large weights to [N][K]
    TR(Wp,                     WT_P,    256, 512);
    TR(Wqkv,                   WT_QKV0, 512, 1536);
    TR(Wqkv + (size_t)512*1536,WT_QKV1, 512, 1536);
    TR(Wo,                     WT_O0,   512, 512);
    TR(Wo + (size_t)512*512,   WT_O1,   512, 512);
    TR(Wc,                     WT_C,    512, 512);
    TR(W1,                     WT_1,    512, 1024);
    TR(W2,                     WT_2,    1024, 512);
    TR(Wt1,                    WT_T1,   512, 256);
    TR(Ws1,                    WT_SA,            544, 256);
    TR(Wa1,                    WT_SA + 256*544,  544, 256);
    concat_bias_kernel<<<1, 512>>>(bs1, ba1, pbsa);

    const dim3 thr(512);
    #define GEMM(ACT, BBIAS, Ap, LDA, WT, BIAS, GB, Cp, NN, KK) \
        gemm_cp<ACT, BBIAS><<<dim3((NN)/128, MROWS/256), thr, SMEM_CP>>>(Ap, LDA, WT, BIAS, GB, Cp, NN, KK)

    // 1. x = state @ Wp + bp
    GEMM(0, false, state, DIN, pwt+WT_P, bp, nullptr, px, 512, 256);

    // 2. two NATTEN layers
    const float* locIn = px;
    for (int i = 0; i < 2; i++) {
        GEMM(0, false, locIn, 512, pwt + (i ? WT_QKV1 : WT_QKV0), bqkv + i*1536, nullptr, pqkv, 1536, 512);
        natten_kernel<<<dim3(LL/64, NHEAD, BB), 64>>>(pqkv, patt);
        GEMM(0, false, patt, 512, pwt + (i ? WT_O1 : WT_O0), bo + i*512, nullptr, ptmp, 512, 512);
        add_ln_kernel<false><<<MROWS, 128>>>(ptmp, locIn, ln_g + i*512, ln_b + i*512, ploc, 512);
        locIn = ploc;
    }

    // 3. global summary path (per-batch, tiny, fp32 exact)
    mean1_kernel<<<dim3(4, BB, 16), 128>>>(px, ppm);
    mean2_kernel<<<dim3(4, BB), 128>>>(ppm, pmean);
    vec_gemm_kernel<<<BB, 512>>>(pmean, Wg, bg, pgsum);
    vec_gemm_kernel<<<BB, 512>>>(pgsum, Wc + (size_t)512*512, bc, pgpart);

    // 4. comb = loc @ Wc[:512] + gpart[batch]
    GEMM(0, true, ploc, 512, pwt+WT_C, nullptr, pgpart, pcomb, 512, 512);

    // 5. FFN + LN(clip) -> enc (into si[:, :512], stride 544)
    GEMM(2, false, pcomb, 512, pwt+WT_1, b1, nullptr, ptmp, 1024, 512);
    GEMM(0, false, ptmp, 1024, pwt+WT_2, b2, nullptr, patt, 512, 1024);
    add_ln_kernel<true><<<MROWS, 128>>>(patt, pcomb, fn_g, fn_b, psi, 544);

    // 6. type head: logits straight to d_out, then softmax@emb -> si[:,512:]
    GEMM(1, false, psi, 544, pwt+WT_T1, bt1, nullptr, ph256, 256, 512);
    small_gemm_kernel<<<(MROWS*18 + 255)/256, 256>>>(ph256, 256, Wt2, bt2, out, 18);
    type_emb_kernel<<<MROWS/8, 256>>>(out, temb, psi);

    // 7+8. fused size+amount first layer: [Ws1|Wa1], relu -> ptmp [8192][512]
    GEMM(1, false, psi, 544, pwt+WT_SA, pbsa, nullptr, ptmp, 512, 544);
    small_gemm_kernel<<<(MROWS*5 + 255)/256, 256>>>(ptmp,       512, Ws2, bs2, out + (size_t)MROWS*18, 5);
    small_gemm_kernel<<<(MROWS*5 + 255)/256, 256>>>(ptmp + 256, 512, Wa2, ba2, out + (size_t)MROWS*23, 5);
}

// round 6
// speedup vs baseline: 2.3830x; 1.0786x over previous
#include <cuda_runtime.h>
#include <math.h>
#include <stdint.h>

#define BB 8
#define LL 1024
#define DIN 256
#define HH 512
#define NHEAD 8
#define MROWS (BB*LL)   // 8192

// ---------------- scratch (device globals; no allocations) ----------------
__device__ float g_x   [MROWS*HH];
__device__ float g_loc [MROWS*HH];
__device__ float g_qkv [MROWS*3*HH];
__device__ float g_att [MROWS*HH];
__device__ float g_tmp [MROWS*2*HH];
__device__ float g_comb[MROWS*HH];
__device__ float g_si  [MROWS*544];
__device__ float g_h256[MROWS*256];
__device__ float g_pmean[16*BB*HH];
__device__ float g_gpart[BB*HH];
__device__ float g_bsa  [512];
__device__ float g_wt  [3948544];       // transposed (tf32-rounded) weights

// transposed-weight offsets (floats)
#define WT_P    0
#define WT_QKV0 131072
#define WT_QKV1 917504
#define WT_O0   1703936
#define WT_O1   1966080
#define WT_C    2228224
#define WT_1    2490368
#define WT_2    3014656
#define WT_T1   3538944
#define WT_SA   3670016     // Ws1^T rows 0..255, Wa1^T rows 256..511 (K=544)

// ---------------- helpers ---------------------------------------------------
__device__ __forceinline__ uint32_t f2tf32(float f) {
    uint32_t r; asm("cvt.rna.tf32.f32 %0, %1;" : "=r"(r) : "f"(f)); return r;
}
__device__ __forceinline__ uint32_t s2u(const void* p) {
    uint32_t a;
    asm("{ .reg .u64 t; cvta.to.shared.u64 t, %1; cvt.u32.u64 %0, t; }" : "=r"(a) : "l"(p));
    return a;
}
__device__ __forceinline__ void cpa16(uint32_t sdst, const void* gsrc) {
    asm volatile("cp.async.cg.shared.global [%0], [%1], 16;" :: "r"(sdst), "l"(gsrc) : "memory");
}
#define CP_COMMIT() asm volatile("cp.async.commit_group;" ::: "memory")
#define CP_WAIT1()  asm volatile("cp.async.wait_group 1;" ::: "memory")

__device__ __forceinline__ void mma_tf32(
    float& d0, float& d1, float& d2, float& d3,
    uint32_t a0, uint32_t a1, uint32_t a2, uint32_t a3,
    uint32_t b0, uint32_t b1)
{
    asm volatile(
        "mma.sync.aligned.m16n8k8.row.col.f32.tf32.tf32.f32 "
        "{%0,%1,%2,%3}, {%4,%5,%6,%7}, {%8,%9}, {%0,%1,%2,%3};"
        : "+f"(d0), "+f"(d1), "+f"(d2), "+f"(d3)
        : "r"(a0), "r"(a1), "r"(a2), "r"(a3), "r"(b0), "r"(b1));
}

// ---------------- cp.async tf32 GEMM ----------------------------------------
// C[M,N] = act(A[M,K] @ W[K,N] + bias [+ gb[batch]]).  Wt = rounded W^T [N][K].
// Block tile 128x128 (256 thr, 8 warps 4x2, warp tile 32x64), 3-stage cp.async,
// ONE __syncthreads per K-iter, 2 CTAs/SM.  M%128==0, N%128==0, K%32==0.
#define STG 3
#define SA_ST 36
#define ST_A_FL (128*SA_ST)          // floats per A stage (4608)
#define ST_B_FL (128*SA_ST)          // floats per B stage (4608)
#define ST_FL   (ST_A_FL + ST_B_FL)  // 9216 floats
#define SMEM_CP (STG*ST_FL*4)        // 110592 bytes

template<int ACT, bool BBIAS>  // ACT: 0=none 1=relu 2=gelu(exact)
__global__ __launch_bounds__(256, 2) void gemm_cp(
    const float* __restrict__ A, int lda,
    const float* __restrict__ Wt,
    const float* __restrict__ bias,
    const float* __restrict__ gb,
    float* __restrict__ C, int N, int K)
{
    extern __shared__ float sm[];
    const uint32_t sbase = s2u(sm);

    const int tid  = threadIdx.x;
    const int warp = tid >> 5;
    const int lane = tid & 31;
    const int wm = warp >> 1;          // 0..3 -> m offset 32*wm
    const int wn = warp & 1;           // 0..1 -> n offset 64*wn
    const int qr = lane >> 2;          // 0..7
    const int qc = lane & 3;           // 0..3

    const int m0 = blockIdx.y * 128;
    const int n0 = blockIdx.x * 128;
    const int nk = K >> 5;

    // cp.async loader indices (256 threads; 128 rows x 8 float4-cols per matrix)
    const int lrow = tid >> 3;         // 0..31 (4 iters of 32)
    const int lc4  = (tid & 7) * 4;    // 0..28

    const float* Abase = A + (size_t)(m0 + lrow) * lda + lc4;
    const float* Bbase = Wt + (size_t)(n0 + lrow) * K + lc4;

#define STAGE_LOAD(kt) do {                                                   \
        const uint32_t sA = sbase + ((kt) % STG) * (ST_FL*4);                 \
        const uint32_t sB = sA + ST_A_FL*4;                                   \
        _Pragma("unroll")                                                     \
        for (int it = 0; it < 4; it++)                                        \
            cpa16(sA + ((lrow + 32*it)*SA_ST + lc4)*4,                        \
                  Abase + (size_t)(32*it)*lda + (kt)*32);                     \
        _Pragma("unroll")                                                     \
        for (int it = 0; it < 4; it++)                                        \
            cpa16(sB + ((lrow + 32*it)*SA_ST + lc4)*4,                        \
                  Bbase + (size_t)(32*it)*K + (kt)*32);                       \
        CP_COMMIT();                                                          \
    } while (0)

    float acc[2][8][4];
#pragma unroll
    for (int i = 0; i < 2; i++)
#pragma unroll
        for (int j = 0; j < 8; j++)
#pragma unroll
            for (int c = 0; c < 4; c++) acc[i][j][c] = 0.f;

    STAGE_LOAD(0);
    STAGE_LOAD(1);

    for (int kt = 0; kt < nk; kt++) {
        CP_WAIT1();                     // stage kt arrived (this thread)
        __syncthreads();                // all stages visible; buffer (kt+2)%3 free
        if (kt + 2 < nk) STAGE_LOAD(kt + 2);

        const float* As = sm + (kt % STG) * ST_FL;
        const float* Bs = As + ST_A_FL;
#pragma unroll
        for (int kk = 0; kk < 32; kk += 8) {
            uint32_t a[2][4], b[8][2];
#pragma unroll
            for (int mf = 0; mf < 2; mf++) {
                const int mb = wm*32 + mf*16;
                a[mf][0] = f2tf32(As[(mb + qr    )*SA_ST + kk + qc]);
                a[mf][1] = f2tf32(As[(mb + qr + 8)*SA_ST + kk + qc]);
                a[mf][2] = f2tf32(As[(mb + qr    )*SA_ST + kk + qc + 4]);
                a[mf][3] = f2tf32(As[(mb + qr + 8)*SA_ST + kk + qc + 4]);
            }
#pragma unroll
            for (int nf = 0; nf < 8; nf++) {
                const int nb = wn*64 + nf*8 + qr;
                b[nf][0] = __float_as_uint(Bs[nb*SA_ST + kk + qc]);
                b[nf][1] = __float_as_uint(Bs[nb*SA_ST + kk + qc + 4]);
            }
#pragma unroll
            for (int mf = 0; mf < 2; mf++)
#pragma unroll
                for (int nf = 0; nf < 8; nf++)
                    mma_tf32(acc[mf][nf][0], acc[mf][nf][1],
                             acc[mf][nf][2], acc[mf][nf][3],
                             a[mf][0], a[mf][1], a[mf][2], a[mf][3],
                             b[nf][0], b[nf][1]);
        }
    }

    // epilogue
    const int batch = m0 >> 10;
#pragma unroll
    for (int mf = 0; mf < 2; mf++) {
#pragma unroll
        for (int nf = 0; nf < 8; nf++) {
            const int n = n0 + wn*64 + nf*8 + qc*2;
            float bx = 0.f, by = 0.f;
            if (bias) { bx = bias[n]; by = bias[n+1]; }
            if (BBIAS) { bx += gb[batch*N + n]; by += gb[batch*N + n + 1]; }
#pragma unroll
            for (int half = 0; half < 2; half++) {
                const int m = m0 + wm*32 + mf*16 + qr + half*8;
                float v0 = acc[mf][nf][half*2+0] + bx;
                float v1 = acc[mf][nf][half*2+1] + by;
                if (ACT == 1) { v0 = fmaxf(v0, 0.f); v1 = fmaxf(v1, 0.f); }
                else if (ACT == 2) {
                    v0 = 0.5f*v0*(1.f + erff(v0*0.70710678118654752f));
                    v1 = 0.5f*v1*(1.f + erff(v1*0.70710678118654752f));
                }
                *(float2*)&C[(size_t)m*N + n] = make_float2(v0, v1);
            }
        }
    }
#undef STAGE_LOAD
}

// ---------------- merged weight transpose (+tf32 round) --------------------
#define NJOBS 11
struct TransJobs {
    const float* src[NJOBS];
    long long    dstoff[NJOBS];
    int K[NJOBS], N[NJOBS];
    int start[NJOBS+1];      // cumulative 32x32 tile offsets
};

__global__ __launch_bounds__(256) void transpose_all_kernel(TransJobs jobs, float* __restrict__ wt)
{
    __shared__ float t[32][33];
    const int bid = blockIdx.x;
    int j = 0;
#pragma unroll
    for (int i = 0; i < NJOBS; i++) if (bid >= jobs.start[i+1]) j = i+1;
    const int lt = bid - jobs.start[j];
    const int K = jobs.K[j], N = jobs.N[j];
    const int tilesx = N >> 5;
    const int n0 = (lt % tilesx) * 32;
    const int k0 = (lt / tilesx) * 32;
    const float* in = jobs.src[j];
    float* outp = wt + jobs.dstoff[j];

    const int x = threadIdx.x & 31, y = threadIdx.x >> 5;   // 32 x 8
#pragma unroll
    for (int i = 0; i < 4; i++)
        t[y + 8*i][x] = in[(size_t)(k0 + y + 8*i) * N + n0 + x];
    __syncthreads();
#pragma unroll
    for (int i = 0; i < 4; i++)
        outp[(size_t)(n0 + y + 8*i) * K + k0 + x] = __uint_as_float(f2tf32(t[x][y + 8*i]));
}

// ---------------- windowed attention (NATTEN, window 31) -------------------
__global__ __launch_bounds__(64) void natten_kernel(
    const float* __restrict__ qkv, float* __restrict__ out)
{
    const int qt = blockIdx.x;
    const int h  = blockIdx.y;
    const int b  = blockIdx.z;
    const int q0 = qt * 64;
    const int base = q0 - 15;

    __shared__ float ks[64][95];
    __shared__ float vs[64][95];

    const int tid = threadIdx.x;
    for (int idx = tid; idx < 94*64; idx += 64) {
        const int r = idx >> 6;
        const int d = idx & 63;
        const int pos = base + r;
        float kk = 0.f, vv = 0.f;
        if (pos >= 0 && pos < LL) {
            const size_t off = ((size_t)(b*LL + pos))*1536 + h*64 + d;
            kk = qkv[off + 512];
            vv = qkv[off + 1024];
        }
        ks[d][r] = kk;
        vs[d][r] = vv;
    }
    __syncthreads();

    const int l = q0 + tid;
    const float* qp = &qkv[((size_t)(b*LL + l))*1536 + h*64];

    float s[31];
#pragma unroll
    for (int j = 0; j < 31; j++) s[j] = 0.f;

#pragma unroll
    for (int c = 0; c < 4; c++) {
        float q[16];
#pragma unroll
        for (int d = 0; d < 16; d++) q[d] = qp[c*16 + d];
#pragma unroll
        for (int j = 0; j < 31; j++) {
            float dot = 0.f;
#pragma unroll
            for (int d = 0; d < 16; d++)
                dot = fmaf(q[d], ks[c*16 + d][tid + j], dot);
            s[j] += dot;
        }
    }

    float mx = -1e30f;
#pragma unroll
    for (int j = 0; j < 31; j++) {
        const int pos = l - 15 + j;
        if (pos < 0 || pos >= LL) s[j] = -1e30f;
        else                      s[j] *= 0.125f;
        mx = fmaxf(mx, s[j]);
    }
    float sum = 0.f;
#pragma unroll
    for (int j = 0; j < 31; j++) { s[j] = expf(s[j] - mx); sum += s[j]; }
    const float inv = 1.f / sum;

    float* op = &out[((size_t)(b*LL + l))*512 + h*64];
#pragma unroll
    for (int c = 0; c < 4; c++) {
        float o[16];
#pragma unroll
        for (int d = 0; d < 16; d++) o[d] = 0.f;
#pragma unroll
        for (int j = 0; j < 31; j++) {
            const float p = s[j];
#pragma unroll
            for (int d = 0; d < 16; d++)
                o[d] = fmaf(p, vs[c*16 + d][tid + j], o[d]);
        }
#pragma unroll
        for (int d = 0; d < 16; d++) op[c*16 + d] = o[d] * inv;
    }
}

// ---------------- fused residual add + LayerNorm (+clip) -------------------
template<bool CLIP>
__global__ __launch_bounds__(128) void add_ln_kernel(
    const float* __restrict__ a, const float* __restrict__ res,
    const float* __restrict__ gam, const float* __restrict__ bet,
    float* __restrict__ outp, int ldo)
{
    const int row = blockIdx.x;
    const int tid = threadIdx.x;
    const float* ap = a   + (size_t)row*512;
    const float* rp = res + (size_t)row*512;

    float v[4];
    float s = 0.f, s2 = 0.f;
#pragma unroll
    for (int i = 0; i < 4; i++) {
        const float x = ap[tid + 128*i] + rp[tid + 128*i];
        v[i] = x; s += x; s2 += x*x;
    }
    __shared__ float red[2][4];
#pragma unroll
    for (int o = 16; o > 0; o >>= 1) {
        s  += __shfl_down_sync(~0u, s,  o);
        s2 += __shfl_down_sync(~0u, s2, o);
    }
    const int wd = tid >> 5, lane = tid & 31;
    if (lane == 0) { red[0][wd] = s; red[1][wd] = s2; }
    __syncthreads();
    __shared__ float stats[2];
    if (tid == 0) {
        float ts = 0.f, ts2 = 0.f;
#pragma unroll
        for (int w = 0; w < 4; w++) { ts += red[0][w]; ts2 += red[1][w]; }
        const float mean = ts * (1.f/512.f);
        stats[0] = mean;
        stats[1] = rsqrtf(ts2 * (1.f/512.f) - mean*mean + 1e-5f);
    }
    __syncthreads();
    const float mean = stats[0], rstd = stats[1];
    float* op = outp + (size_t)row*ldo;
#pragma unroll
    for (int i = 0; i < 4; i++) {
        const int c = tid + 128*i;
        float y = (v[i] - mean) * rstd * gam[c] + bet[c];
        if (CLIP) y = fminf(fmaxf(y, -100.f), 100.f);
        op[c] = y;
    }
}

// ---------------- partial mean over sequence axis --------------------------
__global__ void mean1_kernel(const float* __restrict__ x, float* __restrict__ outp)
{
    const int c = blockIdx.x*128 + threadIdx.x;
    const int b = blockIdx.y;
    const int z = blockIdx.z;
    const float* p = x + ((size_t)b*LL + z*64)*512 + c;
    float s = 0.f;
#pragma unroll 4
    for (int l = 0; l < 64; l++) s += p[(size_t)l*512];
    outp[(z*BB + b)*512 + c] = s;
}

// ---------------- fused summary: mean2 + @Wg + @Wc[512:] -------------------
// grid = BB blocks, 512 threads
__global__ __launch_bounds__(512) void summary_kernel(
    const float* __restrict__ part,
    const float* __restrict__ Wg, const float* __restrict__ bg,
    const float* __restrict__ Wc2, const float* __restrict__ bc,
    float* __restrict__ gpart)
{
    __shared__ float a[512], g[512];
    const int b = blockIdx.x, n = threadIdx.x;
    float s = 0.f;
#pragma unroll
    for (int z = 0; z < 16; z++) s += part[(z*BB + b)*512 + n];
    a[n] = s * (1.f/LL);
    __syncthreads();
    float acc = bg[n];
    for (int k = 0; k < 512; k++) acc = fmaf(a[k], Wg[(size_t)k*512 + n], acc);
    g[n] = acc;
    __syncthreads();
    float acc2 = bc[n];
    for (int k = 0; k < 512; k++) acc2 = fmaf(g[k], Wc2[(size_t)k*512 + n], acc2);
    gpart[b*512 + n] = acc2;
}

// ---------------- bias concat -----------------------------------------------
__global__ void concat_bias_kernel(const float* __restrict__ b1,
                                   const float* __restrict__ b2,
                                   float* __restrict__ o)
{
    const int i = threadIdx.x;
    o[i] = (i < 256) ? b1[i] : b2[i - 256];
}

// ---------------- small-N GEMM (N=5), K=256 --------------------------------
__global__ void small_gemm_kernel(
    const float* __restrict__ A, int lda, const float* __restrict__ W,
    const float* __restrict__ bias, float* __restrict__ C, int N)
{
    const int idx = blockIdx.x*blockDim.x + threadIdx.x;
    if (idx >= MROWS*N) return;
    const int m = idx / N, n = idx - m*N;
    const float* a = A + (size_t)m*lda;
    float s0 = bias[n], s1 = 0.f, s2 = 0.f, s3 = 0.f;
    for (int k = 0; k < 256; k += 4) {
        const float4 av = *(const float4*)&a[k];
        s0 = fmaf(av.x, W[(k  )*N + n], s0);
        s1 = fmaf(av.y, W[(k+1)*N + n], s1);
        s2 = fmaf(av.z, W[(k+2)*N + n], s2);
        s3 = fmaf(av.w, W[(k+3)*N + n], s3);
    }
    C[idx] = (s0 + s1) + (s2 + s3);
}

// ---------------- fused type head: logits + softmax@emb --------------------
// grid = MROWS/8, 256 threads; 8 rows per block
__global__ __launch_bounds__(256) void type_head_kernel(
    const float* __restrict__ h,        // [MROWS][256] relu output
    const float* __restrict__ Wt2, const float* __restrict__ bt2,
    const float* __restrict__ emb,      // [18][32]
    float* __restrict__ out_logits,     // [MROWS][18]
    float* __restrict__ si)             // [MROWS][544], writes cols 512..543
{
    __shared__ float As[8][260];
    __shared__ float lg[8][18];
    const int tid = threadIdx.x;
    const int r0 = blockIdx.x * 8;

    // coop load 8 rows x 256 (float4)
#pragma unroll
    for (int it = 0; it < 2; it++) {
        const int idx = tid + it*256;     // 0..511 -> (row, col4)
        const int r = idx >> 6;           // 0..7
        const int c4 = (idx & 63) * 4;
        *(float4*)&As[r][c4] = *(const float4*)&h[((size_t)(r0 + r))*256 + c4];
    }
    __syncthreads();

    // logits: 144 threads, same 4-accumulator order as before
    if (tid < 144) {
        const int r = tid / 18, n = tid - r*18;
        float s0 = bt2[n], s1 = 0.f, s2 = 0.f, s3 = 0.f;
        for (int k = 0; k < 256; k += 4) {
            const float4 av = *(const float4*)&As[r][k];
            s0 = fmaf(av.x, Wt2[(k  )*18 + n], s0);
            s1 = fmaf(av.y, Wt2[(k+1)*18 + n], s1);
            s2 = fmaf(av.z, Wt2[(k+2)*18 + n], s2);
            s3 = fmaf(av.w, Wt2[(k+3)*18 + n], s3);
        }
        const float v = (s0 + s1) + (s2 + s3);
        lg[r][n] = v;
        out_logits[(size_t)(r0 + r)*18 + n] = v;
    }
    __syncthreads();

    // softmax @ emb: warp w handles row w, lane = emb column
    const int w = tid >> 5, lane = tid & 31;
    float v[18];
    float mx = -1e30f;
#pragma unroll
    for (int j = 0; j < 18; j++) { v[j] = lg[w][j]; mx = fmaxf(mx, v[j]); }
    float sum = 0.f;
#pragma unroll
    for (int j = 0; j < 18; j++) { v[j] = expf(v[j] - mx); sum += v[j]; }
    const float inv = 1.f / sum;
    float o = 0.f;
#pragma unroll
    for (int j = 0; j < 18; j++) o = fmaf(v[j], emb[j*32 + lane], o);
    si[(size_t)(r0 + w)*544 + 512 + lane] = o * inv;
}

// ---------------- launch ----------------------------------------------------
extern "C" void kernel_launch(void* const* d_in, const int* in_sizes, int n_in,
                              void* d_out, int out_size)
{
    (void)in_sizes; (void)n_in; (void)out_size;
    const float* state = (const float*)d_in[0];
    const float* Wp    = (const float*)d_in[1];
    const float* bp    = (const float*)d_in[2];
    const float* Wqkv  = (const float*)d_in[3];
    const float* bqkv  = (const float*)d_in[4];
    const float* Wo    = (const float*)d_in[5];
    const float* bo    = (const float*)d_in[6];
    const float* ln_g  = (const float*)d_in[7];
    const float* ln_b  = (const float*)d_in[8];
    const float* Wg    = (const float*)d_in[9];
    const float* bg    = (const float*)d_in[10];
    const float* Wc    = (const float*)d_in[11];
    const float* bc    = (const float*)d_in[12];
    const float* W1    = (const float*)d_in[13];
    const float* b1    = (const float*)d_in[14];
    const float* W2    = (const float*)d_in[15];
    const float* b2    = (const float*)d_in[16];
    const float* fn_g  = (const float*)d_in[17];
    const float* fn_b  = (const float*)d_in[18];
    const float* Wt1   = (const float*)d_in[19];
    const float* bt1   = (const float*)d_in[20];
    const float* Wt2   = (const float*)d_in[21];
    const float* bt2   = (const float*)d_in[22];
    const float* temb  = (const float*)d_in[23];
    const float* Ws1   = (const float*)d_in[24];
    const float* bs1   = (const float*)d_in[25];
    const float* Ws2   = (const float*)d_in[26];
    const float* bs2   = (const float*)d_in[27];
    const float* Wa1   = (const float*)d_in[28];
    const float* ba1   = (const float*)d_in[29];
    const float* Wa2   = (const float*)d_in[30];
    const float* ba2   = (const float*)d_in[31];

    float* out = (float*)d_out;

    static float *px=nullptr,*ploc,*pqkv,*patt,*ptmp,*pcomb,*psi,*ph256,*ppm,*pgpart,*pwt,*pbsa;
    if (!px) {
        cudaGetSymbolAddress((void**)&px,    g_x);
        cudaGetSymbolAddress((void**)&ploc,  g_loc);
        cudaGetSymbolAddress((void**)&pqkv,  g_qkv);
        cudaGetSymbolAddress((void**)&patt,  g_att);
        cudaGetSymbolAddress((void**)&ptmp,  g_tmp);
        cudaGetSymbolAddress((void**)&pcomb, g_comb);
        cudaGetSymbolAddress((void**)&psi,   g_si);
        cudaGetSymbolAddress((void**)&ph256, g_h256);
        cudaGetSymbolAddress((void**)&ppm,   g_pmean);
        cudaGetSymbolAddress((void**)&pgpart,g_gpart);
        cudaGetSymbolAddress((void**)&pwt,   g_wt);
        cudaGetSymbolAddress((void**)&pbsa,  g_bsa);
        cudaFuncSetAttribute(gemm_cp<0,false>, cudaFuncAttributeMaxDynamicSharedMemorySize, SMEM_CP);
        cudaFuncSetAttribute(gemm_cp<0,true >, cudaFuncAttributeMaxDynamicSharedMemorySize, SMEM_CP);
        cudaFuncSetAttribute(gemm_cp<1,false>, cudaFuncAttributeMaxDynamicSharedMemorySize, SMEM_CP);
        cudaFuncSetAttribute(gemm_cp<2,false>, cudaFuncAttributeMaxDynamicSharedMemorySize, SMEM_CP);
    }

    // 0. merged transpose (+tf32 round) of all large weights to [N][K]
    {
        TransJobs J;
        const float* srcs[NJOBS] = { Wp, Wqkv, Wqkv + (size_t)512*1536, Wo,
                                     Wo + (size_t)512*512, Wc, W1, W2, Wt1, Ws1, Wa1 };
        const long long offs[NJOBS] = { WT_P, WT_QKV0, WT_QKV1, WT_O0, WT_O1,
                                        WT_C, WT_1, WT_2, WT_T1, WT_SA, WT_SA + 256*544 };
        const int Ks[NJOBS] = { 256, 512, 512, 512, 512, 512, 512, 1024, 512, 544, 544 };
        const int Ns[NJOBS] = { 512, 1536, 1536, 512, 512, 512, 1024, 512, 256, 256, 256 };
        int acc = 0;
        for (int i = 0; i < NJOBS; i++) {
            J.src[i] = srcs[i]; J.dstoff[i] = offs[i]; J.K[i] = Ks[i]; J.N[i] = Ns[i];
            J.start[i] = acc;
            acc += (Ns[i] >> 5) * (Ks[i] >> 5);
        }
        J.start[NJOBS] = acc;
        transpose_all_kernel<<<acc, 256>>>(J, pwt);
    }
    concat_bias_kernel<<<1, 512>>>(bs1, ba1, pbsa);

    const dim3 thr(256);
    #define GEMM(ACT, BBIAS, Ap, LDA, WT, BIAS, GB, Cp, NN, KK) \
        gemm_cp<ACT, BBIAS><<<dim3((NN)/128, MROWS/128), thr, SMEM_CP>>>(Ap, LDA, WT, BIAS, GB, Cp, NN, KK)

    // 1. x = state @ Wp + bp
    GEMM(0, false, state, DIN, pwt+WT_P, bp, nullptr, px, 512, 256);

    // 2. two NATTEN layers
    const float* locIn = px;
    for (int i = 0; i < 2; i++) {
        GEMM(0, false, locIn, 512, pwt + (i ? WT_QKV1 : WT_QKV0), bqkv + i*1536, nullptr, pqkv, 1536, 512);
        natten_kernel<<<dim3(LL/64, NHEAD, BB), 64>>>(pqkv, patt);
        GEMM(0, false, patt, 512, pwt + (i ? WT_O1 : WT_O0), bo + i*512, nullptr, ptmp, 512, 512);
        add_ln_kernel<false><<<MROWS, 128>>>(ptmp, locIn, ln_g + i*512, ln_b + i*512, ploc, 512);
        locIn = ploc;
    }

    // 3. global summary path (per-batch, tiny, fp32 exact)
    mean1_kernel<<<dim3(4, BB, 16), 128>>>(px, ppm);
    summary_kernel<<<BB, 512>>>(ppm, Wg, bg, Wc + (size_t)512*512, bc, pgpart);

    // 4. comb = loc @ Wc[:512] + gpart[batch]
    GEMM(0, true, ploc, 512, pwt+WT_C, nullptr, pgpart, pcomb, 512, 512);

    // 5. FFN + LN(clip) -> enc (into si[:, :512], stride 544)
    GEMM(2, false, pcomb, 512, pwt+WT_1, b1, nullptr, ptmp, 1024, 512);
    GEMM(0, false, ptmp, 1024, pwt+WT_2, b2, nullptr, patt, 512, 1024);
    add_ln_kernel<true><<<MROWS, 128>>>(patt, pcomb, fn_g, fn_b, psi, 544);

    // 6. type head: relu GEMM, then fused logits+softmax@emb
    GEMM(1, false, psi, 544, pwt+WT_T1, bt1, nullptr, ph256, 256, 512);
    type_head_kernel<<<MROWS/8, 256>>>(ph256, Wt2, bt2, temb, out, psi);

    // 7+8. fused size+amount first layer: [Ws1|Wa1], relu -> ptmp [8192][512]
    GEMM(1, false, psi, 544, pwt+WT_SA, pbsa, nullptr, ptmp, 512, 544);
    small_gemm_kernel<<<(MROWS*5 + 255)/256, 256>>>(ptmp,       512, Ws2, bs2, out + (size_t)MROWS*18, 5);
    small_gemm_kernel<<<(MROWS*5 + 255)/256, 256>>>(ptmp + 256, 512, Wa2, ba2, out + (size_t)MROWS*23, 5);
}

// round 10
// speedup vs baseline: 2.6439x; 1.1095x over previous
#include <cuda_runtime.h>
#include <math.h>
#include <stdint.h>

#define BB 8
#define LL 1024
#define DIN 256
#define HH 512
#define NHEAD 8
#define MROWS (BB*LL)   // 8192

// ---------------- scratch (device globals; no allocations) ----------------
__device__ float g_x   [MROWS*HH];
__device__ float g_loc [MROWS*HH];
__device__ float g_qkv [MROWS*3*HH];
__device__ float g_att [MROWS*HH];
__device__ float g_tmp [MROWS*2*HH];
__device__ float g_comb[MROWS*HH];
__device__ float g_si  [MROWS*544];
__device__ float g_h256[MROWS*256];
__device__ float g_pmean[16*BB*HH];
__device__ float g_gpart[BB*HH];
__device__ float g_bsa  [512];
__device__ float g_wt  [3948544];       // transposed (tf32-rounded) weights

// transposed-weight offsets (floats)
#define WT_P    0
#define WT_QKV0 131072
#define WT_QKV1 917504
#define WT_O0   1703936
#define WT_O1   1966080
#define WT_C    2228224
#define WT_1    2490368
#define WT_2    3014656
#define WT_T1   3538944
#define WT_SA   3670016     // Ws1^T rows 0..255, Wa1^T rows 256..511 (K=544)

// ---------------- helpers ---------------------------------------------------
__device__ __forceinline__ uint32_t f2tf32(float f) {
    uint32_t r; asm("cvt.rna.tf32.f32 %0, %1;" : "=r"(r) : "f"(f)); return r;
}
__device__ __forceinline__ uint32_t s2u(const void* p) {
    uint32_t a;
    asm("{ .reg .u64 t; cvta.to.shared.u64 t, %1; cvt.u32.u64 %0, t; }" : "=r"(a) : "l"(p));
    return a;
}
__device__ __forceinline__ void cpa16(uint32_t sdst, const void* gsrc) {
    asm volatile("cp.async.cg.shared.global [%0], [%1], 16;" :: "r"(sdst), "l"(gsrc) : "memory");
}
#define CP_COMMIT() asm volatile("cp.async.commit_group;" ::: "memory")
#define CP_WAIT1()  asm volatile("cp.async.wait_group 1;" ::: "memory")

__device__ __forceinline__ void ldsm4(uint32_t& r0, uint32_t& r1, uint32_t& r2, uint32_t& r3,
                                      uint32_t addr) {
    asm volatile("ldmatrix.sync.aligned.m8n8.x4.shared.b16 {%0,%1,%2,%3}, [%4];"
                 : "=r"(r0), "=r"(r1), "=r"(r2), "=r"(r3) : "r"(addr));
}

__device__ __forceinline__ void mma_tf32(
    float& d0, float& d1, float& d2, float& d3,
    uint32_t a0, uint32_t a1, uint32_t a2, uint32_t a3,
    uint32_t b0, uint32_t b1)
{
    asm volatile(
        "mma.sync.aligned.m16n8k8.row.col.f32.tf32.tf32.f32 "
        "{%0,%1,%2,%3}, {%4,%5,%6,%7}, {%8,%9}, {%0,%1,%2,%3};"
        : "+f"(d0), "+f"(d1), "+f"(d2), "+f"(d3)
        : "r"(a0), "r"(a1), "r"(a2), "r"(a3), "r"(b0), "r"(b1));
}

// ---------------- cp.async tf32 GEMM with ldmatrix fragments ----------------
// C[M,N] = act(A[M,K] @ W[K,N] + bias [+ gb[batch]] [+ res]).  Wt = W^T [N][K].
// Block tile 128x128 (256 thr, 8 warps 4x2, warp tile 32x64), 3-stage cp.async,
// one __syncthreads per K-iter, 2 CTAs/SM.  M%128==0, N%128==0, K%32==0.
#define STG 3
#define SA_ST 36
#define ST_A_FL (128*SA_ST)          // 4608 floats
#define ST_B_FL (128*SA_ST)
#define ST_FL   (ST_A_FL + ST_B_FL)  // 9216 floats
#define SMEM_CP (STG*ST_FL*4)        // 110592 bytes

template<int ACT, bool BBIAS, bool RES>  // ACT: 0=none 1=relu 2=gelu(exact)
__global__ __launch_bounds__(256, 2) void gemm_cp(
    const float* __restrict__ A, int lda,
    const float* __restrict__ Wt,
    const float* __restrict__ bias,
    const float* __restrict__ gb,
    const float* __restrict__ res,
    float* __restrict__ C, int N, int K)
{
    extern __shared__ float sm[];
    const uint32_t sbase = s2u(sm);

    const int tid  = threadIdx.x;
    const int warp = tid >> 5;
    const int lane = tid & 31;
    const int wm = warp >> 1;          // 0..3 -> m offset 32*wm
    const int wn = warp & 1;           // 0..1 -> n offset 64*wn
    const int qr = lane >> 2;          // 0..7
    const int qc = lane & 3;           // 0..3

    // ldmatrix per-lane row byte offsets (within a stage sub-buffer)
    // A: lanes 0-15 -> rows 0..15 col 0; lanes 16-31 -> rows 0..15 col 4
    const uint32_t rowA4 = (uint32_t)(((lane & 15)*SA_ST + 4*(lane >> 4)) * 4);
    // B: m0=n0-7/k0, m1=n0-7/k4, m2=n8-15/k0, m3=n8-15/k4
    const uint32_t rowB4 = (uint32_t)((((lane & 7) + 8*(lane >> 4))*SA_ST + 4*((lane >> 3) & 1)) * 4);

    const int m0 = blockIdx.y * 128;
    const int n0 = blockIdx.x * 128;
    const int nk = K >> 5;

    // cp.async loader indices
    const int lrow = tid >> 3;         // 0..31
    const int lc4  = (tid & 7) * 4;    // 0..28

    const float* Abase = A + (size_t)(m0 + lrow) * lda + lc4;
    const float* Bbase = Wt + (size_t)(n0 + lrow) * K + lc4;

#define STAGE_LOAD(kt) do {                                                   \
        const uint32_t sA = sbase + ((kt) % STG) * (ST_FL*4);                 \
        const uint32_t sB = sA + ST_A_FL*4;                                   \
        _Pragma("unroll")                                                     \
        for (int it = 0; it < 4; it++)                                        \
            cpa16(sA + ((lrow + 32*it)*SA_ST + lc4)*4,                        \
                  Abase + (size_t)(32*it)*lda + (kt)*32);                     \
        _Pragma("unroll")                                                     \
        for (int it = 0; it < 4; it++)                                        \
            cpa16(sB + ((lrow + 32*it)*SA_ST + lc4)*4,                        \
                  Bbase + (size_t)(32*it)*K + (kt)*32);                       \
        CP_COMMIT();                                                          \
    } while (0)

    float acc[2][8][4];
#pragma unroll
    for (int i = 0; i < 2; i++)
#pragma unroll
        for (int j = 0; j < 8; j++)
#pragma unroll
            for (int c = 0; c < 4; c++) acc[i][j][c] = 0.f;

    STAGE_LOAD(0);
    STAGE_LOAD(1);

    for (int kt = 0; kt < nk; kt++) {
        CP_WAIT1();
        __syncthreads();
        if (kt + 2 < nk) STAGE_LOAD(kt + 2);

        const uint32_t sA = sbase + (kt % STG) * (ST_FL*4);
        const uint32_t sB = sA + ST_A_FL*4;
#pragma unroll
        for (int kk = 0; kk < 32; kk += 8) {
            uint32_t a[2][4], b[4][4];
#pragma unroll
            for (int mf = 0; mf < 2; mf++) {
                const uint32_t ad = sA + ((wm*32 + mf*16)*SA_ST + kk)*4 + rowA4;
                ldsm4(a[mf][0], a[mf][1], a[mf][2], a[mf][3], ad);
            }
#pragma unroll
            for (int p = 0; p < 4; p++) {
                const uint32_t bd = sB + ((wn*64 + p*16)*SA_ST + kk)*4 + rowB4;
                ldsm4(b[p][0], b[p][1], b[p][2], b[p][3], bd);
            }
#pragma unroll
            for (int mf = 0; mf < 2; mf++)
#pragma unroll
                for (int i = 0; i < 4; i++)
                    a[mf][i] = f2tf32(__uint_as_float(a[mf][i]));
#pragma unroll
            for (int mf = 0; mf < 2; mf++)
#pragma unroll
                for (int p = 0; p < 4; p++) {
                    mma_tf32(acc[mf][2*p][0], acc[mf][2*p][1],
                             acc[mf][2*p][2], acc[mf][2*p][3],
                             a[mf][0], a[mf][1], a[mf][2], a[mf][3],
                             b[p][0], b[p][1]);
                    mma_tf32(acc[mf][2*p+1][0], acc[mf][2*p+1][1],
                             acc[mf][2*p+1][2], acc[mf][2*p+1][3],
                             a[mf][0], a[mf][1], a[mf][2], a[mf][3],
                             b[p][2], b[p][3]);
                }
        }
    }

    // epilogue
    const int batch = m0 >> 10;
#pragma unroll
    for (int mf = 0; mf < 2; mf++) {
#pragma unroll
        for (int nf = 0; nf < 8; nf++) {
            const int n = n0 + wn*64 + nf*8 + qc*2;
            float bx = 0.f, by = 0.f;
            if (bias) { bx = bias[n]; by = bias[n+1]; }
            if (BBIAS) { bx += gb[batch*N + n]; by += gb[batch*N + n + 1]; }
#pragma unroll
            for (int half = 0; half < 2; half++) {
                const int m = m0 + wm*32 + mf*16 + qr + half*8;
                float v0 = acc[mf][nf][half*2+0] + bx;
                float v1 = acc[mf][nf][half*2+1] + by;
                if (RES) {
                    const float2 r2 = *(const float2*)&res[(size_t)m*N + n];
                    v0 += r2.x; v1 += r2.y;
                }
                if (ACT == 1) { v0 = fmaxf(v0, 0.f); v1 = fmaxf(v1, 0.f); }
                else if (ACT == 2) {
                    v0 = 0.5f*v0*(1.f + erff(v0*0.70710678118654752f));
                    v1 = 0.5f*v1*(1.f + erff(v1*0.70710678118654752f));
                }
                *(float2*)&C[(size_t)m*N + n] = make_float2(v0, v1);
            }
        }
    }
#undef STAGE_LOAD
}

// ---------------- merged weight transpose (+tf32 round) --------------------
#define NJOBS 11
struct TransJobs {
    const float* src[NJOBS];
    long long    dstoff[NJOBS];
    int K[NJOBS], N[NJOBS];
    int start[NJOBS+1];
};

__global__ __launch_bounds__(256) void transpose_all_kernel(TransJobs jobs, float* __restrict__ wt)
{
    __shared__ float t[32][33];
    const int bid = blockIdx.x;
    int j = 0;
#pragma unroll
    for (int i = 0; i < NJOBS; i++) if (bid >= jobs.start[i+1]) j = i+1;
    const int lt = bid - jobs.start[j];
    const int K = jobs.K[j], N = jobs.N[j];
    const int tilesx = N >> 5;
    const int n0 = (lt % tilesx) * 32;
    const int k0 = (lt / tilesx) * 32;
    const float* in = jobs.src[j];
    float* outp = wt + jobs.dstoff[j];

    const int x = threadIdx.x & 31, y = threadIdx.x >> 5;
#pragma unroll
    for (int i = 0; i < 4; i++)
        t[y + 8*i][x] = in[(size_t)(k0 + y + 8*i) * N + n0 + x];
    __syncthreads();
#pragma unroll
    for (int i = 0; i < 4; i++)
        outp[(size_t)(n0 + y + 8*i) * K + k0 + x] = __uint_as_float(f2tf32(t[x][y + 8*i]));
}

// ---------------- windowed attention (NATTEN, window 31) -------------------
// [r][d] smem, stride 65 (==1 mod 32: conflict-free dot reads).
// float4 global loads; SCALAR smem stores (stride 65*4 B is not 16B-aligned).
__global__ __launch_bounds__(64) void natten_kernel(
    const float* __restrict__ qkv, float* __restrict__ out)
{
    const int qt = blockIdx.x;
    const int h  = blockIdx.y;
    const int b  = blockIdx.z;
    const int q0 = qt * 64;
    const int base = q0 - 15;

    __shared__ float ks[94][65];
    __shared__ float vs[94][65];

    const int tid = threadIdx.x;
    for (int idx = tid; idx < 94*16; idx += 64) {
        const int r  = idx >> 4;          // 0..93
        const int d4 = (idx & 15) * 4;
        const int pos = base + r;
        float4 kk4 = make_float4(0.f,0.f,0.f,0.f);
        float4 vv4 = make_float4(0.f,0.f,0.f,0.f);
        if (pos >= 0 && pos < LL) {
            const size_t off = ((size_t)(b*LL + pos))*1536 + h*64 + d4;
            kk4 = *(const float4*)&qkv[off + 512];
            vv4 = *(const float4*)&qkv[off + 1024];
        }
        ks[r][d4+0] = kk4.x; ks[r][d4+1] = kk4.y; ks[r][d4+2] = kk4.z; ks[r][d4+3] = kk4.w;
        vs[r][d4+0] = vv4.x; vs[r][d4+1] = vv4.y; vs[r][d4+2] = vv4.z; vs[r][d4+3] = vv4.w;
    }
    __syncthreads();

    const int l = q0 + tid;
    const float* qp = &qkv[((size_t)(b*LL + l))*1536 + h*64];

    float s[31];
#pragma unroll
    for (int j = 0; j < 31; j++) s[j] = 0.f;

#pragma unroll
    for (int c = 0; c < 4; c++) {
        float q[16];
#pragma unroll
        for (int d4 = 0; d4 < 16; d4 += 4)
            *(float4*)&q[d4] = *(const float4*)&qp[c*16 + d4];
#pragma unroll
        for (int j = 0; j < 31; j++) {
            float dot = 0.f;
#pragma unroll
            for (int d = 0; d < 16; d++)
                dot = fmaf(q[d], ks[tid + j][c*16 + d], dot);
            s[j] += dot;
        }
    }

    float mx = -1e30f;
#pragma unroll
    for (int j = 0; j < 31; j++) {
        const int pos = l - 15 + j;
        if (pos < 0 || pos >= LL) s[j] = -1e30f;
        else                      s[j] *= 0.125f;
        mx = fmaxf(mx, s[j]);
    }
    float sum = 0.f;
#pragma unroll
    for (int j = 0; j < 31; j++) { s[j] = expf(s[j] - mx); sum += s[j]; }
    const float inv = 1.f / sum;

    float* op = &out[((size_t)(b*LL + l))*512 + h*64];
#pragma unroll
    for (int c = 0; c < 4; c++) {
        float o[16];
#pragma unroll
        for (int d = 0; d < 16; d++) o[d] = 0.f;
#pragma unroll
        for (int j = 0; j < 31; j++) {
            const float p = s[j];
#pragma unroll
            for (int d = 0; d < 16; d++)
                o[d] = fmaf(p, vs[tid + j][c*16 + d], o[d]);
        }
#pragma unroll
        for (int d = 0; d < 16; d++) o[d] *= inv;
#pragma unroll
        for (int d4 = 0; d4 < 16; d4 += 4)
            *(float4*)&op[c*16 + d4] = *(float4*)&o[d4];
    }
}

// ---------------- LayerNorm (+clip), single input --------------------------
template<bool CLIP>
__global__ __launch_bounds__(128) void ln_kernel(
    const float* __restrict__ a,
    const float* __restrict__ gam, const float* __restrict__ bet,
    float* __restrict__ outp, int ldo)
{
    const int row = blockIdx.x;
    const int tid = threadIdx.x;
    const float* ap = a + (size_t)row*512;

    float v[4];
    float s = 0.f, s2 = 0.f;
#pragma unroll
    for (int i = 0; i < 4; i++) {
        const float x = ap[tid + 128*i];
        v[i] = x; s += x; s2 += x*x;
    }
    __shared__ float red[2][4];
#pragma unroll
    for (int o = 16; o > 0; o >>= 1) {
        s  += __shfl_down_sync(~0u, s,  o);
        s2 += __shfl_down_sync(~0u, s2, o);
    }
    const int wd = tid >> 5, lane = tid & 31;
    if (lane == 0) { red[0][wd] = s; red[1][wd] = s2; }
    __syncthreads();
    __shared__ float stats[2];
    if (tid == 0) {
        float ts = 0.f, ts2 = 0.f;
#pragma unroll
        for (int w = 0; w < 4; w++) { ts += red[0][w]; ts2 += red[1][w]; }
        const float mean = ts * (1.f/512.f);
        stats[0] = mean;
        stats[1] = rsqrtf(ts2 * (1.f/512.f) - mean*mean + 1e-5f);
    }
    __syncthreads();
    const float mean = stats[0], rstd = stats[1];
    float* op = outp + (size_t)row*ldo;
#pragma unroll
    for (int i = 0; i < 4; i++) {
        const int c = tid + 128*i;
        float y = (v[i] - mean) * rstd * gam[c] + bet[c];
        if (CLIP) y = fminf(fmaxf(y, -100.f), 100.f);
        op[c] = y;
    }
}

// ---------------- partial mean over sequence axis --------------------------
__global__ void mean1_kernel(const float* __restrict__ x, float* __restrict__ outp)
{
    const int c = blockIdx.x*128 + threadIdx.x;
    const int b = blockIdx.y;
    const int z = blockIdx.z;
    const float* p = x + ((size_t)b*LL + z*64)*512 + c;
    float s = 0.f;
#pragma unroll 4
    for (int l = 0; l < 64; l++) s += p[(size_t)l*512];
    outp[(z*BB + b)*512 + c] = s;
}

// ---------------- fused summary: mean2 + @Wg + @Wc[512:] -------------------
__global__ __launch_bounds__(512) void summary_kernel(
    const float* __restrict__ part,
    const float* __restrict__ Wg, const float* __restrict__ bg,
    const float* __restrict__ Wc2, const float* __restrict__ bc,
    float* __restrict__ gpart)
{
    __shared__ float a[512], g[512];
    const int b = blockIdx.x, n = threadIdx.x;
    float s = 0.f;
#pragma unroll
    for (int z = 0; z < 16; z++) s += part[(z*BB + b)*512 + n];
    a[n] = s * (1.f/LL);
    __syncthreads();
    float acc = bg[n];
    for (int k = 0; k < 512; k++) acc = fmaf(a[k], Wg[(size_t)k*512 + n], acc);
    g[n] = acc;
    __syncthreads();
    float acc2 = bc[n];
    for (int k = 0; k < 512; k++) acc2 = fmaf(g[k], Wc2[(size_t)k*512 + n], acc2);
    gpart[b*512 + n] = acc2;
}

// ---------------- bias concat -----------------------------------------------
__global__ void concat_bias_kernel(const float* __restrict__ b1,
                                   const float* __restrict__ b2,
                                   float* __restrict__ o)
{
    const int i = threadIdx.x;
    o[i] = (i < 256) ? b1[i] : b2[i - 256];
}

// ---------------- small-N GEMM (N=5), K=256 --------------------------------
__global__ void small_gemm_kernel(
    const float* __restrict__ A, int lda, const float* __restrict__ W,
    const float* __restrict__ bias, float* __restrict__ C, int N)
{
    const int idx = blockIdx.x*blockDim.x + threadIdx.x;
    if (idx >= MROWS*N) return;
    const int m = idx / N, n = idx - m*N;
    const float* a = A + (size_t)m*lda;
    float s0 = bias[n], s1 = 0.f, s2 = 0.f, s3 = 0.f;
    for (int k = 0; k < 256; k += 4) {
        const float4 av = *(const float4*)&a[k];
        s0 = fmaf(av.x, W[(k  )*N + n], s0);
        s1 = fmaf(av.y, W[(k+1)*N + n], s1);
        s2 = fmaf(av.z, W[(k+2)*N + n], s2);
        s3 = fmaf(av.w, W[(k+3)*N + n], s3);
    }
    C[idx] = (s0 + s1) + (s2 + s3);
}

// ---------------- fused type head: logits + softmax@emb --------------------
__global__ __launch_bounds__(256) void type_head_kernel(
    const float* __restrict__ h,
    const float* __restrict__ Wt2, const float* __restrict__ bt2,
    const float* __restrict__ emb,
    float* __restrict__ out_logits,
    float* __restrict__ si)
{
    __shared__ float As[8][260];
    __shared__ float lg[8][18];
    const int tid = threadIdx.x;
    const int r0 = blockIdx.x * 8;

#pragma unroll
    for (int it = 0; it < 2; it++) {
        const int idx = tid + it*256;
        const int r = idx >> 6;
        const int c4 = (idx & 63) * 4;
        *(float4*)&As[r][c4] = *(const float4*)&h[((size_t)(r0 + r))*256 + c4];
    }
    __syncthreads();

    if (tid < 144) {
        const int r = tid / 18, n = tid - r*18;
        float s0 = bt2[n], s1 = 0.f, s2 = 0.f, s3 = 0.f;
        for (int k = 0; k < 256; k += 4) {
            const float4 av = *(const float4*)&As[r][k];
            s0 = fmaf(av.x, Wt2[(k  )*18 + n], s0);
            s1 = fmaf(av.y, Wt2[(k+1)*18 + n], s1);
            s2 = fmaf(av.z, Wt2[(k+2)*18 + n], s2);
            s3 = fmaf(av.w, Wt2[(k+3)*18 + n], s3);
        }
        const float v = (s0 + s1) + (s2 + s3);
        lg[r][n] = v;
        out_logits[(size_t)(r0 + r)*18 + n] = v;
    }
    __syncthreads();

    const int w = tid >> 5, lane = tid & 31;
    float v[18];
    float mx = -1e30f;
#pragma unroll
    for (int j = 0; j < 18; j++) { v[j] = lg[w][j]; mx = fmaxf(mx, v[j]); }
    float sum = 0.f;
#pragma unroll
    for (int j = 0; j < 18; j++) { v[j] = expf(v[j] - mx); sum += v[j]; }
    const float inv = 1.f / sum;
    float o = 0.f;
#pragma unroll
    for (int j = 0; j < 18; j++) o = fmaf(v[j], emb[j*32 + lane], o);
    si[(size_t)(r0 + w)*544 + 512 + lane] = o * inv;
}

// ---------------- launch ----------------------------------------------------
extern "C" void kernel_launch(void* const* d_in, const int* in_sizes, int n_in,
                              void* d_out, int out_size)
{
    (void)in_sizes; (void)n_in; (void)out_size;
    const float* state = (const float*)d_in[0];
    const float* Wp    = (const float*)d_in[1];
    const float* bp    = (const float*)d_in[2];
    const float* Wqkv  = (const float*)d_in[3];
    const float* bqkv  = (const float*)d_in[4];
    const float* Wo    = (const float*)d_in[5];
    const float* bo    = (const float*)d_in[6];
    const float* ln_g  = (const float*)d_in[7];
    const float* ln_b  = (const float*)d_in[8];
    const float* Wg    = (const float*)d_in[9];
    const float* bg    = (const float*)d_in[10];
    const float* Wc    = (const float*)d_in[11];
    const float* bc    = (const float*)d_in[12];
    const float* W1    = (const float*)d_in[13];
    const float* b1    = (const float*)d_in[14];
    const float* W2    = (const float*)d_in[15];
    const float* b2    = (const float*)d_in[16];
    const float* fn_g  = (const float*)d_in[17];
    const float* fn_b  = (const float*)d_in[18];
    const float* Wt1   = (const float*)d_in[19];
    const float* bt1   = (const float*)d_in[20];
    const float* Wt2   = (const float*)d_in[21];
    const float* bt2   = (const float*)d_in[22];
    const float* temb  = (const float*)d_in[23];
    const float* Ws1   = (const float*)d_in[24];
    const float* bs1   = (const float*)d_in[25];
    const float* Ws2   = (const float*)d_in[26];
    const float* bs2   = (const float*)d_in[27];
    const float* Wa1   = (const float*)d_in[28];
    const float* ba1   = (const float*)d_in[29];
    const float* Wa2   = (const float*)d_in[30];
    const float* ba2   = (const float*)d_in[31];

    float* out = (float*)d_out;

    static float *px=nullptr,*ploc,*pqkv,*patt,*ptmp,*pcomb,*psi,*ph256,*ppm,*pgpart,*pwt,*pbsa;
    if (!px) {
        cudaGetSymbolAddress((void**)&px,    g_x);
        cudaGetSymbolAddress((void**)&ploc,  g_loc);
        cudaGetSymbolAddress((void**)&pqkv,  g_qkv);
        cudaGetSymbolAddress((void**)&patt,  g_att);
        cudaGetSymbolAddress((void**)&ptmp,  g_tmp);
        cudaGetSymbolAddress((void**)&pcomb, g_comb);
        cudaGetSymbolAddress((void**)&psi,   g_si);
        cudaGetSymbolAddress((void**)&ph256, g_h256);
        cudaGetSymbolAddress((void**)&ppm,   g_pmean);
        cudaGetSymbolAddress((void**)&pgpart,g_gpart);
        cudaGetSymbolAddress((void**)&pwt,   g_wt);
        cudaGetSymbolAddress((void**)&pbsa,  g_bsa);
        cudaFuncSetAttribute(gemm_cp<0,false,false>, cudaFuncAttributeMaxDynamicSharedMemorySize, SMEM_CP);
        cudaFuncSetAttribute(gemm_cp<0,false,true >, cudaFuncAttributeMaxDynamicSharedMemorySize, SMEM_CP);
        cudaFuncSetAttribute(gemm_cp<0,true ,false>, cudaFuncAttributeMaxDynamicSharedMemorySize, SMEM_CP);
        cudaFuncSetAttribute(gemm_cp<1,false,false>, cudaFuncAttributeMaxDynamicSharedMemorySize, SMEM_CP);
        cudaFuncSetAttribute(gemm_cp<2,false,false>, cudaFuncAttributeMaxDynamicSharedMemorySize, SMEM_CP);
    }

    // 0. merged transpose (+tf32 round) of all large weights to [N][K]
    {
        TransJobs J;
        const float* srcs[NJOBS] = { Wp, Wqkv, Wqkv + (size_t)512*1536, Wo,
                                     Wo + (size_t)512*512, Wc, W1, W2, Wt1, Ws1, Wa1 };
        const long long offs[NJOBS] = { WT_P, WT_QKV0, WT_QKV1, WT_O0, WT_O1,
                                        WT_C, WT_1, WT_2, WT_T1, WT_SA, WT_SA + 256*544 };
        const int Ks[NJOBS] = { 256, 512, 512, 512, 512, 512, 512, 1024, 512, 544, 544 };
        const int Ns[NJOBS] = { 512, 1536, 1536, 512, 512, 512, 1024, 512, 256, 256, 256 };
        int acc = 0;
        for (int i = 0; i < NJOBS; i++) {
            J.src[i] = srcs[i]; J.dstoff[i] = offs[i]; J.K[i] = Ks[i]; J.N[i] = Ns[i];
            J.start[i] = acc;
            acc += (Ns[i] >> 5) * (Ks[i] >> 5);
        }
        J.start[NJOBS] = acc;
        transpose_all_kernel<<<acc, 256>>>(J, pwt);
    }
    concat_bias_kernel<<<1, 512>>>(bs1, ba1, pbsa);

    const dim3 thr(256);
    #define GEMM(ACT, BBIAS, RESF, Ap, LDA, WT, BIAS, GB, RESP, Cp, NN, KK) \
        gemm_cp<ACT, BBIAS, RESF><<<dim3((NN)/128, MROWS/128), thr, SMEM_CP>>>(Ap, LDA, WT, BIAS, GB, RESP, Cp, NN, KK)

    // 1. x = state @ Wp + bp
    GEMM(0, false, false, state, DIN, pwt+WT_P, bp, nullptr, nullptr, px, 512, 256);

    // 2. two NATTEN layers (residual fused into out-proj epilogue)
    const float* locIn = px;
    for (int i = 0; i < 2; i++) {
        GEMM(0, false, false, locIn, 512, pwt + (i ? WT_QKV1 : WT_QKV0), bqkv + i*1536,
             nullptr, nullptr, pqkv, 1536, 512);
        natten_kernel<<<dim3(LL/64, NHEAD, BB), 64>>>(pqkv, patt);
        GEMM(0, false, true, patt, 512, pwt + (i ? WT_O1 : WT_O0), bo + i*512,
             nullptr, locIn, ptmp, 512, 512);
        ln_kernel<false><<<MROWS, 128>>>(ptmp, ln_g + i*512, ln_b + i*512, ploc, 512);
        locIn = ploc;
    }

    // 3. global summary path (per-batch, tiny, fp32 exact)
    mean1_kernel<<<dim3(4, BB, 16), 128>>>(px, ppm);
    summary_kernel<<<BB, 512>>>(ppm, Wg, bg, Wc + (size_t)512*512, bc, pgpart);

    // 4. comb = loc @ Wc[:512] + gpart[batch]
    GEMM(0, true, false, ploc, 512, pwt+WT_C, nullptr, pgpart, nullptr, pcomb, 512, 512);

    // 5. FFN (residual fused into W2 epilogue) + LN(clip) -> si[:, :512]
    GEMM(2, false, false, pcomb, 512, pwt+WT_1, b1, nullptr, nullptr, ptmp, 1024, 512);
    GEMM(0, false, true, ptmp, 1024, pwt+WT_2, b2, nullptr, pcomb, patt, 512, 1024);
    ln_kernel<true><<<MROWS, 128>>>(patt, fn_g, fn_b, psi, 544);

    // 6. type head: relu GEMM, then fused logits+softmax@emb
    GEMM(1, false, false, psi, 544, pwt+WT_T1, bt1, nullptr, nullptr, ph256, 256, 512);
    type_head_kernel<<<MROWS/8, 256>>>(ph256, Wt2, bt2, temb, out, psi);

    // 7+8. fused size+amount first layer: [Ws1|Wa1], relu -> ptmp [8192][512]
    GEMM(1, false, false, psi, 544, pwt+WT_SA, pbsa, nullptr, nullptr, ptmp, 512, 544);
    small_gemm_kernel<<<(MROWS*5 + 255)/256, 256>>>(ptmp,       512, Ws2, bs2, out + (size_t)MROWS*18, 5);
    small_gemm_kernel<<<(MROWS*5 + 255)/256, 256>>>(ptmp + 256, 512, Wa2, ba2, out + (size_t)MROWS*23, 5);
}

// round 11
// speedup vs baseline: 3.3501x; 1.2671x over previous
#include <cuda_runtime.h>
#include <cuda_fp16.h>
#include <math.h>
#include <stdint.h>

#define BB 8
#define LL 1024
#define DIN 256
#define HH 512
#define NHEAD 8
#define MROWS (BB*LL)   // 8192

// ---------------- scratch (device globals; no allocations) ----------------
__device__ float  g_x    [MROWS*HH];      // x f32 (mean + residual)
__device__ __half g_xh   [MROWS*HH];      // x fp16 (qkv A)
__device__ float  g_loc  [MROWS*HH];
__device__ __half g_loch [MROWS*HH];
__device__ float  g_qkv  [MROWS*3*HH];
__device__ __half g_atth [MROWS*HH];
__device__ float  g_att  [MROWS*HH];      // W2 f32 out
__device__ float  g_tmp  [MROWS*HH];      // out-proj f32 out / SA head f32 out
__device__ __half g_tmp1h[MROWS*2*HH];    // FFN hidden fp16
__device__ float  g_comb [MROWS*HH];
__device__ __half g_combh[MROWS*HH];
__device__ __half g_sih  [MROWS*544];
__device__ float  g_h256 [MROWS*256];
__device__ float  g_pmean[16*BB*HH];
__device__ float  g_gpart[BB*HH];
__device__ float  g_bsa  [512];
__device__ __half g_steh [MROWS*DIN];
__device__ __half g_wt   [3948544];       // transposed fp16 weights

// transposed-weight offsets (halves)
#define WT_P    0
#define WT_QKV0 131072
#define WT_QKV1 917504
#define WT_O0   1703936
#define WT_O1   1966080
#define WT_C    2228224
#define WT_1    2490368
#define WT_2    3014656
#define WT_T1   3538944
#define WT_SA   3670016

// ---------------- helpers ---------------------------------------------------
__device__ __forceinline__ uint32_t s2u(const void* p) {
    uint32_t a;
    asm("{ .reg .u64 t; cvta.to.shared.u64 t, %1; cvt.u32.u64 %0, t; }" : "=r"(a) : "l"(p));
    return a;
}
__device__ __forceinline__ void cpa16(uint32_t sdst, const void* gsrc) {
    asm volatile("cp.async.cg.shared.global [%0], [%1], 16;" :: "r"(sdst), "l"(gsrc) : "memory");
}
#define CP_COMMIT() asm volatile("cp.async.commit_group;" ::: "memory")
#define CP_WAIT2()  asm volatile("cp.async.wait_group 2;" ::: "memory")

__device__ __forceinline__ void ldsm4(uint32_t& r0, uint32_t& r1, uint32_t& r2, uint32_t& r3,
                                      uint32_t addr) {
    asm volatile("ldmatrix.sync.aligned.m8n8.x4.shared.b16 {%0,%1,%2,%3}, [%4];"
                 : "=r"(r0), "=r"(r1), "=r"(r2), "=r"(r3) : "r"(addr));
}

__device__ __forceinline__ void mma_f16(
    float& d0, float& d1, float& d2, float& d3,
    uint32_t a0, uint32_t a1, uint32_t a2, uint32_t a3,
    uint32_t b0, uint32_t b1)
{
    asm volatile(
        "mma.sync.aligned.m16n8k16.row.col.f32.f16.f16.f32 "
        "{%0,%1,%2,%3}, {%4,%5,%6,%7}, {%8,%9}, {%0,%1,%2,%3};"
        : "+f"(d0), "+f"(d1), "+f"(d2), "+f"(d3)
        : "r"(a0), "r"(a1), "r"(a2), "r"(a3), "r"(b0), "r"(b1));
}

// ---------------- fp16 cp.async GEMM with ldmatrix ---------------------------
// C = act(A[M,K]h @ W[K,N] + bias [+ gb[batch]] [+ res_f32]); writes f32 and/or fp16.
// Wt = fp16 W^T [N][K].  Block 128x128, 256 thr (8 warps 4x2, warp 32x64),
// 4-stage cp.async (wait_group 2, always-commit), 2 CTAs/SM.
// M%128==0, N%128==0, K%32==0, nk>=3.
#define RS 40                         // smem row stride in halves (80 B)
#define ST_MAT_H (128*RS)             // 5120 halves per matrix
#define ST_BYTES (2*ST_MAT_H*2)       // 20480 B per stage (A+B)
#define SMEM_H   (4*ST_BYTES)         // 81920 B

template<int ACT, bool BBIAS, bool RES, bool WF, bool WH>
__global__ __launch_bounds__(256, 2) void gemm_h(
    const __half* __restrict__ A, int lda,
    const __half* __restrict__ Wt,
    const float* __restrict__ bias,
    const float* __restrict__ gb,
    const float* __restrict__ res,
    float* __restrict__ Cf, __half* __restrict__ Ch,
    int N, int K)
{
    extern __shared__ __half smh[];
    const uint32_t sbase = s2u(smh);

    const int tid  = threadIdx.x;
    const int warp = tid >> 5;
    const int lane = tid & 31;
    const int wm = warp >> 1;          // m offset 32*wm
    const int wn = warp & 1;           // n offset 64*wn
    const int qr = lane >> 2;
    const int qc = lane & 3;

    // ldmatrix lane address components (halves)
    const int lrow = (lane & 7) + 8*((lane >> 3) & 1);   // row within 16-block
    const int lk   = 8*(lane >> 4);                      // k half-offset (0|8)

    const int m0 = blockIdx.y * 128;
    const int n0 = blockIdx.x * 128;
    const int nk = K >> 5;

    // cp.async loader: per matrix 128 rows x 4 chunks(16B=8 halves)
    const float* dummy = nullptr; (void)dummy;

#define STAGE_LOAD(kt) do {                                                     \
        const uint32_t sA = sbase + ((kt) & 3) * ST_BYTES;                      \
        const uint32_t sB = sA + ST_MAT_H*2;                                    \
        _Pragma("unroll")                                                       \
        for (int it = 0; it < 2; it++) {                                        \
            const int id  = tid + 256*it;                                       \
            const int row = id >> 2;                                            \
            const int c8  = (id & 3) * 8;                                       \
            cpa16(sA + (row*RS + c8)*2,                                         \
                  A  + (size_t)(m0 + row)*lda + (kt)*32 + c8);                  \
            cpa16(sB + (row*RS + c8)*2,                                         \
                  Wt + (size_t)(n0 + row)*K   + (kt)*32 + c8);                  \
        }                                                                       \
        CP_COMMIT();                                                            \
    } while (0)

    float acc[2][8][4];
#pragma unroll
    for (int i = 0; i < 2; i++)
#pragma unroll
        for (int j = 0; j < 8; j++)
#pragma unroll
            for (int c = 0; c < 4; c++) acc[i][j][c] = 0.f;

    STAGE_LOAD(0);
    STAGE_LOAD(1);
    STAGE_LOAD(2);

    for (int kt = 0; kt < nk; kt++) {
        CP_WAIT2();                    // stage kt complete (3 groups always outstanding)
        __syncthreads();
        if (kt + 3 < nk) STAGE_LOAD(kt + 3); else CP_COMMIT();

        const uint32_t sA = sbase + (kt & 3) * ST_BYTES;
        const uint32_t sB = sA + ST_MAT_H*2;
#pragma unroll
        for (int kk = 0; kk < 32; kk += 16) {
            uint32_t a[2][4], b[4][4];
#pragma unroll
            for (int mf = 0; mf < 2; mf++) {
                const uint32_t ad = sA + ((wm*32 + mf*16 + lrow)*RS + kk + lk)*2;
                ldsm4(a[mf][0], a[mf][1], a[mf][2], a[mf][3], ad);
            }
#pragma unroll
            for (int ng = 0; ng < 4; ng++) {
                const uint32_t bd = sB + ((wn*64 + ng*16 + lrow)*RS + kk + lk)*2;
                ldsm4(b[ng][0], b[ng][1], b[ng][2], b[ng][3], bd);
            }
#pragma unroll
            for (int mf = 0; mf < 2; mf++)
#pragma unroll
                for (int ng = 0; ng < 4; ng++) {
                    mma_f16(acc[mf][2*ng][0], acc[mf][2*ng][1],
                            acc[mf][2*ng][2], acc[mf][2*ng][3],
                            a[mf][0], a[mf][1], a[mf][2], a[mf][3],
                            b[ng][0], b[ng][2]);
                    mma_f16(acc[mf][2*ng+1][0], acc[mf][2*ng+1][1],
                            acc[mf][2*ng+1][2], acc[mf][2*ng+1][3],
                            a[mf][0], a[mf][1], a[mf][2], a[mf][3],
                            b[ng][1], b[ng][3]);
                }
        }
    }

    // epilogue
    const int batch = m0 >> 10;
#pragma unroll
    for (int mf = 0; mf < 2; mf++) {
#pragma unroll
        for (int nf = 0; nf < 8; nf++) {
            const int n = n0 + wn*64 + nf*8 + qc*2;
            float bx = 0.f, by = 0.f;
            if (bias) { bx = bias[n]; by = bias[n+1]; }
            if (BBIAS) { bx += gb[batch*N + n]; by += gb[batch*N + n + 1]; }
#pragma unroll
            for (int half = 0; half < 2; half++) {
                const int m = m0 + wm*32 + mf*16 + qr + half*8;
                float v0 = acc[mf][nf][half*2+0] + bx;
                float v1 = acc[mf][nf][half*2+1] + by;
                if (RES) {
                    const float2 r2 = *(const float2*)&res[(size_t)m*N + n];
                    v0 += r2.x; v1 += r2.y;
                }
                if (ACT == 1) { v0 = fmaxf(v0, 0.f); v1 = fmaxf(v1, 0.f); }
                else if (ACT == 2) {
                    v0 = 0.5f*v0*(1.f + erff(v0*0.70710678118654752f));
                    v1 = 0.5f*v1*(1.f + erff(v1*0.70710678118654752f));
                }
                if (WF) *(float2*)&Cf[(size_t)m*N + n] = make_float2(v0, v1);
                if (WH) *(__half2*)&Ch[(size_t)m*N + n] =
                            __halves2half2(__float2half_rn(v0), __float2half_rn(v1));
            }
        }
    }
#undef STAGE_LOAD
}

// ---------------- merged weight transpose (f32 -> fp16 [N][K]) --------------
#define NJOBS 11
struct TransJobs {
    const float* src[NJOBS];
    long long    dstoff[NJOBS];
    int K[NJOBS], N[NJOBS];
    int start[NJOBS+1];
};

__global__ __launch_bounds__(256) void transpose_all_kernel(TransJobs jobs, __half* __restrict__ wt)
{
    __shared__ float t[32][33];
    const int bid = blockIdx.x;
    int j = 0;
#pragma unroll
    for (int i = 0; i < NJOBS; i++) if (bid >= jobs.start[i+1]) j = i+1;
    const int lt = bid - jobs.start[j];
    const int K = jobs.K[j], N = jobs.N[j];
    const int tilesx = N >> 5;
    const int n0 = (lt % tilesx) * 32;
    const int k0 = (lt / tilesx) * 32;
    const float* in = jobs.src[j];
    __half* outp = wt + jobs.dstoff[j];

    const int x = threadIdx.x & 31, y = threadIdx.x >> 5;
#pragma unroll
    for (int i = 0; i < 4; i++)
        t[y + 8*i][x] = in[(size_t)(k0 + y + 8*i) * N + n0 + x];
    __syncthreads();
#pragma unroll
    for (int i = 0; i < 4; i++)
        outp[(size_t)(n0 + y + 8*i) * K + k0 + x] = __float2half_rn(t[x][y + 8*i]);
}

// ---------------- f32 -> fp16 convert (state) -------------------------------
__global__ void tohalf_kernel(const float* __restrict__ in, __half* __restrict__ o, int n2)
{
    const int i = blockIdx.x*256 + threadIdx.x;
    if (i < n2) {
        const float2 v = ((const float2*)in)[i];
        ((__half2*)o)[i] = __halves2half2(__float2half_rn(v.x), __float2half_rn(v.y));
    }
}

// ---------------- windowed attention (NATTEN, window 31) -------------------
__global__ __launch_bounds__(64) void natten_kernel(
    const float* __restrict__ qkv, __half* __restrict__ out)
{
    const int qt = blockIdx.x;
    const int h  = blockIdx.y;
    const int b  = blockIdx.z;
    const int q0 = qt * 64;
    const int base = q0 - 15;

    __shared__ float ks[94][65];
    __shared__ float vs[94][65];

    const int tid = threadIdx.x;
    for (int idx = tid; idx < 94*16; idx += 64) {
        const int r  = idx >> 4;
        const int d4 = (idx & 15) * 4;
        const int pos = base + r;
        float4 kk4 = make_float4(0.f,0.f,0.f,0.f);
        float4 vv4 = make_float4(0.f,0.f,0.f,0.f);
        if (pos >= 0 && pos < LL) {
            const size_t off = ((size_t)(b*LL + pos))*1536 + h*64 + d4;
            kk4 = *(const float4*)&qkv[off + 512];
            vv4 = *(const float4*)&qkv[off + 1024];
        }
        ks[r][d4+0] = kk4.x; ks[r][d4+1] = kk4.y; ks[r][d4+2] = kk4.z; ks[r][d4+3] = kk4.w;
        vs[r][d4+0] = vv4.x; vs[r][d4+1] = vv4.y; vs[r][d4+2] = vv4.z; vs[r][d4+3] = vv4.w;
    }
    __syncthreads();

    const int l = q0 + tid;
    const float* qp = &qkv[((size_t)(b*LL + l))*1536 + h*64];

    float s[31];
#pragma unroll
    for (int j = 0; j < 31; j++) s[j] = 0.f;

#pragma unroll
    for (int c = 0; c < 4; c++) {
        float q[16];
#pragma unroll
        for (int d4 = 0; d4 < 16; d4 += 4)
            *(float4*)&q[d4] = *(const float4*)&qp[c*16 + d4];
#pragma unroll
        for (int j = 0; j < 31; j++) {
            float dot = 0.f;
#pragma unroll
            for (int d = 0; d < 16; d++)
                dot = fmaf(q[d], ks[tid + j][c*16 + d], dot);
            s[j] += dot;
        }
    }

    float mx = -1e30f;
#pragma unroll
    for (int j = 0; j < 31; j++) {
        const int pos = l - 15 + j;
        if (pos < 0 || pos >= LL) s[j] = -1e30f;
        else                      s[j] *= 0.125f;
        mx = fmaxf(mx, s[j]);
    }
    float sum = 0.f;
#pragma unroll
    for (int j = 0; j < 31; j++) { s[j] = expf(s[j] - mx); sum += s[j]; }
    const float inv = 1.f / sum;

    __half* op = &out[((size_t)(b*LL + l))*512 + h*64];
#pragma unroll
    for (int c = 0; c < 4; c++) {
        float o[16];
#pragma unroll
        for (int d = 0; d < 16; d++) o[d] = 0.f;
#pragma unroll
        for (int j = 0; j < 31; j++) {
            const float p = s[j];
#pragma unroll
            for (int d = 0; d < 16; d++)
                o[d] = fmaf(p, vs[tid + j][c*16 + d], o[d]);
        }
#pragma unroll
        for (int d = 0; d < 16; d += 2)
            *(__half2*)&op[c*16 + d] = __halves2half2(__float2half_rn(o[d]*inv),
                                                      __float2half_rn(o[d+1]*inv));
    }
}

// ---------------- LayerNorm (+clip), dual output ----------------------------
template<bool CLIP, bool WF, bool WH>
__global__ __launch_bounds__(128) void ln_kernel(
    const float* __restrict__ a,
    const float* __restrict__ gam, const float* __restrict__ bet,
    float* __restrict__ outf, int ldf,
    __half* __restrict__ outh, int ldh)
{
    const int row = blockIdx.x;
    const int tid = threadIdx.x;
    const float* ap = a + (size_t)row*512;

    float v[4];
    float s = 0.f, s2 = 0.f;
#pragma unroll
    for (int i = 0; i < 4; i++) {
        const float x = ap[tid + 128*i];
        v[i] = x; s += x; s2 += x*x;
    }
    __shared__ float red[2][4];
#pragma unroll
    for (int o = 16; o > 0; o >>= 1) {
        s  += __shfl_down_sync(~0u, s,  o);
        s2 += __shfl_down_sync(~0u, s2, o);
    }
    const int wd = tid >> 5, lane = tid & 31;
    if (lane == 0) { red[0][wd] = s; red[1][wd] = s2; }
    __syncthreads();
    __shared__ float stats[2];
    if (tid == 0) {
        float ts = 0.f, ts2 = 0.f;
#pragma unroll
        for (int w = 0; w < 4; w++) { ts += red[0][w]; ts2 += red[1][w]; }
        const float mean = ts * (1.f/512.f);
        stats[0] = mean;
        stats[1] = rsqrtf(ts2 * (1.f/512.f) - mean*mean + 1e-5f);
    }
    __syncthreads();
    const float mean = stats[0], rstd = stats[1];
#pragma unroll
    for (int i = 0; i < 4; i++) {
        const int c = tid + 128*i;
        float y = (v[i] - mean) * rstd * gam[c] + bet[c];
        if (CLIP) y = fminf(fmaxf(y, -100.f), 100.f);
        if (WF) outf[(size_t)row*ldf + c] = y;
        if (WH) outh[(size_t)row*ldh + c] = __float2half_rn(y);
    }
}

// ---------------- partial mean over sequence axis --------------------------
__global__ void mean1_kernel(const float* __restrict__ x, float* __restrict__ outp)
{
    const int c = blockIdx.x*128 + threadIdx.x;
    const int b = blockIdx.y;
    const int z = blockIdx.z;
    const float* p = x + ((size_t)b*LL + z*64)*512 + c;
    float s = 0.f;
#pragma unroll 4
    for (int l = 0; l < 64; l++) s += p[(size_t)l*512];
    outp[(z*BB + b)*512 + c] = s;
}

// ---------------- fused summary: mean2 + @Wg + @Wc[512:] -------------------
__global__ __launch_bounds__(512) void summary_kernel(
    const float* __restrict__ part,
    const float* __restrict__ Wg, const float* __restrict__ bg,
    const float* __restrict__ Wc2, const float* __restrict__ bc,
    float* __restrict__ gpart)
{
    __shared__ float a[512], g[512];
    const int b = blockIdx.x, n = threadIdx.x;
    float s = 0.f;
#pragma unroll
    for (int z = 0; z < 16; z++) s += part[(z*BB + b)*512 + n];
    a[n] = s * (1.f/LL);
    __syncthreads();
    float acc = bg[n];
    for (int k = 0; k < 512; k++) acc = fmaf(a[k], Wg[(size_t)k*512 + n], acc);
    g[n] = acc;
    __syncthreads();
    float acc2 = bc[n];
    for (int k = 0; k < 512; k++) acc2 = fmaf(g[k], Wc2[(size_t)k*512 + n], acc2);
    gpart[b*512 + n] = acc2;
}

// ---------------- bias concat -----------------------------------------------
__global__ void concat_bias_kernel(const float* __restrict__ b1,
                                   const float* __restrict__ b2,
                                   float* __restrict__ o)
{
    const int i = threadIdx.x;
    o[i] = (i < 256) ? b1[i] : b2[i - 256];
}

// ---------------- small-N GEMM (N=5), K=256 --------------------------------
__global__ void small_gemm_kernel(
    const float* __restrict__ A, int lda, const float* __restrict__ W,
    const float* __restrict__ bias, float* __restrict__ C, int N)
{
    const int idx = blockIdx.x*blockDim.x + threadIdx.x;
    if (idx >= MROWS*N) return;
    const int m = idx / N, n = idx - m*N;
    const float* a = A + (size_t)m*lda;
    float s0 = bias[n], s1 = 0.f, s2 = 0.f, s3 = 0.f;
    for (int k = 0; k < 256; k += 4) {
        const float4 av = *(const float4*)&a[k];
        s0 = fmaf(av.x, W[(k  )*N + n], s0);
        s1 = fmaf(av.y, W[(k+1)*N + n], s1);
        s2 = fmaf(av.z, W[(k+2)*N + n], s2);
        s3 = fmaf(av.w, W[(k+3)*N + n], s3);
    }
    C[idx] = (s0 + s1) + (s2 + s3);
}

// ---------------- fused type head: logits + softmax@emb --------------------
__global__ __launch_bounds__(256) void type_head_kernel(
    const float* __restrict__ h,
    const float* __restrict__ Wt2, const float* __restrict__ bt2,
    const float* __restrict__ emb,
    float* __restrict__ out_logits,
    __half* __restrict__ si)
{
    __shared__ float As[8][260];
    __shared__ float lg[8][18];
    const int tid = threadIdx.x;
    const int r0 = blockIdx.x * 8;

#pragma unroll
    for (int it = 0; it < 2; it++) {
        const int idx = tid + it*256;
        const int r = idx >> 6;
        const int c4 = (idx & 63) * 4;
        *(float4*)&As[r][c4] = *(const float4*)&h[((size_t)(r0 + r))*256 + c4];
    }
    __syncthreads();

    if (tid < 144) {
        const int r = tid / 18, n = tid - r*18;
        float s0 = bt2[n], s1 = 0.f, s2 = 0.f, s3 = 0.f;
        for (int k = 0; k < 256; k += 4) {
            const float4 av = *(const float4*)&As[r][k];
            s0 = fmaf(av.x, Wt2[(k  )*18 + n], s0);
            s1 = fmaf(av.y, Wt2[(k+1)*18 + n], s1);
            s2 = fmaf(av.z, Wt2[(k+2)*18 + n], s2);
            s3 = fmaf(av.w, Wt2[(k+3)*18 + n], s3);
        }
        const float v = (s0 + s1) + (s2 + s3);
        lg[r][n] = v;
        out_logits[(size_t)(r0 + r)*18 + n] = v;
    }
    __syncthreads();

    const int w = tid >> 5, lane = tid & 31;
    float v[18];
    float mx = -1e30f;
#pragma unroll
    for (int j = 0; j < 18; j++) { v[j] = lg[w][j]; mx = fmaxf(mx, v[j]); }
    float sum = 0.f;
#pragma unroll
    for (int j = 0; j < 18; j++) { v[j] = expf(v[j] - mx); sum += v[j]; }
    const float inv = 1.f / sum;
    float o = 0.f;
#pragma unroll
    for (int j = 0; j < 18; j++) o = fmaf(v[j], emb[j*32 + lane], o);
    si[(size_t)(r0 + w)*544 + 512 + lane] = __float2half_rn(o * inv);
}

// ---------------- launch ----------------------------------------------------
extern "C" void kernel_launch(void* const* d_in, const int* in_sizes, int n_in,
                              void* d_out, int out_size)
{
    (void)in_sizes; (void)n_in; (void)out_size;
    const float* state = (const float*)d_in[0];
    const float* Wp    = (const float*)d_in[1];
    const float* bp    = (const float*)d_in[2];
    const float* Wqkv  = (const float*)d_in[3];
    const float* bqkv  = (const float*)d_in[4];
    const float* Wo    = (const float*)d_in[5];
    const float* bo    = (const float*)d_in[6];
    const float* ln_g  = (const float*)d_in[7];
    const float* ln_b  = (const float*)d_in[8];
    const float* Wg    = (const float*)d_in[9];
    const float* bg    = (const float*)d_in[10];
    const float* Wc    = (const float*)d_in[11];
    const float* bc    = (const float*)d_in[12];
    const float* W1    = (const float*)d_in[13];
    const float* b1    = (const float*)d_in[14];
    const float* W2    = (const float*)d_in[15];
    const float* b2    = (const float*)d_in[16];
    const float* fn_g  = (const float*)d_in[17];
    const float* fn_b  = (const float*)d_in[18];
    const float* Wt1   = (const float*)d_in[19];
    const float* bt1   = (const float*)d_in[20];
    const float* Wt2   = (const float*)d_in[21];
    const float* bt2   = (const float*)d_in[22];
    const float* temb  = (const float*)d_in[23];
    const float* Ws1   = (const float*)d_in[24];
    const float* bs1   = (const float*)d_in[25];
    const float* Ws2   = (const float*)d_in[26];
    const float* bs2   = (const float*)d_in[27];
    const float* Wa1   = (const float*)d_in[28];
    const float* ba1   = (const float*)d_in[29];
    const float* Wa2   = (const float*)d_in[30];
    const float* ba2   = (const float*)d_in[31];

    float* out = (float*)d_out;

    static float *px=nullptr,*ploc,*pqkv,*pattf,*ptmp,*pcomb,*ph256,*ppm,*pgpart,*pbsa;
    static __half *pxh,*ploch,*patth,*ptmp1h,*pcombh,*psih,*psteh,*pwt;
    if (!px) {
        cudaGetSymbolAddress((void**)&px,    g_x);
        cudaGetSymbolAddress((void**)&pxh,   g_xh);
        cudaGetSymbolAddress((void**)&ploc,  g_loc);
        cudaGetSymbolAddress((void**)&ploch, g_loch);
        cudaGetSymbolAddress((void**)&pqkv,  g_qkv);
        cudaGetSymbolAddress((void**)&pattf, g_att);
        cudaGetSymbolAddress((void**)&patth, g_atth);
        cudaGetSymbolAddress((void**)&ptmp,  g_tmp);
        cudaGetSymbolAddress((void**)&ptmp1h,g_tmp1h);
        cudaGetSymbolAddress((void**)&pcomb, g_comb);
        cudaGetSymbolAddress((void**)&pcombh,g_combh);
        cudaGetSymbolAddress((void**)&psih,  g_sih);
        cudaGetSymbolAddress((void**)&ph256, g_h256);
        cudaGetSymbolAddress((void**)&ppm,   g_pmean);
        cudaGetSymbolAddress((void**)&pgpart,g_gpart);
        cudaGetSymbolAddress((void**)&pbsa,  g_bsa);
        cudaGetSymbolAddress((void**)&psteh, g_steh);
        cudaGetSymbolAddress((void**)&pwt,   g_wt);
        cudaFuncSetAttribute(gemm_h<0,false,false,true ,true >, cudaFuncAttributeMaxDynamicSharedMemorySize, SMEM_H);
        cudaFuncSetAttribute(gemm_h<0,false,false,true ,false>, cudaFuncAttributeMaxDynamicSharedMemorySize, SMEM_H);
        cudaFuncSetAttribute(gemm_h<0,false,true ,true ,false>, cudaFuncAttributeMaxDynamicSharedMemorySize, SMEM_H);
        cudaFuncSetAttribute(gemm_h<0,true ,false,true ,true >, cudaFuncAttributeMaxDynamicSharedMemorySize, SMEM_H);
        cudaFuncSetAttribute(gemm_h<2,false,false,false,true >, cudaFuncAttributeMaxDynamicSharedMemorySize, SMEM_H);
        cudaFuncSetAttribute(gemm_h<1,false,false,true ,false>, cudaFuncAttributeMaxDynamicSharedMemorySize, SMEM_H);
    }

    // 0. transposed fp16 weights + fp16 state + concat bias
    {
        TransJobs J;
        const float* srcs[NJOBS] = { Wp, Wqkv, Wqkv + (size_t)512*1536, Wo,
                                     Wo + (size_t)512*512, Wc, W1, W2, Wt1, Ws1, Wa1 };
        const long long offs[NJOBS] = { WT_P, WT_QKV0, WT_QKV1, WT_O0, WT_O1,
                                        WT_C, WT_1, WT_2, WT_T1, WT_SA, WT_SA + 256*544 };
        const int Ks[NJOBS] = { 256, 512, 512, 512, 512, 512, 512, 1024, 512, 544, 544 };
        const int Ns[NJOBS] = { 512, 1536, 1536, 512, 512, 512, 1024, 512, 256, 256, 256 };
        int acc = 0;
        for (int i = 0; i < NJOBS; i++) {
            J.src[i] = srcs[i]; J.dstoff[i] = offs[i]; J.K[i] = Ks[i]; J.N[i] = Ns[i];
            J.start[i] = acc;
            acc += (Ns[i] >> 5) * (Ks[i] >> 5);
        }
        J.start[NJOBS] = acc;
        transpose_all_kernel<<<acc, 256>>>(J, pwt);
    }
    tohalf_kernel<<<(MROWS*DIN/2 + 255)/256, 256>>>(state, psteh, MROWS*DIN/2);
    concat_bias_kernel<<<1, 512>>>(bs1, ba1, pbsa);

    const dim3 thr(256);
    #define GEMM(T1,T2,T3,T4,T5, Ap, LDA, WT, BIAS, GB, RESP, CF, CH, NN, KK) \
        gemm_h<T1,T2,T3,T4,T5><<<dim3((NN)/128, MROWS/128), thr, SMEM_H>>>(Ap, LDA, WT, BIAS, GB, RESP, CF, CH, NN, KK)

    // 1. x = state @ Wp + bp  (f32 + fp16)
    GEMM(0,false,false,true,true, psteh, DIN, pwt+WT_P, bp, nullptr, nullptr, px, pxh, 512, 256);

    // 2. two NATTEN layers
    const float*  locF = px;
    const __half* locH = pxh;
    for (int i = 0; i < 2; i++) {
        GEMM(0,false,false,true,false, locH, 512, pwt + (i ? WT_QKV1 : WT_QKV0), bqkv + i*1536,
             nullptr, nullptr, pqkv, (__half*)nullptr, 1536, 512);
        natten_kernel<<<dim3(LL/64, NHEAD, BB), 64>>>(pqkv, patth);
        GEMM(0,false,true,true,false, patth, 512, pwt + (i ? WT_O1 : WT_O0), bo + i*512,
             nullptr, locF, ptmp, (__half*)nullptr, 512, 512);
        ln_kernel<false,true,true><<<MROWS, 128>>>(ptmp, ln_g + i*512, ln_b + i*512,
                                                   ploc, 512, ploch, 512);
        locF = ploc; locH = ploch;
    }

    // 3. global summary path (per-batch, f32 exact)
    mean1_kernel<<<dim3(4, BB, 16), 128>>>(px, ppm);
    summary_kernel<<<BB, 512>>>(ppm, Wg, bg, Wc + (size_t)512*512, bc, pgpart);

    // 4. comb = loc @ Wc[:512] + gpart[batch]  (f32 + fp16)
    GEMM(0,true,false,true,true, ploch, 512, pwt+WT_C, nullptr, pgpart, nullptr,
         pcomb, pcombh, 512, 512);

    // 5. FFN (hidden fp16 only; residual fused into W2) + LN(clip) -> si_h
    GEMM(2,false,false,false,true, pcombh, 512, pwt+WT_1, b1, nullptr, nullptr,
         (float*)nullptr, ptmp1h, 1024, 512);
    GEMM(0,false,true,true,false, ptmp1h, 1024, pwt+WT_2, b2, nullptr, pcomb,
         pattf, (__half*)nullptr, 512, 1024);
    ln_kernel<true,false,true><<<MROWS, 128>>>(pattf, fn_g, fn_b,
                                               (float*)nullptr, 0, psih, 544);

    // 6. type head
    GEMM(1,false,false,true,false, psih, 544, pwt+WT_T1, bt1, nullptr, nullptr,
         ph256, (__half*)nullptr, 256, 512);
    type_head_kernel<<<MROWS/8, 256>>>(ph256, Wt2, bt2, temb, out, psih);

    // 7+8. fused size+amount first layer (K=544 incl. temb cols)
    GEMM(1,false,false,true,false, psih, 544, pwt+WT_SA, pbsa, nullptr, nullptr,
         ptmp, (__half*)nullptr, 512, 544);
    small_gemm_kernel<<<(MROWS*5 + 255)/256, 256>>>(ptmp,       512, Ws2, bs2, out + (size_t)MROWS*18, 5);
    small_gemm_kernel<<<(MROWS*5 + 255)/256, 256>>>(ptmp + 256, 512, Wa2, ba2, out + (size_t)MROWS*23, 5);
}

// round 13
// speedup vs baseline: 3.4957x; 1.0435x over previous
#include <cuda_runtime.h>
#include <cuda_fp16.h>
#include <math.h>
#include <stdint.h>

#define BB 8
#define LL 1024
#define DIN 256
#define HH 512
#define NHEAD 8
#define MROWS (BB*LL)   // 8192

// ---------------- scratch (device globals; no allocations) ----------------
__device__ float  g_x    [MROWS*HH];
__device__ __half g_xh   [MROWS*HH];
__device__ float  g_loc  [MROWS*HH];
__device__ __half g_loch [MROWS*HH];
__device__ float  g_qkv  [MROWS*3*HH];
__device__ __half g_atth [MROWS*HH];
__device__ float  g_att  [MROWS*HH];
__device__ float  g_tmp  [MROWS*HH];
__device__ __half g_tmp1h[MROWS*2*HH];
__device__ float  g_comb [MROWS*HH];
__device__ __half g_combh[MROWS*HH];
__device__ __half g_sih  [MROWS*544];
__device__ float  g_h256 [MROWS*256];
__device__ float  g_pmean[16*BB*HH];
__device__ float  g_gpart[BB*HH];
__device__ float  g_bsa  [512];
__device__ __half g_steh [MROWS*DIN];
__device__ __half g_wt   [3948544];

// transposed-weight offsets (halves)
#define WT_P    0
#define WT_QKV0 131072
#define WT_QKV1 917504
#define WT_O0   1703936
#define WT_O1   1966080
#define WT_C    2228224
#define WT_1    2490368
#define WT_2    3014656
#define WT_T1   3538944
#define WT_SA   3670016

// ---------------- helpers ---------------------------------------------------
__device__ __forceinline__ uint32_t s2u(const void* p) {
    uint32_t a;
    asm("{ .reg .u64 t; cvta.to.shared.u64 t, %1; cvt.u32.u64 %0, t; }" : "=r"(a) : "l"(p));
    return a;
}
__device__ __forceinline__ void cpa16(uint32_t sdst, const void* gsrc) {
    asm volatile("cp.async.cg.shared.global [%0], [%1], 16;" :: "r"(sdst), "l"(gsrc) : "memory");
}
#define CP_COMMIT() asm volatile("cp.async.commit_group;" ::: "memory")
#define CP_WAIT3()  asm volatile("cp.async.wait_group 3;" ::: "memory")

__device__ __forceinline__ void ldsm4(uint32_t& r0, uint32_t& r1, uint32_t& r2, uint32_t& r3,
                                      uint32_t addr) {
    asm volatile("ldmatrix.sync.aligned.m8n8.x4.shared.b16 {%0,%1,%2,%3}, [%4];"
                 : "=r"(r0), "=r"(r1), "=r"(r2), "=r"(r3) : "r"(addr));
}

__device__ __forceinline__ void mma_f16(
    float& d0, float& d1, float& d2, float& d3,
    uint32_t a0, uint32_t a1, uint32_t a2, uint32_t a3,
    uint32_t b0, uint32_t b1)
{
    asm volatile(
        "mma.sync.aligned.m16n8k16.row.col.f32.f16.f16.f32 "
        "{%0,%1,%2,%3}, {%4,%5,%6,%7}, {%8,%9}, {%0,%1,%2,%3};"
        : "+f"(d0), "+f"(d1), "+f"(d2), "+f"(d3)
        : "r"(a0), "r"(a1), "r"(a2), "r"(a3), "r"(b0), "r"(b1));
}

// ---------------- fp16 cp.async GEMM with ldmatrix ---------------------------
// Block 128x128, 256 thr (8 warps 4x2, warp 32x64), 5-stage cp.async
// (wait_group 3, always-commit), 2 CTAs/SM.  M%128==0, N%128==0, K%32==0, nk>=4.
#define RS 40
#define ST_MAT_H (128*RS)
#define ST_BYTES (2*ST_MAT_H*2)       // 20480 B per stage
#define NSTG 5
#define SMEM_H   (NSTG*ST_BYTES)      // 102400 B

template<int ACT, bool BBIAS, bool RES, bool WF, bool WH>
__global__ __launch_bounds__(256, 2) void gemm_h(
    const __half* __restrict__ A, int lda,
    const __half* __restrict__ Wt,
    const float* __restrict__ bias,
    const float* __restrict__ gb,
    const float* __restrict__ res,
    float* __restrict__ Cf, __half* __restrict__ Ch,
    int N, int K)
{
    extern __shared__ __half smh[];
    const uint32_t sbase = s2u(smh);

    const int tid  = threadIdx.x;
    const int warp = tid >> 5;
    const int lane = tid & 31;
    const int wm = warp >> 1;
    const int wn = warp & 1;
    const int qr = lane >> 2;
    const int qc = lane & 3;

    const int lrow = (lane & 7) + 8*((lane >> 3) & 1);
    const int lk   = 8*(lane >> 4);

    const int m0 = blockIdx.y * 128;
    const int n0 = blockIdx.x * 128;
    const int nk = K >> 5;

#define STAGE_LOAD(kt) do {                                                     \
        const uint32_t sA = sbase + ((kt) % NSTG) * ST_BYTES;                   \
        const uint32_t sB = sA + ST_MAT_H*2;                                    \
        _Pragma("unroll")                                                       \
        for (int it = 0; it < 2; it++) {                                        \
            const int id  = tid + 256*it;                                       \
            const int row = id >> 2;                                            \
            const int c8  = (id & 3) * 8;                                       \
            cpa16(sA + (row*RS + c8)*2,                                         \
                  A  + (size_t)(m0 + row)*lda + (kt)*32 + c8);                  \
            cpa16(sB + (row*RS + c8)*2,                                         \
                  Wt + (size_t)(n0 + row)*K   + (kt)*32 + c8);                  \
        }                                                                       \
        CP_COMMIT();                                                            \
    } while (0)

    float acc[2][8][4];
#pragma unroll
    for (int i = 0; i < 2; i++)
#pragma unroll
        for (int j = 0; j < 8; j++)
#pragma unroll
            for (int c = 0; c < 4; c++) acc[i][j][c] = 0.f;

    STAGE_LOAD(0);
    STAGE_LOAD(1);
    STAGE_LOAD(2);
    STAGE_LOAD(3);

    for (int kt = 0; kt < nk; kt++) {
        CP_WAIT3();
        __syncthreads();
        if (kt + 4 < nk) STAGE_LOAD(kt + 4); else CP_COMMIT();

        const uint32_t sA = sbase + (kt % NSTG) * ST_BYTES;
        const uint32_t sB = sA + ST_MAT_H*2;
#pragma unroll
        for (int kk = 0; kk < 32; kk += 16) {
            uint32_t a[2][4], b[4][4];
#pragma unroll
            for (int mf = 0; mf < 2; mf++) {
                const uint32_t ad = sA + ((wm*32 + mf*16 + lrow)*RS + kk + lk)*2;
                ldsm4(a[mf][0], a[mf][1], a[mf][2], a[mf][3], ad);
            }
#pragma unroll
            for (int ng = 0; ng < 4; ng++) {
                const uint32_t bd = sB + ((wn*64 + ng*16 + lrow)*RS + kk + lk)*2;
                ldsm4(b[ng][0], b[ng][1], b[ng][2], b[ng][3], bd);
            }
#pragma unroll
            for (int mf = 0; mf < 2; mf++)
#pragma unroll
                for (int ng = 0; ng < 4; ng++) {
                    mma_f16(acc[mf][2*ng][0], acc[mf][2*ng][1],
                            acc[mf][2*ng][2], acc[mf][2*ng][3],
                            a[mf][0], a[mf][1], a[mf][2], a[mf][3],
                            b[ng][0], b[ng][2]);
                    mma_f16(acc[mf][2*ng+1][0], acc[mf][2*ng+1][1],
                            acc[mf][2*ng+1][2], acc[mf][2*ng+1][3],
                            a[mf][0], a[mf][1], a[mf][2], a[mf][3],
                            b[ng][1], b[ng][3]);
                }
        }
    }

    // epilogue
    const int batch = m0 >> 10;
#pragma unroll
    for (int mf = 0; mf < 2; mf++) {
#pragma unroll
        for (int nf = 0; nf < 8; nf++) {
            const int n = n0 + wn*64 + nf*8 + qc*2;
            float bx = 0.f, by = 0.f;
            if (bias) { bx = bias[n]; by = bias[n+1]; }
            if (BBIAS) { bx += gb[batch*N + n]; by += gb[batch*N + n + 1]; }
#pragma unroll
            for (int half = 0; half < 2; half++) {
                const int m = m0 + wm*32 + mf*16 + qr + half*8;
                float v0 = acc[mf][nf][half*2+0] + bx;
                float v1 = acc[mf][nf][half*2+1] + by;
                if (RES) {
                    const float2 r2 = *(const float2*)&res[(size_t)m*N + n];
                    v0 += r2.x; v1 += r2.y;
                }
                if (ACT == 1) { v0 = fmaxf(v0, 0.f); v1 = fmaxf(v1, 0.f); }
                else if (ACT == 2) {
                    v0 = 0.5f*v0*(1.f + erff(v0*0.70710678118654752f));
                    v1 = 0.5f*v1*(1.f + erff(v1*0.70710678118654752f));
                }
                if (WF) *(float2*)&Cf[(size_t)m*N + n] = make_float2(v0, v1);
                if (WH) *(__half2*)&Ch[(size_t)m*N + n] =
                            __halves2half2(__float2half_rn(v0), __float2half_rn(v1));
            }
        }
    }
#undef STAGE_LOAD
}

// ---------------- merged weight transpose (f32 -> fp16 [N][K]) --------------
#define NJOBS 11
struct TransJobs {
    const float* src[NJOBS];
    long long    dstoff[NJOBS];
    int K[NJOBS], N[NJOBS];
    int start[NJOBS+1];
};

__global__ __launch_bounds__(256) void transpose_all_kernel(TransJobs jobs, __half* __restrict__ wt)
{
    __shared__ float t[32][33];
    const int bid = blockIdx.x;
    int j = 0;
#pragma unroll
    for (int i = 0; i < NJOBS; i++) if (bid >= jobs.start[i+1]) j = i+1;
    const int lt = bid - jobs.start[j];
    const int K = jobs.K[j], N = jobs.N[j];
    const int tilesx = N >> 5;
    const int n0 = (lt % tilesx) * 32;
    const int k0 = (lt / tilesx) * 32;
    const float* in = jobs.src[j];
    __half* outp = wt + jobs.dstoff[j];

    const int x = threadIdx.x & 31, y = threadIdx.x >> 5;
#pragma unroll
    for (int i = 0; i < 4; i++)
        t[y + 8*i][x] = in[(size_t)(k0 + y + 8*i) * N + n0 + x];
    __syncthreads();
#pragma unroll
    for (int i = 0; i < 4; i++)
        outp[(size_t)(n0 + y + 8*i) * K + k0 + x] = __float2half_rn(t[x][y + 8*i]);
}

// ---------------- f32 -> fp16 convert (state) -------------------------------
__global__ void tohalf_kernel(const float* __restrict__ in, __half* __restrict__ o, int n2)
{
    const int i = blockIdx.x*256 + threadIdx.x;
    if (i < n2) {
        const float2 v = ((const float2*)in)[i];
        ((__half2*)o)[i] = __halves2half2(__float2half_rn(v.x), __float2half_rn(v.y));
    }
}

// ---------------- windowed attention (NATTEN, window 31) -------------------
// [r][d] DYNAMIC smem, stride 68 floats (272 B): float4 loads legal AND
// conflict-free.  51,136 B > 48KB static limit -> dynamic + attribute opt-in.
#define NAT_RS 68
#define SMEM_NAT (2*94*NAT_RS*4)      // 51136 B

__global__ __launch_bounds__(64) void natten_kernel(
    const float* __restrict__ qkv, __half* __restrict__ out)
{
    extern __shared__ float nsm[];
    float (*ks)[NAT_RS] = (float(*)[NAT_RS])nsm;
    float (*vs)[NAT_RS] = (float(*)[NAT_RS])(nsm + 94*NAT_RS);

    const int qt = blockIdx.x;
    const int h  = blockIdx.y;
    const int b  = blockIdx.z;
    const int q0 = qt * 64;
    const int base = q0 - 15;

    const int tid = threadIdx.x;
    for (int idx = tid; idx < 94*16; idx += 64) {
        const int r  = idx >> 4;
        const int d4 = (idx & 15) * 4;
        const int pos = base + r;
        float4 kk4 = make_float4(0.f,0.f,0.f,0.f);
        float4 vv4 = make_float4(0.f,0.f,0.f,0.f);
        if (pos >= 0 && pos < LL) {
            const size_t off = ((size_t)(b*LL + pos))*1536 + h*64 + d4;
            kk4 = *(const float4*)&qkv[off + 512];
            vv4 = *(const float4*)&qkv[off + 1024];
        }
        *(float4*)&ks[r][d4] = kk4;
        *(float4*)&vs[r][d4] = vv4;
    }
    __syncthreads();

    const int l = q0 + tid;
    const float* qp = &qkv[((size_t)(b*LL + l))*1536 + h*64];

    float s[31];
#pragma unroll
    for (int j = 0; j < 31; j++) s[j] = 0.f;

#pragma unroll
    for (int c = 0; c < 4; c++) {
        float q[16];
#pragma unroll
        for (int d4 = 0; d4 < 16; d4 += 4)
            *(float4*)&q[d4] = *(const float4*)&qp[c*16 + d4];
#pragma unroll
        for (int j = 0; j < 31; j++) {
            float kv[16];
#pragma unroll
            for (int d4 = 0; d4 < 16; d4 += 4)
                *(float4*)&kv[d4] = *(const float4*)&ks[tid + j][c*16 + d4];
            float dot = 0.f;
#pragma unroll
            for (int d = 0; d < 16; d++)
                dot = fmaf(q[d], kv[d], dot);
            s[j] += dot;
        }
    }

    float mx = -1e30f;
#pragma unroll
    for (int j = 0; j < 31; j++) {
        const int pos = l - 15 + j;
        if (pos < 0 || pos >= LL) s[j] = -1e30f;
        else                      s[j] *= 0.125f;
        mx = fmaxf(mx, s[j]);
    }
    float sum = 0.f;
#pragma unroll
    for (int j = 0; j < 31; j++) { s[j] = expf(s[j] - mx); sum += s[j]; }
    const float inv = 1.f / sum;

    __half* op = &out[((size_t)(b*LL + l))*512 + h*64];
#pragma unroll
    for (int c = 0; c < 4; c++) {
        float o[16];
#pragma unroll
        for (int d = 0; d < 16; d++) o[d] = 0.f;
#pragma unroll
        for (int j = 0; j < 31; j++) {
            const float p = s[j];
            float vv[16];
#pragma unroll
            for (int d4 = 0; d4 < 16; d4 += 4)
                *(float4*)&vv[d4] = *(const float4*)&vs[tid + j][c*16 + d4];
#pragma unroll
            for (int d = 0; d < 16; d++)
                o[d] = fmaf(p, vv[d], o[d]);
        }
#pragma unroll
        for (int d = 0; d < 16; d += 2)
            *(__half2*)&op[c*16 + d] = __halves2half2(__float2half_rn(o[d]*inv),
                                                      __float2half_rn(o[d+1]*inv));
    }
}

// ---------------- LayerNorm (+clip), dual output ----------------------------
template<bool CLIP, bool WF, bool WH>
__global__ __launch_bounds__(128) void ln_kernel(
    const float* __restrict__ a,
    const float* __restrict__ gam, const float* __restrict__ bet,
    float* __restrict__ outf, int ldf,
    __half* __restrict__ outh, int ldh)
{
    const int row = blockIdx.x;
    const int tid = threadIdx.x;
    const float* ap = a + (size_t)row*512;

    float v[4];
    float s = 0.f, s2 = 0.f;
#pragma unroll
    for (int i = 0; i < 4; i++) {
        const float x = ap[tid + 128*i];
        v[i] = x; s += x; s2 += x*x;
    }
    __shared__ float red[2][4];
#pragma unroll
    for (int o = 16; o > 0; o >>= 1) {
        s  += __shfl_down_sync(~0u, s,  o);
        s2 += __shfl_down_sync(~0u, s2, o);
    }
    const int wd = tid >> 5, lane = tid & 31;
    if (lane == 0) { red[0][wd] = s; red[1][wd] = s2; }
    __syncthreads();
    __shared__ float stats[2];
    if (tid == 0) {
        float ts = 0.f, ts2 = 0.f;
#pragma unroll
        for (int w = 0; w < 4; w++) { ts += red[0][w]; ts2 += red[1][w]; }
        const float mean = ts * (1.f/512.f);
        stats[0] = mean;
        stats[1] = rsqrtf(ts2 * (1.f/512.f) - mean*mean + 1e-5f);
    }
    __syncthreads();
    const float mean = stats[0], rstd = stats[1];
#pragma unroll
    for (int i = 0; i < 4; i++) {
        const int c = tid + 128*i;
        float y = (v[i] - mean) * rstd * gam[c] + bet[c];
        if (CLIP) y = fminf(fmaxf(y, -100.f), 100.f);
        if (WF) outf[(size_t)row*ldf + c] = y;
        if (WH) outh[(size_t)row*ldh + c] = __float2half_rn(y);
    }
}

// ---------------- partial mean over sequence axis --------------------------
__global__ void mean1_kernel(const float* __restrict__ x, float* __restrict__ outp)
{
    const int c = blockIdx.x*128 + threadIdx.x;
    const int b = blockIdx.y;
    const int z = blockIdx.z;
    const float* p = x + ((size_t)b*LL + z*64)*512 + c;
    float s = 0.f;
#pragma unroll 4
    for (int l = 0; l < 64; l++) s += p[(size_t)l*512];
    outp[(z*BB + b)*512 + c] = s;
}

// ---------------- fused summary: mean2 + @Wg + @Wc[512:] -------------------
__global__ __launch_bounds__(512) void summary_kernel(
    const float* __restrict__ part,
    const float* __restrict__ Wg, const float* __restrict__ bg,
    const float* __restrict__ Wc2, const float* __restrict__ bc,
    float* __restrict__ gpart)
{
    __shared__ float a[512], g[512];
    const int b = blockIdx.x, n = threadIdx.x;
    float s = 0.f;
#pragma unroll
    for (int z = 0; z < 16; z++) s += part[(z*BB + b)*512 + n];
    a[n] = s * (1.f/LL);
    __syncthreads();
    float acc = bg[n];
    for (int k = 0; k < 512; k++) acc = fmaf(a[k], Wg[(size_t)k*512 + n], acc);
    g[n] = acc;
    __syncthreads();
    float acc2 = bc[n];
    for (int k = 0; k < 512; k++) acc2 = fmaf(g[k], Wc2[(size_t)k*512 + n], acc2);
    gpart[b*512 + n] = acc2;
}

// ---------------- bias concat -----------------------------------------------
__global__ void concat_bias_kernel(const float* __restrict__ b1,
                                   const float* __restrict__ b2,
                                   float* __restrict__ o)
{
    const int i = threadIdx.x;
    o[i] = (i < 256) ? b1[i] : b2[i - 256];
}

// ---------------- small-N GEMM (N=5), K=256 --------------------------------
__global__ void small_gemm_kernel(
    const float* __restrict__ A, int lda, const float* __restrict__ W,
    const float* __restrict__ bias, float* __restrict__ C, int N)
{
    const int idx = blockIdx.x*blockDim.x + threadIdx.x;
    if (idx >= MROWS*N) return;
    const int m = idx / N, n = idx - m*N;
    const float* a = A + (size_t)m*lda;
    float s0 = bias[n], s1 = 0.f, s2 = 0.f, s3 = 0.f;
    for (int k = 0; k < 256; k += 4) {
        const float4 av = *(const float4*)&a[k];
        s0 = fmaf(av.x, W[(k  )*N + n], s0);
        s1 = fmaf(av.y, W[(k+1)*N + n], s1);
        s2 = fmaf(av.z, W[(k+2)*N + n], s2);
        s3 = fmaf(av.w, W[(k+3)*N + n], s3);
    }
    C[idx] = (s0 + s1) + (s2 + s3);
}

// ---------------- fused type head: logits + softmax@emb --------------------
__global__ __launch_bounds__(256) void type_head_kernel(
    const float* __restrict__ h,
    const float* __restrict__ Wt2, const float* __restrict__ bt2,
    const float* __restrict__ emb,
    float* __restrict__ out_logits,
    __half* __restrict__ si)
{
    __shared__ float As[8][260];
    __shared__ float lg[8][18];
    const int tid = threadIdx.x;
    const int r0 = blockIdx.x * 8;

#pragma unroll
    for (int it = 0; it < 2; it++) {
        const int idx = tid + it*256;
        const int r = idx >> 6;
        const int c4 = (idx & 63) * 4;
        *(float4*)&As[r][c4] = *(const float4*)&h[((size_t)(r0 + r))*256 + c4];
    }
    __syncthreads();

    if (tid < 144) {
        const int r = tid / 18, n = tid - r*18;
        float s0 = bt2[n], s1 = 0.f, s2 = 0.f, s3 = 0.f;
        for (int k = 0; k < 256; k += 4) {
            const float4 av = *(const float4*)&As[r][k];
            s0 = fmaf(av.x, Wt2[(k  )*18 + n], s0);
            s1 = fmaf(av.y, Wt2[(k+1)*18 + n], s1);
            s2 = fmaf(av.z, Wt2[(k+2)*18 + n], s2);
            s3 = fmaf(av.w, Wt2[(k+3)*18 + n], s3);
        }
        const float v = (s0 + s1) + (s2 + s3);
        lg[r][n] = v;
        out_logits[(size_t)(r0 + r)*18 + n] = v;
    }
    __syncthreads();

    const int w = tid >> 5, lane = tid & 31;
    float v[18];
    float mx = -1e30f;
#pragma unroll
    for (int j = 0; j < 18; j++) { v[j] = lg[w][j]; mx = fmaxf(mx, v[j]); }
    float sum = 0.f;
#pragma unroll
    for (int j = 0; j < 18; j++) { v[j] = expf(v[j] - mx); sum += v[j]; }
    const float inv = 1.f / sum;
    float o = 0.f;
#pragma unroll
    for (int j = 0; j < 18; j++) o = fmaf(v[j], emb[j*32 + lane], o);
    si[(size_t)(r0 + w)*544 + 512 + lane] = __float2half_rn(o * inv);
}

// ---------------- launch ----------------------------------------------------
extern "C" void kernel_launch(void* const* d_in, const int* in_sizes, int n_in,
                              void* d_out, int out_size)
{
    (void)in_sizes; (void)n_in; (void)out_size;
    const float* state = (const float*)d_in[0];
    const float* Wp    = (const float*)d_in[1];
    const float* bp    = (const float*)d_in[2];
    const float* Wqkv  = (const float*)d_in[3];
    const float* bqkv  = (const float*)d_in[4];
    const float* Wo    = (const float*)d_in[5];
    const float* bo    = (const float*)d_in[6];
    const float* ln_g  = (const float*)d_in[7];
    const float* ln_b  = (const float*)d_in[8];
    const float* Wg    = (const float*)d_in[9];
    const float* bg    = (const float*)d_in[10];
    const float* Wc    = (const float*)d_in[11];
    const float* bc    = (const float*)d_in[12];
    const float* W1    = (const float*)d_in[13];
    const float* b1    = (const float*)d_in[14];
    const float* W2    = (const float*)d_in[15];
    const float* b2    = (const float*)d_in[16];
    const float* fn_g  = (const float*)d_in[17];
    const float* fn_b  = (const float*)d_in[18];
    const float* Wt1   = (const float*)d_in[19];
    const float* bt1   = (const float*)d_in[20];
    const float* Wt2   = (const float*)d_in[21];
    const float* bt2   = (const float*)d_in[22];
    const float* temb  = (const float*)d_in[23];
    const float* Ws1   = (const float*)d_in[24];
    const float* bs1   = (const float*)d_in[25];
    const float* Ws2   = (const float*)d_in[26];
    const float* bs2   = (const float*)d_in[27];
    const float* Wa1   = (const float*)d_in[28];
    const float* ba1   = (const float*)d_in[29];
    const float* Wa2   = (const float*)d_in[30];
    const float* ba2   = (const float*)d_in[31];

    float* out = (float*)d_out;

    static float *px=nullptr,*ploc,*pqkv,*pattf,*ptmp,*pcomb,*ph256,*ppm,*pgpart,*pbsa;
    static __half *pxh,*ploch,*patth,*ptmp1h,*pcombh,*psih,*psteh,*pwt;
    if (!px) {
        cudaGetSymbolAddress((void**)&px,    g_x);
        cudaGetSymbolAddress((void**)&pxh,   g_xh);
        cudaGetSymbolAddress((void**)&ploc,  g_loc);
        cudaGetSymbolAddress((void**)&ploch, g_loch);
        cudaGetSymbolAddress((void**)&pqkv,  g_qkv);
        cudaGetSymbolAddress((void**)&pattf, g_att);
        cudaGetSymbolAddress((void**)&patth, g_atth);
        cudaGetSymbolAddress((void**)&ptmp,  g_tmp);
        cudaGetSymbolAddress((void**)&ptmp1h,g_tmp1h);
        cudaGetSymbolAddress((void**)&pcomb, g_comb);
        cudaGetSymbolAddress((void**)&pcombh,g_combh);
        cudaGetSymbolAddress((void**)&psih,  g_sih);
        cudaGetSymbolAddress((void**)&ph256, g_h256);
        cudaGetSymbolAddress((void**)&ppm,   g_pmean);
        cudaGetSymbolAddress((void**)&pgpart,g_gpart);
        cudaGetSymbolAddress((void**)&pbsa,  g_bsa);
        cudaGetSymbolAddress((void**)&psteh, g_steh);
        cudaGetSymbolAddress((void**)&pwt,   g_wt);
        cudaFuncSetAttribute(gemm_h<0,false,false,true ,true >, cudaFuncAttributeMaxDynamicSharedMemorySize, SMEM_H);
        cudaFuncSetAttribute(gemm_h<0,false,false,true ,false>, cudaFuncAttributeMaxDynamicSharedMemorySize, SMEM_H);
        cudaFuncSetAttribute(gemm_h<0,false,true ,true ,false>, cudaFuncAttributeMaxDynamicSharedMemorySize, SMEM_H);
        cudaFuncSetAttribute(gemm_h<0,true ,false,true ,true >, cudaFuncAttributeMaxDynamicSharedMemorySize, SMEM_H);
        cudaFuncSetAttribute(gemm_h<2,false,false,false,true >, cudaFuncAttributeMaxDynamicSharedMemorySize, SMEM_H);
        cudaFuncSetAttribute(gemm_h<1,false,false,true ,false>, cudaFuncAttributeMaxDynamicSharedMemorySize, SMEM_H);
        cudaFuncSetAttribute(natten_kernel, cudaFuncAttributeMaxDynamicSharedMemorySize, SMEM_NAT);
    }

    // 0. transposed fp16 weights + fp16 state + concat bias
    {
        TransJobs J;
        const float* srcs[NJOBS] = { Wp, Wqkv, Wqkv + (size_t)512*1536, Wo,
                                     Wo + (size_t)512*512, Wc, W1, W2, Wt1, Ws1, Wa1 };
        const long long offs[NJOBS] = { WT_P, WT_QKV0, WT_QKV1, WT_O0, WT_O1,
                                        WT_C, WT_1, WT_2, WT_T1, WT_SA, WT_SA + 256*544 };
        const int Ks[NJOBS] = { 256, 512, 512, 512, 512, 512, 512, 1024, 512, 544, 544 };
        const int Ns[NJOBS] = { 512, 1536, 1536, 512, 512, 512, 1024, 512, 256, 256, 256 };
        int acc = 0;
        for (int i = 0; i < NJOBS; i++) {
            J.src[i] = srcs[i]; J.dstoff[i] = offs[i]; J.K[i] = Ks[i]; J.N[i] = Ns[i];
            J.start[i] = acc;
            acc += (Ns[i] >> 5) * (Ks[i] >> 5);
        }
        J.start[NJOBS] = acc;
        transpose_all_kernel<<<acc, 256>>>(J, pwt);
    }
    tohalf_kernel<<<(MROWS*DIN/2 + 255)/256, 256>>>(state, psteh, MROWS*DIN/2);
    concat_bias_kernel<<<1, 512>>>(bs1, ba1, pbsa);

    const dim3 thr(256);
    #define GEMM(T1,T2,T3,T4,T5, Ap, LDA, WT, BIAS, GB, RESP, CF, CH, NN, KK) \
        gemm_h<T1,T2,T3,T4,T5><<<dim3((NN)/128, MROWS/128), thr, SMEM_H>>>(Ap, LDA, WT, BIAS, GB, RESP, CF, CH, NN, KK)

    // 1. x = state @ Wp + bp  (f32 + fp16)
    GEMM(0,false,false,true,true, psteh, DIN, pwt+WT_P, bp, nullptr, nullptr, px, pxh, 512, 256);

    // 2. two NATTEN layers
    const float*  locF = px;
    const __half* locH = pxh;
    for (int i = 0; i < 2; i++) {
        GEMM(0,false,false,true,false, locH, 512, pwt + (i ? WT_QKV1 : WT_QKV0), bqkv + i*1536,
             nullptr, nullptr, pqkv, (__half*)nullptr, 1536, 512);
        natten_kernel<<<dim3(LL/64, NHEAD, BB), 64, SMEM_NAT>>>(pqkv, patth);
        GEMM(0,false,true,true,false, patth, 512, pwt + (i ? WT_O1 : WT_O0), bo + i*512,
             nullptr, locF, ptmp, (__half*)nullptr, 512, 512);
        ln_kernel<false,true,true><<<MROWS, 128>>>(ptmp, ln_g + i*512, ln_b + i*512,
                                                   ploc, 512, ploch, 512);
        locF = ploc; locH = ploch;
    }

    // 3. global summary path (per-batch, f32 exact)
    mean1_kernel<<<dim3(4, BB, 16), 128>>>(px, ppm);
    summary_kernel<<<BB, 512>>>(ppm, Wg, bg, Wc + (size_t)512*512, bc, pgpart);

    // 4. comb = loc @ Wc[:512] + gpart[batch]  (f32 + fp16)
    GEMM(0,true,false,true,true, ploch, 512, pwt+WT_C, nullptr, pgpart, nullptr,
         pcomb, pcombh, 512, 512);

    // 5. FFN (hidden fp16 only; residual fused into W2) + LN(clip) -> si_h
    GEMM(2,false,false,false,true, pcombh, 512, pwt+WT_1, b1, nullptr, nullptr,
         (float*)nullptr, ptmp1h, 1024, 512);
    GEMM(0,false,true,true,false, ptmp1h, 1024, pwt+WT_2, b2, nullptr, pcomb,
         pattf, (__half*)nullptr, 512, 1024);
    ln_kernel<true,false,true><<<MROWS, 128>>>(pattf, fn_g, fn_b,
                                               (float*)nullptr, 0, psih, 544);

    // 6. type head
    GEMM(1,false,false,true,false, psih, 544, pwt+WT_T1, bt1, nullptr, nullptr,
         ph256, (__half*)nullptr, 256, 512);
    type_head_kernel<<<MROWS/8, 256>>>(ph256, Wt2, bt2, temb, out, psih);

    // 7+8. fused size+amount first layer
    GEMM(1,false,false,true,false, psih, 544, pwt+WT_SA, pbsa, nullptr, nullptr,
         ptmp, (__half*)nullptr, 512, 544);
    small_gemm_kernel<<<(MROWS*5 + 255)/256, 256>>>(ptmp,       512, Ws2, bs2, out + (size_t)MROWS*18, 5);
    small_gemm_kernel<<<(MROWS*5 + 255)/256, 256>>>(ptmp + 256, 512, Wa2, ba2, out + (size_t)MROWS*23, 5);
}